// round 4
// baseline (speedup 1.0000x reference)
#include <cuda_runtime.h>

#define N_B 32
#define C_B 64
#define D_B 128
#define MAT (D_B*D_B)          // 16384
#define STR 132                // padded smem row stride (floats)
#define SMEM3 (3*D_B*STR*4)    // 202752 bytes dynamic smem for k_attn
#define TPB 256

typedef unsigned long long u64;

// ---------------- scratch (device globals; no allocations allowed) ----------
__device__ float g_rv[N_B*C_B*D_B];   // rsqrt(max(|diag|,1e-4)) per (n,c,i)
__device__ float g_XQ[N_B*C_B*MAT];   // X mixed by w_queries
__device__ float g_XK[N_B*C_B*MAT];   // X mixed by w_keys

// ---------------- packed f32x2 helpers (2x fp32 FMA throughput) -------------
__device__ __forceinline__ u64 bcast2(float x){
    u64 r; unsigned xi = __float_as_uint(x);
    asm("mov.b64 %0, {%1, %1};" : "=l"(r) : "r"(xi));
    return r;
}
__device__ __forceinline__ u64 pack2(float lo, float hi){
    u64 r;
    asm("mov.b64 %0, {%1, %2};" : "=l"(r) : "r"(__float_as_uint(lo)), "r"(__float_as_uint(hi)));
    return r;
}
__device__ __forceinline__ u64 ffma2(u64 a, u64 b, u64 c){
    u64 d;
    asm("fma.rn.f32x2 %0, %1, %2, %3;" : "=l"(d) : "l"(a), "l"(b), "l"(c));
    return d;
}
__device__ __forceinline__ u64 add2(u64 a, u64 b){
    u64 d;
    asm("add.rn.f32x2 %0, %1, %2;" : "=l"(d) : "l"(a), "l"(b));
    return d;
}
__device__ __forceinline__ u64 mul2(u64 a, u64 b){
    u64 d;
    asm("mul.rn.f32x2 %0, %1, %2;" : "=l"(d) : "l"(a), "l"(b));
    return d;
}
__device__ __forceinline__ void unpack2(u64 v, float& lo, float& hi){
    unsigned a, b;
    asm("mov.b64 {%0, %1}, %2;" : "=r"(a), "=r"(b) : "l"(v));
    lo = __uint_as_float(a); hi = __uint_as_float(b);
}
__device__ __forceinline__ void unpack2u(u64 v, unsigned& a, unsigned& b){
    asm("mov.b64 {%0, %1}, %2;" : "=r"(a), "=r"(b) : "l"(v));
}
union F4U { float4 f; u64 u[2]; };

__device__ __forceinline__ float clip1(float x){
    return fminf(1.f, fmaxf(-1.f, x));
}

// fma-pipe exp of a packed pair (any input; clamped to >= ~2^-127 at underflow)
// exp(x) = 2^(x*log2e); magic-rounding range reduction + deg-5 Taylor for 2^f.
__device__ __forceinline__ u64 exp_pair(u64 xb, u64 kL2E, u64 kMAG, u64 kNMAG,
                                        u64 kN1, u64 kC5, u64 kC4, u64 kC3,
                                        u64 kC2, u64 kC1, u64 kONE){
    u64 y = mul2(xb, kL2E);
    u64 z = add2(y, kMAG);          // rounds y to int n in low mantissa bits
    u64 t = add2(z, kNMAG);         // t = n (exact)
    u64 f = ffma2(t, kN1, y);       // f = y - n, in [-0.5, 0.5]
    u64 p = ffma2(kC5, f, kC4);
    p = ffma2(p, f, kC3);
    p = ffma2(p, f, kC2);
    p = ffma2(p, f, kC1);
    p = ffma2(p, f, kONE);
    unsigned zl, zh; unpack2u(z, zl, zh);
    int n0 = (int)(zl - 0x4B400000u); n0 = max(n0, -127);
    int n1 = (int)(zh - 0x4B400000u); n1 = max(n1, -127);
    unsigned s0 = (unsigned)(n0 + 127) << 23;
    unsigned s1 = (unsigned)(n1 + 127) << 23;
    u64 s;
    asm("mov.b64 %0, {%1, %2};" : "=l"(s) : "r"(s0), "r"(s1));
    return mul2(p, s);
}

// ============================================================================
// Kernel 0: per-(n,c) diagonal rsqrt factors
// ============================================================================
__global__ void k_rinv(const float* __restrict__ in){
    int nk = blockIdx.x;            // n*C + c
    int t  = threadIdx.x;           // 0..127
    float v = in[(size_t)nk*MAT + t*D_B + t];
    g_rv[nk*D_B + t] = rsqrtf(fmaxf(fabsf(v), 1e-4f));
}

// ============================================================================
// Kernel 1: fused cov2cor + channel mixing.
//   X[n,c,i,j] = clip(in * rv_i * rv_j);  XWQ/XWK = einsum('ncij,ck->nkij')
// grid (D_B, N_B): block handles row i = blockIdx.x (128 j's), all 64 k.
// ============================================================================
__global__ __launch_bounds__(256, 2) void k_mix(const float* __restrict__ inp,
                                                const float* __restrict__ wq,
                                                const float* __restrict__ wk){
    __shared__ float sWQ[C_B*C_B];
    __shared__ float sWK[C_B*C_B];
    __shared__ float sX [8*D_B];
    __shared__ float sRV[8*D_B];
    int tid = threadIdx.x;
    int n   = blockIdx.y;
    int irow= blockIdx.x;               // row i, j = 0..127
    for (int i = tid; i < C_B*C_B; i += 256){ sWQ[i] = wq[i]; sWK[i] = wk[i]; }
    int tx = tid & 31;           // j sub-tile: j = tx*4 + p
    int ty = tid >> 5;           // k sub-tile
    int k0 = ty * 8;
    u64 aQ[4][4], aK[4][4];
    #pragma unroll
    for (int p = 0; p < 4; p++)
        #pragma unroll
        for (int q = 0; q < 4; q++){ aQ[p][q] = 0ull; aK[p][q] = 0ull; }
    __syncthreads();
    for (int cc = 0; cc < C_B; cc += 8){
        {   // stage rinv rows for these 8 channels (g_rv is tiny -> L2-hot)
            int idx = tid * 4;           // 256*4 = 1024 floats
            int cl = idx >> 7, j = idx & 127;
            *(float4*)&sRV[idx] = *(const float4*)&g_rv[((size_t)(n*C_B + cc + cl))*D_B + j];
        }
        __syncthreads();
        {   // stage 8 channels x 128 j of X = clip(cov2cor)
            int cl = tid >> 5, jj = (tid & 31) * 4;
            float4 v = *(const float4*)&inp[((size_t)(n*C_B + cc + cl))*MAT + irow*D_B + jj];
            float ri = sRV[cl*D_B + irow];
            v.x = clip1(v.x * ri * sRV[cl*D_B + jj+0]);
            v.y = clip1(v.y * ri * sRV[cl*D_B + jj+1]);
            v.z = clip1(v.z * ri * sRV[cl*D_B + jj+2]);
            v.w = clip1(v.w * ri * sRV[cl*D_B + jj+3]);
            *(float4*)&sX[cl*D_B + jj] = v;
        }
        __syncthreads();
        #pragma unroll
        for (int cl = 0; cl < 8; cl++){
            int c = cc + cl;
            float4 xv = *(const float4*)&sX[cl*D_B + tx*4];
            u64 xx[4] = { bcast2(xv.x), bcast2(xv.y), bcast2(xv.z), bcast2(xv.w) };
            F4U q0, q1, kk0, kk1;
            q0.f  = *(const float4*)&sWQ[c*C_B + k0];
            q1.f  = *(const float4*)&sWQ[c*C_B + k0 + 4];
            kk0.f = *(const float4*)&sWK[c*C_B + k0];
            kk1.f = *(const float4*)&sWK[c*C_B + k0 + 4];
            u64 bq[4] = { q0.u[0],  q0.u[1],  q1.u[0],  q1.u[1]  };
            u64 bk[4] = { kk0.u[0], kk0.u[1], kk1.u[0], kk1.u[1] };
            #pragma unroll
            for (int p = 0; p < 4; p++){
                #pragma unroll
                for (int q = 0; q < 4; q++){
                    aQ[p][q] = ffma2(xx[p], bq[q], aQ[p][q]);
                    aK[p][q] = ffma2(xx[p], bk[q], aK[p][q]);
                }
            }
        }
        __syncthreads();
    }
    #pragma unroll
    for (int q = 0; q < 4; q++){
        #pragma unroll
        for (int h = 0; h < 2; h++){
            int k = k0 + q*2 + h;
            float vq[4], vk[4];
            #pragma unroll
            for (int p = 0; p < 4; p++){
                float lo, hi;
                unpack2(aQ[p][q], lo, hi); vq[p] = h ? hi : lo;
                unpack2(aK[p][q], lo, hi); vk[p] = h ? hi : lo;
            }
            size_t base = ((size_t)(n*C_B + k))*MAT + irow*D_B + tx*4;
            *(float4*)&g_XQ[base] = make_float4(vq[0], vq[1], vq[2], vq[3]);
            *(float4*)&g_XK[base] = make_float4(vk[0], vk[1], vk[2], vk[3]);
        }
    }
}

// ============================================================================
// Kernel 2 helpers: smem-resident 128x128x128 matmuls, 256 threads,
// thread computes an 8x8 output tile as 8x4 f32x2 accumulators.
// ============================================================================
__device__ __forceinline__ void load_tile(float* dst, const float* __restrict__ src, int tid){
    #pragma unroll
    for (int e = tid; e < MAT/4; e += TPB){
        int i = e >> 5, j = (e & 31) * 4;
        *(float4*)&dst[i*STR + j] = *(const float4*)&src[e*4];
    }
}

// X tile: clip(inp * rv_i * rv_j), cov2cor fused
__device__ __forceinline__ void load_X(float* dst, const float* __restrict__ src,
                                       const float* __restrict__ rv, int tid){
    #pragma unroll
    for (int e = tid; e < MAT/4; e += TPB){
        int i = e >> 5, j = (e & 31) * 4;
        float4 v = *(const float4*)&src[e*4];
        float ri = rv[i];
        v.x = clip1(v.x * ri * rv[j+0]);
        v.y = clip1(v.y * ri * rv[j+1]);
        v.z = clip1(v.z * ri * rv[j+2]);
        v.w = clip1(v.w * ri * rv[j+3]);
        *(float4*)&dst[i*STR + j] = v;
    }
}

// C[i][j] = sum_m A[m][i] * B[m][j]        (both operands read along rows)
__device__ __forceinline__ void mm_atb(float* __restrict__ C, const float* __restrict__ A,
                                       const float* __restrict__ B, int tid){
    int tx = tid & 15, ty = tid >> 4;
    int i0 = ty*8, j0 = tx*8;
    u64 acc[8][4];
    #pragma unroll
    for (int p = 0; p < 8; p++)
        #pragma unroll
        for (int q = 0; q < 4; q++) acc[p][q] = 0ull;
    #pragma unroll 2
    for (int m = 0; m < D_B; m++){
        float4 a0 = *(const float4*)&A[m*STR + i0];
        float4 a1 = *(const float4*)&A[m*STR + i0 + 4];
        F4U b0v, b1v;
        b0v.f = *(const float4*)&B[m*STR + j0];
        b1v.f = *(const float4*)&B[m*STR + j0 + 4];
        u64 bb[4] = { b0v.u[0], b0v.u[1], b1v.u[0], b1v.u[1] };
        float av[8] = { a0.x, a0.y, a0.z, a0.w, a1.x, a1.y, a1.z, a1.w };
        #pragma unroll
        for (int p = 0; p < 8; p++){
            u64 ap = bcast2(av[p]);
            #pragma unroll
            for (int q = 0; q < 4; q++) acc[p][q] = ffma2(ap, bb[q], acc[p][q]);
        }
    }
    #pragma unroll
    for (int p = 0; p < 8; p++){
        F4U o0, o1;
        o0.u[0] = acc[p][0]; o0.u[1] = acc[p][1];
        o1.u[0] = acc[p][2]; o1.u[1] = acc[p][3];
        *(float4*)&C[(i0+p)*STR + j0]     = o0.f;
        *(float4*)&C[(i0+p)*STR + j0 + 4] = o1.f;
    }
}

// Same as mm_atb but also computes the per-warp max of outputs into s_red[warp].
__device__ __forceinline__ void mm_atb_mx(float* __restrict__ C, const float* __restrict__ A,
                                          const float* __restrict__ B, int tid,
                                          float* s_red){
    int tx = tid & 15, ty = tid >> 4;
    int i0 = ty*8, j0 = tx*8;
    u64 acc[8][4];
    #pragma unroll
    for (int p = 0; p < 8; p++)
        #pragma unroll
        for (int q = 0; q < 4; q++) acc[p][q] = 0ull;
    #pragma unroll 2
    for (int m = 0; m < D_B; m++){
        float4 a0 = *(const float4*)&A[m*STR + i0];
        float4 a1 = *(const float4*)&A[m*STR + i0 + 4];
        F4U b0v, b1v;
        b0v.f = *(const float4*)&B[m*STR + j0];
        b1v.f = *(const float4*)&B[m*STR + j0 + 4];
        u64 bb[4] = { b0v.u[0], b0v.u[1], b1v.u[0], b1v.u[1] };
        float av[8] = { a0.x, a0.y, a0.z, a0.w, a1.x, a1.y, a1.z, a1.w };
        #pragma unroll
        for (int p = 0; p < 8; p++){
            u64 ap = bcast2(av[p]);
            #pragma unroll
            for (int q = 0; q < 4; q++) acc[p][q] = ffma2(ap, bb[q], acc[p][q]);
        }
    }
    float mx = -3.4e38f;
    #pragma unroll
    for (int p = 0; p < 8; p++){
        F4U o0, o1;
        o0.u[0] = acc[p][0]; o0.u[1] = acc[p][1];
        o1.u[0] = acc[p][2]; o1.u[1] = acc[p][3];
        *(float4*)&C[(i0+p)*STR + j0]     = o0.f;
        *(float4*)&C[(i0+p)*STR + j0 + 4] = o1.f;
        mx = fmaxf(mx, fmaxf(fmaxf(o0.f.x, o0.f.y), fmaxf(o0.f.z, o0.f.w)));
        mx = fmaxf(mx, fmaxf(fmaxf(o1.f.x, o1.f.y), fmaxf(o1.f.z, o1.f.w)));
    }
    #pragma unroll
    for (int o = 16; o; o >>= 1) mx = fmaxf(mx, __shfl_xor_sync(0xffffffffu, mx, o));
    if ((tid & 31) == 0) s_red[tid >> 5] = mx;
}

// C[i][j] = sum_m A[i][m] * B[m][j]        (A read along rows too, m-unroll 4)
__device__ __forceinline__ void mm_ab(float* __restrict__ C, const float* __restrict__ A,
                                      const float* __restrict__ B, int tid){
    int tx = tid & 15, ty = tid >> 4;
    int i0 = ty*8, j0 = tx*8;
    u64 acc[8][4];
    #pragma unroll
    for (int p = 0; p < 8; p++)
        #pragma unroll
        for (int q = 0; q < 4; q++) acc[p][q] = 0ull;
    for (int m = 0; m < D_B; m += 4){
        float4 a4[8];
        #pragma unroll
        for (int p = 0; p < 8; p++) a4[p] = *(const float4*)&A[(i0+p)*STR + m];
        #pragma unroll
        for (int s = 0; s < 4; s++){
            F4U b0v, b1v;
            b0v.f = *(const float4*)&B[(m+s)*STR + j0];
            b1v.f = *(const float4*)&B[(m+s)*STR + j0 + 4];
            u64 bb[4] = { b0v.u[0], b0v.u[1], b1v.u[0], b1v.u[1] };
            #pragma unroll
            for (int p = 0; p < 8; p++){
                float as = (s == 0) ? a4[p].x : (s == 1) ? a4[p].y
                         : (s == 2) ? a4[p].z : a4[p].w;
                u64 ap = bcast2(as);
                #pragma unroll
                for (int q = 0; q < 4; q++) acc[p][q] = ffma2(ap, bb[q], acc[p][q]);
            }
        }
    }
    #pragma unroll
    for (int p = 0; p < 8; p++){
        F4U o0, o1;
        o0.u[0] = acc[p][0]; o0.u[1] = acc[p][1];
        o1.u[0] = acc[p][2]; o1.u[1] = acc[p][3];
        *(float4*)&C[(i0+p)*STR + j0]     = o0.f;
        *(float4*)&C[(i0+p)*STR + j0 + 4] = o1.f;
    }
}

// out = inputs + lam * (A * B), streamed to gmem
__device__ __forceinline__ void mm_ab_out(const float* __restrict__ A, const float* __restrict__ B,
                                          const float* __restrict__ inp, float* __restrict__ out,
                                          float lam, int tid){
    int tx = tid & 15, ty = tid >> 4;
    int i0 = ty*8, j0 = tx*8;
    u64 acc[8][4];
    #pragma unroll
    for (int p = 0; p < 8; p++)
        #pragma unroll
        for (int q = 0; q < 4; q++) acc[p][q] = 0ull;
    for (int m = 0; m < D_B; m += 4){
        float4 a4[8];
        #pragma unroll
        for (int p = 0; p < 8; p++) a4[p] = *(const float4*)&A[(i0+p)*STR + m];
        #pragma unroll
        for (int s = 0; s < 4; s++){
            F4U b0v, b1v;
            b0v.f = *(const float4*)&B[(m+s)*STR + j0];
            b1v.f = *(const float4*)&B[(m+s)*STR + j0 + 4];
            u64 bb[4] = { b0v.u[0], b0v.u[1], b1v.u[0], b1v.u[1] };
            #pragma unroll
            for (int p = 0; p < 8; p++){
                float as = (s == 0) ? a4[p].x : (s == 1) ? a4[p].y
                         : (s == 2) ? a4[p].z : a4[p].w;
                u64 ap = bcast2(as);
                #pragma unroll
                for (int q = 0; q < 4; q++) acc[p][q] = ffma2(ap, bb[q], acc[p][q]);
            }
        }
    }
    #pragma unroll
    for (int p = 0; p < 8; p++){
        int row = i0 + p;
        float4 iv0 = *(const float4*)&inp[row*D_B + j0];
        float4 iv1 = *(const float4*)&inp[row*D_B + j0 + 4];
        float r[8];
        unpack2(acc[p][0], r[0], r[1]); unpack2(acc[p][1], r[2], r[3]);
        unpack2(acc[p][2], r[4], r[5]); unpack2(acc[p][3], r[6], r[7]);
        float4 o0 = make_float4(iv0.x + lam*r[0], iv0.y + lam*r[1],
                                iv0.z + lam*r[2], iv0.w + lam*r[3]);
        float4 o1 = make_float4(iv1.x + lam*r[4], iv1.y + lam*r[5],
                                iv1.z + lam*r[6], iv1.w + lam*r[7]);
        *(float4*)&out[row*D_B + j0]     = o0;
        *(float4*)&out[row*D_B + j0 + 4] = o1;
    }
}

// soft_pd_max given bmax already in s_red[8]. In place on smem tile M.
// Exp pass: 7/16 iterations via fma-pipe poly, 9/16 via MUFU (dual-pipe).
// Row sums folded into the exp pass (each warp iteration covers one row).
// Ends synced.
__device__ __forceinline__ void soft_pd(float* M, int tid, float* s_dia,
                                        float* s_rinv, float* s_red){
    float bmax = s_red[8];
    // hoisted packed constants for the poly path
    u64 kL2E = bcast2(1.4426950408889634f);
    u64 kMAG = bcast2(12582912.0f);
    u64 kNMAG= bcast2(-12582912.0f);
    u64 kN1  = bcast2(-1.0f);
    u64 kC5  = bcast2(1.3333558146e-3f);
    u64 kC4  = bcast2(9.6181291076e-3f);
    u64 kC3  = bcast2(5.5504108664e-2f);
    u64 kC2  = bcast2(2.4022650695e-1f);
    u64 kC1  = bcast2(6.9314718055e-1f);
    u64 kONE = bcast2(1.0f);
    u64 kNB  = bcast2(-bmax);
    #pragma unroll
    for (int k = 0; k < 16; k++){
        int e = tid + k*TPB;
        int i = e >> 5, j = (e & 31) * 4;    // i = warp + 8k: whole warp same row
        float4 v = *(const float4*)&M[i*STR + j];
        float4 r;
        if ((k & 1) == 0 && k < 14){         // 7 poly iterations (fma pipe)
            u64 xb0 = add2(pack2(v.x, v.y), kNB);
            u64 xb1 = add2(pack2(v.z, v.w), kNB);
            u64 r0 = exp_pair(xb0, kL2E, kMAG, kNMAG, kN1, kC5, kC4, kC3, kC2, kC1, kONE);
            u64 r1 = exp_pair(xb1, kL2E, kMAG, kNMAG, kN1, kC5, kC4, kC3, kC2, kC1, kONE);
            unpack2(r0, r.x, r.y); unpack2(r1, r.z, r.w);
        } else {                             // 9 MUFU iterations
            r.x = __expf(v.x - bmax); r.y = __expf(v.y - bmax);
            r.z = __expf(v.z - bmax); r.w = __expf(v.w - bmax);
        }
        *(float4*)&M[i*STR + j] = r;
        float s4 = (r.x + r.y) + (r.z + r.w);
        #pragma unroll
        for (int o = 16; o; o >>= 1) s4 += __shfl_xor_sync(0xffffffffu, s4, o);
        if ((tid & 31) == 0) s_dia[i] = s4;
    }
    __syncthreads();
    if (tid < 32){
        float t = s_dia[tid] + s_dia[tid+32] + s_dia[tid+64] + s_dia[tid+96];
        #pragma unroll
        for (int o = 16; o; o >>= 1) t += __shfl_xor_sync(0xffffffffu, t, o);
        if (tid == 0) s_red[9] = t;
    }
    __syncthreads();
    if (tid < D_B){
        float total = s_red[9];
        float d = fmaxf(fmaxf(s_dia[tid], total / 100000.0f), 1e-5f);
        s_rinv[tid] = rsqrtf(d);
    }
    __syncthreads();
    #pragma unroll
    for (int e = tid; e < MAT/4; e += TPB){
        int i = e >> 5, j = (e & 31) * 4;
        float ri = s_rinv[i];
        float4 v = *(float4*)&M[i*STR + j];
        v.x *= ri * s_rinv[j];   v.y *= ri * s_rinv[j+1];
        v.z *= ri * s_rinv[j+2]; v.w *= ri * s_rinv[j+3];
        *(float4*)&M[i*STR + j] = v;
    }
    __syncthreads();
}

// ============================================================================
// Kernel 2: per-(n,k) chain. A_pre = K^T Q K; A = soft_pd(A_pre);
//           out = inputs + lam * (A X A^T)
// ============================================================================
__global__ __launch_bounds__(TPB, 1) void k_attn(const float* __restrict__ inp,
                                                 const float* __restrict__ lam,
                                                 float* __restrict__ out){
    extern __shared__ float sm[];
    float* b0 = sm;                 // XWK -> X -> A^T
    float* b1 = sm +     D_B*STR;   // XWQ -> A_pre -> A
    float* b2 = sm + 2 * D_B*STR;   // St  -> P = A*X
    __shared__ float s_dia[D_B], s_rinvd[D_B], s_rv[D_B], s_red[16];
    int tid = threadIdx.x;
    int nk  = blockIdx.x;
    size_t base = (size_t)nk * MAT;

    if (tid < D_B) s_rv[tid] = g_rv[nk*D_B + tid];
    load_tile(b0, g_XK + base, tid);
    load_tile(b1, g_XQ + base, tid);
    __syncthreads();
    mm_atb(b2, b1, b0, tid);           // St = Q^T K  (== (K^T Q)^T)
    __syncthreads();
    mm_atb_mx(b1, b2, b0, tid, s_red); // A_pre = St^T K; warp maxes -> s_red[0..7]
    __syncthreads();
    if (tid == 0){
        float m2 = s_red[0];
        #pragma unroll
        for (int w = 1; w < TPB/32; w++) m2 = fmaxf(m2, s_red[w]);
        s_red[8] = m2;
    }
    load_X(b0, inp + base, s_rv, tid); // overlap gmem X load with max-combine
    __syncthreads();
    soft_pd(b1, tid, s_dia, s_rinvd, s_red);  // b1 = A (ends synced)
    mm_ab(b2, b1, b0, tid);            // P = A X
    __syncthreads();
    for (int e = tid; e < MAT; e += TPB){     // b0 = A^T
        int i = e >> 7, j = e & 127;
        b0[j*STR + i] = b1[i*STR + j];
    }
    __syncthreads();
    mm_ab_out(b2, b0, inp + base, out + base, lam[nk & (C_B - 1)], tid);
}

// ============================================================================
extern "C" void kernel_launch(void* const* d_in, const int* in_sizes, int n_in,
                              void* d_out, int out_size){
    const float* inp = (const float*)d_in[0];
    const float* wq  = (const float*)d_in[1];
    const float* wk  = (const float*)d_in[2];
    const float* lam = (const float*)d_in[3];
    float* out = (float*)d_out;

    cudaFuncSetAttribute(k_attn, cudaFuncAttributeMaxDynamicSharedMemorySize, SMEM3);

    k_rinv<<<N_B*C_B, D_B>>>(inp);
    k_mix<<<dim3(D_B, N_B), 256>>>(inp, wq, wk);
    k_attn<<<N_B*C_B, TPB, SMEM3>>>(inp, lam, out);
}

// round 5
// speedup vs baseline: 1.0231x; 1.0231x over previous
#include <cuda_runtime.h>

#define N_B 32
#define C_B 64
#define D_B 128
#define MAT (D_B*D_B)          // 16384
#define STR 132                // padded smem row stride (floats)
#define SMEM3 (3*D_B*STR*4)    // 202752 bytes dynamic smem for k_attn
#define TPB 256

typedef unsigned long long u64;

// ---------------- scratch (device globals; no allocations allowed) ----------
__device__ float g_rv[N_B*C_B*D_B];   // rsqrt(max(|diag|,1e-4)) per (n,c,i)
__device__ float g_XQ[N_B*C_B*MAT];   // X mixed by w_queries
__device__ float g_XK[N_B*C_B*MAT];   // X mixed by w_keys

// ---------------- packed f32x2 helpers (2x fp32 FMA throughput) -------------
__device__ __forceinline__ u64 bcast2(float x){
    u64 r; unsigned xi = __float_as_uint(x);
    asm("mov.b64 %0, {%1, %1};" : "=l"(r) : "r"(xi));
    return r;
}
__device__ __forceinline__ u64 pack2(float lo, float hi){
    u64 r;
    asm("mov.b64 %0, {%1, %2};" : "=l"(r) : "r"(__float_as_uint(lo)), "r"(__float_as_uint(hi)));
    return r;
}
__device__ __forceinline__ u64 ffma2(u64 a, u64 b, u64 c){
    u64 d;
    asm("fma.rn.f32x2 %0, %1, %2, %3;" : "=l"(d) : "l"(a), "l"(b), "l"(c));
    return d;
}
__device__ __forceinline__ u64 add2(u64 a, u64 b){
    u64 d;
    asm("add.rn.f32x2 %0, %1, %2;" : "=l"(d) : "l"(a), "l"(b));
    return d;
}
__device__ __forceinline__ u64 mul2(u64 a, u64 b){
    u64 d;
    asm("mul.rn.f32x2 %0, %1, %2;" : "=l"(d) : "l"(a), "l"(b));
    return d;
}
__device__ __forceinline__ void unpack2(u64 v, float& lo, float& hi){
    unsigned a, b;
    asm("mov.b64 {%0, %1}, %2;" : "=r"(a), "=r"(b) : "l"(v));
    lo = __uint_as_float(a); hi = __uint_as_float(b);
}
__device__ __forceinline__ void unpack2u(u64 v, unsigned& a, unsigned& b){
    asm("mov.b64 {%0, %1}, %2;" : "=r"(a), "=r"(b) : "l"(v));
}
union F4U { float4 f; u64 u[2]; };

__device__ __forceinline__ float clip1(float x){
    return fminf(1.f, fmaxf(-1.f, x));
}

// fma-pipe exp of a packed pair (any input; clamped to >= ~2^-127 at underflow)
// exp(x) = 2^(x*log2e); magic-rounding range reduction + deg-5 Taylor for 2^f.
__device__ __forceinline__ u64 exp_pair(u64 xb, u64 kL2E, u64 kMAG, u64 kNMAG,
                                        u64 kN1, u64 kC5, u64 kC4, u64 kC3,
                                        u64 kC2, u64 kC1, u64 kONE){
    u64 y = mul2(xb, kL2E);
    u64 z = add2(y, kMAG);          // rounds y to int n in low mantissa bits
    u64 t = add2(z, kNMAG);         // t = n (exact)
    u64 f = ffma2(t, kN1, y);       // f = y - n, in [-0.5, 0.5]
    u64 p = ffma2(kC5, f, kC4);
    p = ffma2(p, f, kC3);
    p = ffma2(p, f, kC2);
    p = ffma2(p, f, kC1);
    p = ffma2(p, f, kONE);
    unsigned zl, zh; unpack2u(z, zl, zh);
    int n0 = (int)(zl - 0x4B400000u); n0 = max(n0, -127);
    int n1 = (int)(zh - 0x4B400000u); n1 = max(n1, -127);
    unsigned s0 = (unsigned)(n0 + 127) << 23;
    unsigned s1 = (unsigned)(n1 + 127) << 23;
    u64 s;
    asm("mov.b64 %0, {%1, %2};" : "=l"(s) : "r"(s0), "r"(s1));
    return mul2(p, s);
}

// ============================================================================
// Kernel 0: per-(n,c) diagonal rsqrt factors
// ============================================================================
__global__ void k_rinv(const float* __restrict__ in){
    int nk = blockIdx.x;            // n*C + c
    int t  = threadIdx.x;           // 0..127
    float v = in[(size_t)nk*MAT + t*D_B + t];
    g_rv[nk*D_B + t] = rsqrtf(fmaxf(fabsf(v), 1e-4f));
}

// ============================================================================
// Kernel 1: fused cov2cor + channel mixing.
//   X[n,c,i,j] = clip(in * rv_i * rv_j);  XWQ/XWK = einsum('ncij,ck->nkij')
// grid (D_B, N_B): block handles row i = blockIdx.x (128 j's), all 64 k.
// ============================================================================
__global__ __launch_bounds__(256, 1) void k_mix(const float* __restrict__ inp,
                                                const float* __restrict__ wq,
                                                const float* __restrict__ wk){
    __shared__ float sWQ[C_B*C_B];
    __shared__ float sWK[C_B*C_B];
    __shared__ float sX [8*D_B];
    __shared__ float sRV[8*D_B];
    int tid = threadIdx.x;
    int n   = blockIdx.y;
    int irow= blockIdx.x;               // row i, j = 0..127
    for (int i = tid; i < C_B*C_B; i += 256){ sWQ[i] = wq[i]; sWK[i] = wk[i]; }
    int tx = tid & 31;           // j sub-tile: j = tx*4 + p
    int ty = tid >> 5;           // k sub-tile
    int k0 = ty * 8;
    u64 aQ[4][4], aK[4][4];
    #pragma unroll
    for (int p = 0; p < 4; p++)
        #pragma unroll
        for (int q = 0; q < 4; q++){ aQ[p][q] = 0ull; aK[p][q] = 0ull; }
    __syncthreads();
    for (int cc = 0; cc < C_B; cc += 8){
        {   // stage rinv rows for these 8 channels (g_rv is tiny -> L2-hot)
            int idx = tid * 4;           // 256*4 = 1024 floats
            int cl = idx >> 7, j = idx & 127;
            *(float4*)&sRV[idx] = *(const float4*)&g_rv[((size_t)(n*C_B + cc + cl))*D_B + j];
        }
        __syncthreads();
        {   // stage 8 channels x 128 j of X = clip(cov2cor)
            int cl = tid >> 5, jj = (tid & 31) * 4;
            float4 v = *(const float4*)&inp[((size_t)(n*C_B + cc + cl))*MAT + irow*D_B + jj];
            float ri = sRV[cl*D_B + irow];
            v.x = clip1(v.x * ri * sRV[cl*D_B + jj+0]);
            v.y = clip1(v.y * ri * sRV[cl*D_B + jj+1]);
            v.z = clip1(v.z * ri * sRV[cl*D_B + jj+2]);
            v.w = clip1(v.w * ri * sRV[cl*D_B + jj+3]);
            *(float4*)&sX[cl*D_B + jj] = v;
        }
        __syncthreads();
        #pragma unroll
        for (int cl = 0; cl < 8; cl++){
            int c = cc + cl;
            float4 xv = *(const float4*)&sX[cl*D_B + tx*4];
            u64 xx[4] = { bcast2(xv.x), bcast2(xv.y), bcast2(xv.z), bcast2(xv.w) };
            F4U q0, q1, kk0, kk1;
            q0.f  = *(const float4*)&sWQ[c*C_B + k0];
            q1.f  = *(const float4*)&sWQ[c*C_B + k0 + 4];
            kk0.f = *(const float4*)&sWK[c*C_B + k0];
            kk1.f = *(const float4*)&sWK[c*C_B + k0 + 4];
            u64 bq[4] = { q0.u[0],  q0.u[1],  q1.u[0],  q1.u[1]  };
            u64 bk[4] = { kk0.u[0], kk0.u[1], kk1.u[0], kk1.u[1] };
            #pragma unroll
            for (int p = 0; p < 4; p++){
                #pragma unroll
                for (int q = 0; q < 4; q++){
                    aQ[p][q] = ffma2(xx[p], bq[q], aQ[p][q]);
                    aK[p][q] = ffma2(xx[p], bk[q], aK[p][q]);
                }
            }
        }
        __syncthreads();
    }
    #pragma unroll
    for (int q = 0; q < 4; q++){
        #pragma unroll
        for (int h = 0; h < 2; h++){
            int k = k0 + q*2 + h;
            float vq[4], vk[4];
            #pragma unroll
            for (int p = 0; p < 4; p++){
                float lo, hi;
                unpack2(aQ[p][q], lo, hi); vq[p] = h ? hi : lo;
                unpack2(aK[p][q], lo, hi); vk[p] = h ? hi : lo;
            }
            size_t base = ((size_t)(n*C_B + k))*MAT + irow*D_B + tx*4;
            *(float4*)&g_XQ[base] = make_float4(vq[0], vq[1], vq[2], vq[3]);
            *(float4*)&g_XK[base] = make_float4(vk[0], vk[1], vk[2], vk[3]);
        }
    }
}

// ============================================================================
// Kernel 2 helpers: smem-resident 128x128x128 matmuls, 256 threads,
// thread computes an 8x8 output tile as 8x4 f32x2 accumulators.
// ============================================================================
__device__ __forceinline__ void load_tile(float* dst, const float* __restrict__ src, int tid){
    #pragma unroll
    for (int e = tid; e < MAT/4; e += TPB){
        int i = e >> 5, j = (e & 31) * 4;
        *(float4*)&dst[i*STR + j] = *(const float4*)&src[e*4];
    }
}

// X tile: clip(inp * rv_i * rv_j), cov2cor fused
__device__ __forceinline__ void load_X(float* dst, const float* __restrict__ src,
                                       const float* __restrict__ rv, int tid){
    #pragma unroll
    for (int e = tid; e < MAT/4; e += TPB){
        int i = e >> 5, j = (e & 31) * 4;
        float4 v = *(const float4*)&src[e*4];
        float ri = rv[i];
        v.x = clip1(v.x * ri * rv[j+0]);
        v.y = clip1(v.y * ri * rv[j+1]);
        v.z = clip1(v.z * ri * rv[j+2]);
        v.w = clip1(v.w * ri * rv[j+3]);
        *(float4*)&dst[i*STR + j] = v;
    }
}

// C[i][j] = sum_m A[m][i] * B[m][j]        (both operands read along rows)
__device__ __forceinline__ void mm_atb(float* __restrict__ C, const float* __restrict__ A,
                                       const float* __restrict__ B, int tid){
    int tx = tid & 15, ty = tid >> 4;
    int i0 = ty*8, j0 = tx*8;
    u64 acc[8][4];
    #pragma unroll
    for (int p = 0; p < 8; p++)
        #pragma unroll
        for (int q = 0; q < 4; q++) acc[p][q] = 0ull;
    #pragma unroll 2
    for (int m = 0; m < D_B; m++){
        float4 a0 = *(const float4*)&A[m*STR + i0];
        float4 a1 = *(const float4*)&A[m*STR + i0 + 4];
        F4U b0v, b1v;
        b0v.f = *(const float4*)&B[m*STR + j0];
        b1v.f = *(const float4*)&B[m*STR + j0 + 4];
        u64 bb[4] = { b0v.u[0], b0v.u[1], b1v.u[0], b1v.u[1] };
        float av[8] = { a0.x, a0.y, a0.z, a0.w, a1.x, a1.y, a1.z, a1.w };
        #pragma unroll
        for (int p = 0; p < 8; p++){
            u64 ap = bcast2(av[p]);
            #pragma unroll
            for (int q = 0; q < 4; q++) acc[p][q] = ffma2(ap, bb[q], acc[p][q]);
        }
    }
    #pragma unroll
    for (int p = 0; p < 8; p++){
        F4U o0, o1;
        o0.u[0] = acc[p][0]; o0.u[1] = acc[p][1];
        o1.u[0] = acc[p][2]; o1.u[1] = acc[p][3];
        *(float4*)&C[(i0+p)*STR + j0]     = o0.f;
        *(float4*)&C[(i0+p)*STR + j0 + 4] = o1.f;
    }
}

// Same as mm_atb but also computes the per-warp max of outputs into s_red[warp].
__device__ __forceinline__ void mm_atb_mx(float* __restrict__ C, const float* __restrict__ A,
                                          const float* __restrict__ B, int tid,
                                          float* s_red){
    int tx = tid & 15, ty = tid >> 4;
    int i0 = ty*8, j0 = tx*8;
    u64 acc[8][4];
    #pragma unroll
    for (int p = 0; p < 8; p++)
        #pragma unroll
        for (int q = 0; q < 4; q++) acc[p][q] = 0ull;
    #pragma unroll 2
    for (int m = 0; m < D_B; m++){
        float4 a0 = *(const float4*)&A[m*STR + i0];
        float4 a1 = *(const float4*)&A[m*STR + i0 + 4];
        F4U b0v, b1v;
        b0v.f = *(const float4*)&B[m*STR + j0];
        b1v.f = *(const float4*)&B[m*STR + j0 + 4];
        u64 bb[4] = { b0v.u[0], b0v.u[1], b1v.u[0], b1v.u[1] };
        float av[8] = { a0.x, a0.y, a0.z, a0.w, a1.x, a1.y, a1.z, a1.w };
        #pragma unroll
        for (int p = 0; p < 8; p++){
            u64 ap = bcast2(av[p]);
            #pragma unroll
            for (int q = 0; q < 4; q++) acc[p][q] = ffma2(ap, bb[q], acc[p][q]);
        }
    }
    float mx = -3.4e38f;
    #pragma unroll
    for (int p = 0; p < 8; p++){
        F4U o0, o1;
        o0.u[0] = acc[p][0]; o0.u[1] = acc[p][1];
        o1.u[0] = acc[p][2]; o1.u[1] = acc[p][3];
        *(float4*)&C[(i0+p)*STR + j0]     = o0.f;
        *(float4*)&C[(i0+p)*STR + j0 + 4] = o1.f;
        mx = fmaxf(mx, fmaxf(fmaxf(o0.f.x, o0.f.y), fmaxf(o0.f.z, o0.f.w)));
        mx = fmaxf(mx, fmaxf(fmaxf(o1.f.x, o1.f.y), fmaxf(o1.f.z, o1.f.w)));
    }
    #pragma unroll
    for (int o = 16; o; o >>= 1) mx = fmaxf(mx, __shfl_xor_sync(0xffffffffu, mx, o));
    if ((tid & 31) == 0) s_red[tid >> 5] = mx;
}

// C[i][j] = sum_m A[i][m] * B[m][j]        (A read along rows too, m-unroll 4)
__device__ __forceinline__ void mm_ab(float* __restrict__ C, const float* __restrict__ A,
                                      const float* __restrict__ B, int tid){
    int tx = tid & 15, ty = tid >> 4;
    int i0 = ty*8, j0 = tx*8;
    u64 acc[8][4];
    #pragma unroll
    for (int p = 0; p < 8; p++)
        #pragma unroll
        for (int q = 0; q < 4; q++) acc[p][q] = 0ull;
    for (int m = 0; m < D_B; m += 4){
        float4 a4[8];
        #pragma unroll
        for (int p = 0; p < 8; p++) a4[p] = *(const float4*)&A[(i0+p)*STR + m];
        #pragma unroll
        for (int s = 0; s < 4; s++){
            F4U b0v, b1v;
            b0v.f = *(const float4*)&B[(m+s)*STR + j0];
            b1v.f = *(const float4*)&B[(m+s)*STR + j0 + 4];
            u64 bb[4] = { b0v.u[0], b0v.u[1], b1v.u[0], b1v.u[1] };
            #pragma unroll
            for (int p = 0; p < 8; p++){
                float as = (s == 0) ? a4[p].x : (s == 1) ? a4[p].y
                         : (s == 2) ? a4[p].z : a4[p].w;
                u64 ap = bcast2(as);
                #pragma unroll
                for (int q = 0; q < 4; q++) acc[p][q] = ffma2(ap, bb[q], acc[p][q]);
            }
        }
    }
    #pragma unroll
    for (int p = 0; p < 8; p++){
        F4U o0, o1;
        o0.u[0] = acc[p][0]; o0.u[1] = acc[p][1];
        o1.u[0] = acc[p][2]; o1.u[1] = acc[p][3];
        *(float4*)&C[(i0+p)*STR + j0]     = o0.f;
        *(float4*)&C[(i0+p)*STR + j0 + 4] = o1.f;
    }
}

// out = inputs + lam * (A * B), streamed to gmem
__device__ __forceinline__ void mm_ab_out(const float* __restrict__ A, const float* __restrict__ B,
                                          const float* __restrict__ inp, float* __restrict__ out,
                                          float lam, int tid){
    int tx = tid & 15, ty = tid >> 4;
    int i0 = ty*8, j0 = tx*8;
    u64 acc[8][4];
    #pragma unroll
    for (int p = 0; p < 8; p++)
        #pragma unroll
        for (int q = 0; q < 4; q++) acc[p][q] = 0ull;
    for (int m = 0; m < D_B; m += 4){
        float4 a4[8];
        #pragma unroll
        for (int p = 0; p < 8; p++) a4[p] = *(const float4*)&A[(i0+p)*STR + m];
        #pragma unroll
        for (int s = 0; s < 4; s++){
            F4U b0v, b1v;
            b0v.f = *(const float4*)&B[(m+s)*STR + j0];
            b1v.f = *(const float4*)&B[(m+s)*STR + j0 + 4];
            u64 bb[4] = { b0v.u[0], b0v.u[1], b1v.u[0], b1v.u[1] };
            #pragma unroll
            for (int p = 0; p < 8; p++){
                float as = (s == 0) ? a4[p].x : (s == 1) ? a4[p].y
                         : (s == 2) ? a4[p].z : a4[p].w;
                u64 ap = bcast2(as);
                #pragma unroll
                for (int q = 0; q < 4; q++) acc[p][q] = ffma2(ap, bb[q], acc[p][q]);
            }
        }
    }
    #pragma unroll
    for (int p = 0; p < 8; p++){
        int row = i0 + p;
        float4 iv0 = *(const float4*)&inp[row*D_B + j0];
        float4 iv1 = *(const float4*)&inp[row*D_B + j0 + 4];
        float r[8];
        unpack2(acc[p][0], r[0], r[1]); unpack2(acc[p][1], r[2], r[3]);
        unpack2(acc[p][2], r[4], r[5]); unpack2(acc[p][3], r[6], r[7]);
        float4 o0 = make_float4(iv0.x + lam*r[0], iv0.y + lam*r[1],
                                iv0.z + lam*r[2], iv0.w + lam*r[3]);
        float4 o1 = make_float4(iv1.x + lam*r[4], iv1.y + lam*r[5],
                                iv1.z + lam*r[6], iv1.w + lam*r[7]);
        *(float4*)&out[row*D_B + j0]     = o0;
        *(float4*)&out[row*D_B + j0 + 4] = o1;
    }
}

// soft_pd_max given bmax already in s_red[8]. In place on smem tile M.
// Exp pass: 7/16 iterations via fma-pipe poly, 9/16 via MUFU (dual-pipe).
// Separate vectorized row-sum pass (no per-iteration shuffles). Ends synced.
__device__ __forceinline__ void soft_pd(float* M, int tid, float* s_dia,
                                        float* s_rinv, float* s_red){
    float bmax = s_red[8];
    u64 kL2E = bcast2(1.4426950408889634f);
    u64 kMAG = bcast2(12582912.0f);
    u64 kNMAG= bcast2(-12582912.0f);
    u64 kN1  = bcast2(-1.0f);
    u64 kC5  = bcast2(1.3333558146e-3f);
    u64 kC4  = bcast2(9.6181291076e-3f);
    u64 kC3  = bcast2(5.5504108664e-2f);
    u64 kC2  = bcast2(2.4022650695e-1f);
    u64 kC1  = bcast2(6.9314718055e-1f);
    u64 kONE = bcast2(1.0f);
    u64 kNB  = bcast2(-bmax);
    #pragma unroll
    for (int k = 0; k < 16; k++){
        int e = tid + k*TPB;
        int i = e >> 5, j = (e & 31) * 4;
        float4 v = *(const float4*)&M[i*STR + j];
        float4 r;
        if ((k & 1) == 0 && k < 14){         // 7 poly iterations (fma pipe)
            u64 xb0 = add2(pack2(v.x, v.y), kNB);
            u64 xb1 = add2(pack2(v.z, v.w), kNB);
            u64 r0 = exp_pair(xb0, kL2E, kMAG, kNMAG, kN1, kC5, kC4, kC3, kC2, kC1, kONE);
            u64 r1 = exp_pair(xb1, kL2E, kMAG, kNMAG, kN1, kC5, kC4, kC3, kC2, kC1, kONE);
            unpack2(r0, r.x, r.y); unpack2(r1, r.z, r.w);
        } else {                             // 9 MUFU iterations
            r.x = __expf(v.x - bmax); r.y = __expf(v.y - bmax);
            r.z = __expf(v.z - bmax); r.w = __expf(v.w - bmax);
        }
        *(float4*)&M[i*STR + j] = r;
    }
    __syncthreads();
    if (tid < D_B){
        const float* r = M + tid*STR;
        float s = 0.f;
        #pragma unroll
        for (int j4 = 0; j4 < D_B/4; j4++){
            float4 v = *(const float4*)&r[j4*4];
            s += (v.x + v.y) + (v.z + v.w);
        }
        s_dia[tid] = s;
    }
    __syncthreads();
    if (tid < 32){
        float t = s_dia[tid] + s_dia[tid+32] + s_dia[tid+64] + s_dia[tid+96];
        #pragma unroll
        for (int o = 16; o; o >>= 1) t += __shfl_xor_sync(0xffffffffu, t, o);
        if (tid == 0) s_red[9] = t;
    }
    __syncthreads();
    if (tid < D_B){
        float total = s_red[9];
        float d = fmaxf(fmaxf(s_dia[tid], total / 100000.0f), 1e-5f);
        s_rinv[tid] = rsqrtf(d);
    }
    __syncthreads();
    #pragma unroll
    for (int e = tid; e < MAT/4; e += TPB){
        int i = e >> 5, j = (e & 31) * 4;
        float ri = s_rinv[i];
        float4 v = *(float4*)&M[i*STR + j];
        v.x *= ri * s_rinv[j];   v.y *= ri * s_rinv[j+1];
        v.z *= ri * s_rinv[j+2]; v.w *= ri * s_rinv[j+3];
        *(float4*)&M[i*STR + j] = v;
    }
    __syncthreads();
}

// ============================================================================
// Kernel 2: per-(n,k) chain. A_pre = K^T Q K; A = soft_pd(A_pre);
//           out = inputs + lam * (A X A^T)
// ============================================================================
__global__ __launch_bounds__(TPB, 1) void k_attn(const float* __restrict__ inp,
                                                 const float* __restrict__ lam,
                                                 float* __restrict__ out){
    extern __shared__ float sm[];
    float* b0 = sm;                 // XWK -> X -> A^T
    float* b1 = sm +     D_B*STR;   // XWQ -> A_pre -> A
    float* b2 = sm + 2 * D_B*STR;   // St  -> P = A*X
    __shared__ float s_dia[D_B], s_rinvd[D_B], s_rv[D_B], s_red[16];
    int tid = threadIdx.x;
    int nk  = blockIdx.x;
    size_t base = (size_t)nk * MAT;

    if (tid < D_B) s_rv[tid] = g_rv[nk*D_B + tid];
    load_tile(b0, g_XK + base, tid);
    load_tile(b1, g_XQ + base, tid);
    __syncthreads();
    mm_atb(b2, b1, b0, tid);           // St = Q^T K  (== (K^T Q)^T)
    __syncthreads();
    mm_atb_mx(b1, b2, b0, tid, s_red); // A_pre = St^T K; warp maxes -> s_red[0..7]
    __syncthreads();
    if (tid == 0){
        float m2 = s_red[0];
        #pragma unroll
        for (int w = 1; w < TPB/32; w++) m2 = fmaxf(m2, s_red[w]);
        s_red[8] = m2;
    }
    load_X(b0, inp + base, s_rv, tid); // overlap gmem X load with max-combine
    __syncthreads();
    soft_pd(b1, tid, s_dia, s_rinvd, s_red);  // b1 = A (ends synced)
    mm_ab(b2, b1, b0, tid);            // P = A X
    __syncthreads();
    for (int e = tid; e < MAT; e += TPB){     // b0 = A^T
        int i = e >> 7, j = e & 127;
        b0[j*STR + i] = b1[i*STR + j];
    }
    __syncthreads();
    mm_ab_out(b2, b0, inp + base, out + base, lam[nk & (C_B - 1)], tid);
}

// ============================================================================
extern "C" void kernel_launch(void* const* d_in, const int* in_sizes, int n_in,
                              void* d_out, int out_size){
    const float* inp = (const float*)d_in[0];
    const float* wq  = (const float*)d_in[1];
    const float* wk  = (const float*)d_in[2];
    const float* lam = (const float*)d_in[3];
    float* out = (float*)d_out;

    cudaFuncSetAttribute(k_attn, cudaFuncAttributeMaxDynamicSharedMemorySize, SMEM3);

    k_rinv<<<N_B*C_B, D_B>>>(inp);
    k_mix<<<dim3(D_B, N_B), 256>>>(inp, wq, wk);
    k_attn<<<N_B*C_B, TPB, SMEM3>>>(inp, lam, out);
}

// round 6
// speedup vs baseline: 1.0341x; 1.0107x over previous
#include <cuda_runtime.h>

#define N_B 32
#define C_B 64
#define D_B 128
#define MAT (D_B*D_B)          // 16384
#define STR 132                // padded smem row stride (floats)
#define SMEM3 (3*D_B*STR*4)    // 202752 bytes dynamic smem for k_attn
#define TPB 256
#define NK_TOT (N_B*C_B)

typedef unsigned long long u64;

// ---------------- scratch (device globals; no allocations allowed) ----------
__device__ float g_rv[N_B*C_B*D_B];   // rsqrt(max(|diag|,1e-4)) per (n,c,i)
__device__ float g_XQ[N_B*C_B*MAT];   // X mixed by w_queries
__device__ float g_XK[N_B*C_B*MAT];   // X mixed by w_keys

// ---------------- packed f32x2 helpers (2x fp32 FMA throughput) -------------
__device__ __forceinline__ u64 bcast2(float x){
    u64 r; unsigned xi = __float_as_uint(x);
    asm("mov.b64 %0, {%1, %1};" : "=l"(r) : "r"(xi));
    return r;
}
__device__ __forceinline__ u64 pack2(float lo, float hi){
    u64 r;
    asm("mov.b64 %0, {%1, %2};" : "=l"(r) : "r"(__float_as_uint(lo)), "r"(__float_as_uint(hi)));
    return r;
}
__device__ __forceinline__ u64 ffma2(u64 a, u64 b, u64 c){
    u64 d;
    asm("fma.rn.f32x2 %0, %1, %2, %3;" : "=l"(d) : "l"(a), "l"(b), "l"(c));
    return d;
}
__device__ __forceinline__ u64 add2(u64 a, u64 b){
    u64 d;
    asm("add.rn.f32x2 %0, %1, %2;" : "=l"(d) : "l"(a), "l"(b));
    return d;
}
__device__ __forceinline__ u64 mul2(u64 a, u64 b){
    u64 d;
    asm("mul.rn.f32x2 %0, %1, %2;" : "=l"(d) : "l"(a), "l"(b));
    return d;
}
__device__ __forceinline__ void unpack2(u64 v, float& lo, float& hi){
    unsigned a, b;
    asm("mov.b64 {%0, %1}, %2;" : "=r"(a), "=r"(b) : "l"(v));
    lo = __uint_as_float(a); hi = __uint_as_float(b);
}
__device__ __forceinline__ void unpack2u(u64 v, unsigned& a, unsigned& b){
    asm("mov.b64 {%0, %1}, %2;" : "=r"(a), "=r"(b) : "l"(v));
}
union F4U { float4 f; u64 u[2]; };

__device__ __forceinline__ float clip1(float x){
    return fminf(1.f, fmaxf(-1.f, x));
}

// ---------------- cp.async helpers ------------------------------------------
__device__ __forceinline__ void cp16(unsigned saddr, const void* g){
    asm volatile("cp.async.cg.shared.global [%0], [%1], 16;" :: "r"(saddr), "l"(g));
}
__device__ __forceinline__ void cp_commit(){
    asm volatile("cp.async.commit_group;");
}
__device__ __forceinline__ void cp_wait0(){
    asm volatile("cp.async.wait_group 0;");
}

// async copy of a 128x128 tile into padded smem (stride STR)
__device__ __forceinline__ void tile_async(float* dst, const float* __restrict__ src, int tid){
    unsigned base = (unsigned)__cvta_generic_to_shared(dst);
    #pragma unroll
    for (int e = tid; e < MAT/4; e += TPB){
        int i = e >> 5, j = (e & 31) * 4;
        cp16(base + (i*STR + j)*4u, src + e*4);
    }
}

// fma-pipe exp of a packed pair (clamped to >= ~2^-127 at underflow)
__device__ __forceinline__ u64 exp_pair(u64 xb, u64 kL2E, u64 kMAG, u64 kNMAG,
                                        u64 kN1, u64 kC5, u64 kC4, u64 kC3,
                                        u64 kC2, u64 kC1, u64 kONE){
    u64 y = mul2(xb, kL2E);
    u64 z = add2(y, kMAG);
    u64 t = add2(z, kNMAG);
    u64 f = ffma2(t, kN1, y);
    u64 p = ffma2(kC5, f, kC4);
    p = ffma2(p, f, kC3);
    p = ffma2(p, f, kC2);
    p = ffma2(p, f, kC1);
    p = ffma2(p, f, kONE);
    unsigned zl, zh; unpack2u(z, zl, zh);
    int n0 = (int)(zl - 0x4B400000u); n0 = max(n0, -127);
    int n1 = (int)(zh - 0x4B400000u); n1 = max(n1, -127);
    unsigned s0 = (unsigned)(n0 + 127) << 23;
    unsigned s1 = (unsigned)(n1 + 127) << 23;
    u64 s;
    asm("mov.b64 %0, {%1, %2};" : "=l"(s) : "r"(s0), "r"(s1));
    return mul2(p, s);
}

// ============================================================================
// Kernel 0: per-(n,c) diagonal rsqrt factors
// ============================================================================
__global__ void k_rinv(const float* __restrict__ in){
    int nk = blockIdx.x;
    int t  = threadIdx.x;
    float v = in[(size_t)nk*MAT + t*D_B + t];
    g_rv[nk*D_B + t] = rsqrtf(fmaxf(fabsf(v), 1e-4f));
}

// ============================================================================
// Kernel 1: fused cov2cor + channel mixing (unchanged, validated)
// ============================================================================
__global__ __launch_bounds__(256, 1) void k_mix(const float* __restrict__ inp,
                                                const float* __restrict__ wq,
                                                const float* __restrict__ wk){
    __shared__ float sWQ[C_B*C_B];
    __shared__ float sWK[C_B*C_B];
    __shared__ float sX [8*D_B];
    __shared__ float sRV[8*D_B];
    int tid = threadIdx.x;
    int n   = blockIdx.y;
    int irow= blockIdx.x;
    for (int i = tid; i < C_B*C_B; i += 256){ sWQ[i] = wq[i]; sWK[i] = wk[i]; }
    int tx = tid & 31;
    int ty = tid >> 5;
    int k0 = ty * 8;
    u64 aQ[4][4], aK[4][4];
    #pragma unroll
    for (int p = 0; p < 4; p++)
        #pragma unroll
        for (int q = 0; q < 4; q++){ aQ[p][q] = 0ull; aK[p][q] = 0ull; }
    __syncthreads();
    for (int cc = 0; cc < C_B; cc += 8){
        {
            int idx = tid * 4;
            int cl = idx >> 7, j = idx & 127;
            *(float4*)&sRV[idx] = *(const float4*)&g_rv[((size_t)(n*C_B + cc + cl))*D_B + j];
        }
        __syncthreads();
        {
            int cl = tid >> 5, jj = (tid & 31) * 4;
            float4 v = *(const float4*)&inp[((size_t)(n*C_B + cc + cl))*MAT + irow*D_B + jj];
            float ri = sRV[cl*D_B + irow];
            v.x = clip1(v.x * ri * sRV[cl*D_B + jj+0]);
            v.y = clip1(v.y * ri * sRV[cl*D_B + jj+1]);
            v.z = clip1(v.z * ri * sRV[cl*D_B + jj+2]);
            v.w = clip1(v.w * ri * sRV[cl*D_B + jj+3]);
            *(float4*)&sX[cl*D_B + jj] = v;
        }
        __syncthreads();
        #pragma unroll
        for (int cl = 0; cl < 8; cl++){
            int c = cc + cl;
            float4 xv = *(const float4*)&sX[cl*D_B + tx*4];
            u64 xx[4] = { bcast2(xv.x), bcast2(xv.y), bcast2(xv.z), bcast2(xv.w) };
            F4U q0, q1, kk0, kk1;
            q0.f  = *(const float4*)&sWQ[c*C_B + k0];
            q1.f  = *(const float4*)&sWQ[c*C_B + k0 + 4];
            kk0.f = *(const float4*)&sWK[c*C_B + k0];
            kk1.f = *(const float4*)&sWK[c*C_B + k0 + 4];
            u64 bq[4] = { q0.u[0],  q0.u[1],  q1.u[0],  q1.u[1]  };
            u64 bk[4] = { kk0.u[0], kk0.u[1], kk1.u[0], kk1.u[1] };
            #pragma unroll
            for (int p = 0; p < 4; p++){
                #pragma unroll
                for (int q = 0; q < 4; q++){
                    aQ[p][q] = ffma2(xx[p], bq[q], aQ[p][q]);
                    aK[p][q] = ffma2(xx[p], bk[q], aK[p][q]);
                }
            }
        }
        __syncthreads();
    }
    #pragma unroll
    for (int q = 0; q < 4; q++){
        #pragma unroll
        for (int h = 0; h < 2; h++){
            int k = k0 + q*2 + h;
            float vq[4], vk[4];
            #pragma unroll
            for (int p = 0; p < 4; p++){
                float lo, hi;
                unpack2(aQ[p][q], lo, hi); vq[p] = h ? hi : lo;
                unpack2(aK[p][q], lo, hi); vk[p] = h ? hi : lo;
            }
            size_t base = ((size_t)(n*C_B + k))*MAT + irow*D_B + tx*4;
            *(float4*)&g_XQ[base] = make_float4(vq[0], vq[1], vq[2], vq[3]);
            *(float4*)&g_XK[base] = make_float4(vk[0], vk[1], vk[2], vk[3]);
        }
    }
}

// ============================================================================
// k_attn helpers (256 threads, 8x8 register tiles)
// ============================================================================

// C[i][j] = sum_m A[m][i] * B[m][j]
__device__ __forceinline__ void mm_atb(float* __restrict__ C, const float* __restrict__ A,
                                       const float* __restrict__ B, int tid){
    int tx = tid & 15, ty = tid >> 4;
    int i0 = ty*8, j0 = tx*8;
    u64 acc[8][4];
    #pragma unroll
    for (int p = 0; p < 8; p++)
        #pragma unroll
        for (int q = 0; q < 4; q++) acc[p][q] = 0ull;
    #pragma unroll 2
    for (int m = 0; m < D_B; m++){
        float4 a0 = *(const float4*)&A[m*STR + i0];
        float4 a1 = *(const float4*)&A[m*STR + i0 + 4];
        F4U b0v, b1v;
        b0v.f = *(const float4*)&B[m*STR + j0];
        b1v.f = *(const float4*)&B[m*STR + j0 + 4];
        u64 bb[4] = { b0v.u[0], b0v.u[1], b1v.u[0], b1v.u[1] };
        float av[8] = { a0.x, a0.y, a0.z, a0.w, a1.x, a1.y, a1.z, a1.w };
        #pragma unroll
        for (int p = 0; p < 8; p++){
            u64 ap = bcast2(av[p]);
            #pragma unroll
            for (int q = 0; q < 4; q++) acc[p][q] = ffma2(ap, bb[q], acc[p][q]);
        }
    }
    #pragma unroll
    for (int p = 0; p < 8; p++){
        F4U o0, o1;
        o0.u[0] = acc[p][0]; o0.u[1] = acc[p][1];
        o1.u[0] = acc[p][2]; o1.u[1] = acc[p][3];
        *(float4*)&C[(i0+p)*STR + j0]     = o0.f;
        *(float4*)&C[(i0+p)*STR + j0 + 4] = o1.f;
    }
}

// mm_atb + per-warp output max into s_red[warp]
__device__ __forceinline__ void mm_atb_mx(float* __restrict__ C, const float* __restrict__ A,
                                          const float* __restrict__ B, int tid,
                                          float* s_red){
    int tx = tid & 15, ty = tid >> 4;
    int i0 = ty*8, j0 = tx*8;
    u64 acc[8][4];
    #pragma unroll
    for (int p = 0; p < 8; p++)
        #pragma unroll
        for (int q = 0; q < 4; q++) acc[p][q] = 0ull;
    #pragma unroll 2
    for (int m = 0; m < D_B; m++){
        float4 a0 = *(const float4*)&A[m*STR + i0];
        float4 a1 = *(const float4*)&A[m*STR + i0 + 4];
        F4U b0v, b1v;
        b0v.f = *(const float4*)&B[m*STR + j0];
        b1v.f = *(const float4*)&B[m*STR + j0 + 4];
        u64 bb[4] = { b0v.u[0], b0v.u[1], b1v.u[0], b1v.u[1] };
        float av[8] = { a0.x, a0.y, a0.z, a0.w, a1.x, a1.y, a1.z, a1.w };
        #pragma unroll
        for (int p = 0; p < 8; p++){
            u64 ap = bcast2(av[p]);
            #pragma unroll
            for (int q = 0; q < 4; q++) acc[p][q] = ffma2(ap, bb[q], acc[p][q]);
        }
    }
    float mx = -3.4e38f;
    #pragma unroll
    for (int p = 0; p < 8; p++){
        F4U o0, o1;
        o0.u[0] = acc[p][0]; o0.u[1] = acc[p][1];
        o1.u[0] = acc[p][2]; o1.u[1] = acc[p][3];
        *(float4*)&C[(i0+p)*STR + j0]     = o0.f;
        *(float4*)&C[(i0+p)*STR + j0 + 4] = o1.f;
        mx = fmaxf(mx, fmaxf(fmaxf(o0.f.x, o0.f.y), fmaxf(o0.f.z, o0.f.w)));
        mx = fmaxf(mx, fmaxf(fmaxf(o1.f.x, o1.f.y), fmaxf(o1.f.z, o1.f.w)));
    }
    #pragma unroll
    for (int o = 16; o; o >>= 1) mx = fmaxf(mx, __shfl_xor_sync(0xffffffffu, mx, o));
    if ((tid & 31) == 0) s_red[tid >> 5] = mx;
}

// C[i][j] = sum_m A[i][m] * B[m][j]
__device__ __forceinline__ void mm_ab(float* __restrict__ C, const float* __restrict__ A,
                                      const float* __restrict__ B, int tid){
    int tx = tid & 15, ty = tid >> 4;
    int i0 = ty*8, j0 = tx*8;
    u64 acc[8][4];
    #pragma unroll
    for (int p = 0; p < 8; p++)
        #pragma unroll
        for (int q = 0; q < 4; q++) acc[p][q] = 0ull;
    for (int m = 0; m < D_B; m += 4){
        float4 a4[8];
        #pragma unroll
        for (int p = 0; p < 8; p++) a4[p] = *(const float4*)&A[(i0+p)*STR + m];
        #pragma unroll
        for (int s = 0; s < 4; s++){
            F4U b0v, b1v;
            b0v.f = *(const float4*)&B[(m+s)*STR + j0];
            b1v.f = *(const float4*)&B[(m+s)*STR + j0 + 4];
            u64 bb[4] = { b0v.u[0], b0v.u[1], b1v.u[0], b1v.u[1] };
            #pragma unroll
            for (int p = 0; p < 8; p++){
                float as = (s == 0) ? a4[p].x : (s == 1) ? a4[p].y
                         : (s == 2) ? a4[p].z : a4[p].w;
                u64 ap = bcast2(as);
                #pragma unroll
                for (int q = 0; q < 4; q++) acc[p][q] = ffma2(ap, bb[q], acc[p][q]);
            }
        }
    }
    #pragma unroll
    for (int p = 0; p < 8; p++){
        F4U o0, o1;
        o0.u[0] = acc[p][0]; o0.u[1] = acc[p][1];
        o1.u[0] = acc[p][2]; o1.u[1] = acc[p][3];
        *(float4*)&C[(i0+p)*STR + j0]     = o0.f;
        *(float4*)&C[(i0+p)*STR + j0 + 4] = o1.f;
    }
}

// out = inputs + lam * sr_i * (A*B)[i][j] * sr_j, streamed to gmem
__device__ __forceinline__ void mm_ab_out(const float* __restrict__ A, const float* __restrict__ B,
                                          const float* __restrict__ inp, float* __restrict__ out,
                                          float lam, const float* __restrict__ sr, int tid){
    int tx = tid & 15, ty = tid >> 4;
    int i0 = ty*8, j0 = tx*8;
    u64 acc[8][4];
    #pragma unroll
    for (int p = 0; p < 8; p++)
        #pragma unroll
        for (int q = 0; q < 4; q++) acc[p][q] = 0ull;
    for (int m = 0; m < D_B; m += 4){
        float4 a4[8];
        #pragma unroll
        for (int p = 0; p < 8; p++) a4[p] = *(const float4*)&A[(i0+p)*STR + m];
        #pragma unroll
        for (int s = 0; s < 4; s++){
            F4U b0v, b1v;
            b0v.f = *(const float4*)&B[(m+s)*STR + j0];
            b1v.f = *(const float4*)&B[(m+s)*STR + j0 + 4];
            u64 bb[4] = { b0v.u[0], b0v.u[1], b1v.u[0], b1v.u[1] };
            #pragma unroll
            for (int p = 0; p < 8; p++){
                float as = (s == 0) ? a4[p].x : (s == 1) ? a4[p].y
                         : (s == 2) ? a4[p].z : a4[p].w;
                u64 ap = bcast2(as);
                #pragma unroll
                for (int q = 0; q < 4; q++) acc[p][q] = ffma2(ap, bb[q], acc[p][q]);
            }
        }
    }
    float4 sj0 = *(const float4*)&sr[j0];
    float4 sj1 = *(const float4*)&sr[j0 + 4];
    #pragma unroll
    for (int p = 0; p < 8; p++){
        int row = i0 + p;
        float li = lam * sr[row];
        float4 iv0 = *(const float4*)&inp[row*D_B + j0];
        float4 iv1 = *(const float4*)&inp[row*D_B + j0 + 4];
        float r[8];
        unpack2(acc[p][0], r[0], r[1]); unpack2(acc[p][1], r[2], r[3]);
        unpack2(acc[p][2], r[4], r[5]); unpack2(acc[p][3], r[6], r[7]);
        float4 o0 = make_float4(iv0.x + li*sj0.x*r[0], iv0.y + li*sj0.y*r[1],
                                iv0.z + li*sj0.z*r[2], iv0.w + li*sj0.w*r[3]);
        float4 o1 = make_float4(iv1.x + li*sj1.x*r[4], iv1.y + li*sj1.y*r[5],
                                iv1.z + li*sj1.z*r[6], iv1.w + li*sj1.w*r[7]);
        *(float4*)&out[row*D_B + j0]     = o0;
        *(float4*)&out[row*D_B + j0 + 4] = o1;
    }
}

// exp pass (in place, dual-pipe) + row sums + s_rinv. NO final rescale pass
// (the S-scalings are folded into the X transform and epilogue). Ends synced.
__device__ __forceinline__ void soft_pd2(float* M, int tid, float* s_dia,
                                         float* s_rinv, float* s_red){
    float bmax = s_red[8];
    u64 kL2E = bcast2(1.4426950408889634f);
    u64 kMAG = bcast2(12582912.0f);
    u64 kNMAG= bcast2(-12582912.0f);
    u64 kN1  = bcast2(-1.0f);
    u64 kC5  = bcast2(1.3333558146e-3f);
    u64 kC4  = bcast2(9.6181291076e-3f);
    u64 kC3  = bcast2(5.5504108664e-2f);
    u64 kC2  = bcast2(2.4022650695e-1f);
    u64 kC1  = bcast2(6.9314718055e-1f);
    u64 kONE = bcast2(1.0f);
    u64 kNB  = bcast2(-bmax);
    #pragma unroll
    for (int k = 0; k < 16; k++){
        int e = tid + k*TPB;
        int i = e >> 5, j = (e & 31) * 4;
        float4 v = *(const float4*)&M[i*STR + j];
        float4 r;
        if ((k & 1) == 0 && k < 14){
            u64 xb0 = add2(pack2(v.x, v.y), kNB);
            u64 xb1 = add2(pack2(v.z, v.w), kNB);
            u64 r0 = exp_pair(xb0, kL2E, kMAG, kNMAG, kN1, kC5, kC4, kC3, kC2, kC1, kONE);
            u64 r1 = exp_pair(xb1, kL2E, kMAG, kNMAG, kN1, kC5, kC4, kC3, kC2, kC1, kONE);
            unpack2(r0, r.x, r.y); unpack2(r1, r.z, r.w);
        } else {
            r.x = __expf(v.x - bmax); r.y = __expf(v.y - bmax);
            r.z = __expf(v.z - bmax); r.w = __expf(v.w - bmax);
        }
        *(float4*)&M[i*STR + j] = r;
    }
    __syncthreads();
    if (tid < D_B){
        const float* r = M + tid*STR;
        float s = 0.f;
        #pragma unroll
        for (int j4 = 0; j4 < D_B/4; j4++){
            float4 v = *(const float4*)&r[j4*4];
            s += (v.x + v.y) + (v.z + v.w);
        }
        s_dia[tid] = s;
    }
    __syncthreads();
    if (tid < 32){
        float t = s_dia[tid] + s_dia[tid+32] + s_dia[tid+64] + s_dia[tid+96];
        #pragma unroll
        for (int o = 16; o; o >>= 1) t += __shfl_xor_sync(0xffffffffu, t, o);
        if (tid == 0) s_red[9] = t;
    }
    __syncthreads();
    if (tid < D_B){
        float total = s_red[9];
        float d = fmaxf(fmaxf(s_dia[tid], total / 100000.0f), 1e-5f);
        s_rinv[tid] = rsqrtf(d);
    }
    __syncthreads();
}

// ============================================================================
// Kernel 2: persistent, cp.async-pipelined per-(n,k) chain.
//   A_pre = K^T Q K; e = exp(A_pre - max); sr from row sums;
//   out = inp + lam * S (e (S X S) e^T) S
// Buffer rotation per iter:  b1:XQ->e   b0:XK->P   b2:St->X''->e^T
// ============================================================================
__global__ __launch_bounds__(TPB, 1) void k_attn(const float* __restrict__ inp,
                                                 const float* __restrict__ lam,
                                                 float* __restrict__ out){
    extern __shared__ float sm[];
    float* b0 = sm;
    float* b1 = sm +     D_B*STR;
    float* b2 = sm + 2 * D_B*STR;
    __shared__ float s_dia[D_B], s_rinvd[D_B], s_rv[D_B], s_red[16];
    int tid = threadIdx.x;
    int stride = gridDim.x;
    int nk = blockIdx.x;
    if (nk >= NK_TOT) return;

    tile_async(b1, g_XQ + (size_t)nk*MAT, tid);  // prefetch first XQ
    cp_commit();

    for (; nk < NK_TOT; nk += stride){
        size_t base = (size_t)nk * MAT;
        tile_async(b0, g_XK + base, tid);
        cp_commit();
        if (tid < D_B) s_rv[tid] = g_rv[nk*D_B + tid];
        cp_wait0();
        __syncthreads();

        mm_atb(b2, b1, b0, tid);               // St = Q^T K
        __syncthreads();
        mm_atb_mx(b1, b2, b0, tid, s_red);     // A_pre = St^T K (b1), warp maxes
        __syncthreads();
        if (tid == 0){
            float m2 = s_red[0];
            #pragma unroll
            for (int w = 1; w < TPB/32; w++) m2 = fmaxf(m2, s_red[w]);
            s_red[8] = m2;
        }
        tile_async(b2, inp + base, tid);       // raw X tile, lands during soft_pd2
        cp_commit();
        __syncthreads();                       // bmax visible

        soft_pd2(b1, tid, s_dia, s_rinvd, s_red);  // b1 = e, s_rinvd ready
        cp_wait0();                            // X arrived

        // X'' = sr_i * sr_j * clip(inp * rv_i * rv_j), in place on b2
        #pragma unroll
        for (int e = tid; e < MAT/4; e += TPB){
            int i = e >> 5, j = (e & 31) * 4;
            float4 v = *(float4*)&b2[i*STR + j];
            float ai = s_rv[i], bi = s_rinvd[i];
            v.x = clip1(v.x * ai * s_rv[j+0]) * bi * s_rinvd[j+0];
            v.y = clip1(v.y * ai * s_rv[j+1]) * bi * s_rinvd[j+1];
            v.z = clip1(v.z * ai * s_rv[j+2]) * bi * s_rinvd[j+2];
            v.w = clip1(v.w * ai * s_rv[j+3]) * bi * s_rinvd[j+3];
            *(float4*)&b2[i*STR + j] = v;
        }
        __syncthreads();

        mm_ab(b0, b1, b2, tid);                // P = e * X''  (b0)
        __syncthreads();
        for (int e = tid; e < MAT; e += TPB){  // b2 = e^T
            int i = e >> 7, j = e & 127;
            b2[j*STR + i] = b1[i*STR + j];
        }
        __syncthreads();
        int nk2 = nk + stride;
        if (nk2 < NK_TOT){                     // prefetch next XQ during epilogue
            tile_async(b1, g_XQ + (size_t)nk2*MAT, tid);
            cp_commit();
        }
        mm_ab_out(b0, b2, inp + base, out + base,
                  lam[nk & (C_B - 1)], s_rinvd, tid);
        __syncthreads();
    }
}

// ============================================================================
extern "C" void kernel_launch(void* const* d_in, const int* in_sizes, int n_in,
                              void* d_out, int out_size){
    const float* inp = (const float*)d_in[0];
    const float* wq  = (const float*)d_in[1];
    const float* wk  = (const float*)d_in[2];
    const float* lam = (const float*)d_in[3];
    float* out = (float*)d_out;

    int nsm = 148;
    cudaDeviceGetAttribute(&nsm, cudaDevAttrMultiProcessorCount, 0);
    if (nsm <= 0 || nsm > NK_TOT) nsm = 148;

    cudaFuncSetAttribute(k_attn, cudaFuncAttributeMaxDynamicSharedMemorySize, SMEM3);

    k_rinv<<<N_B*C_B, D_B>>>(inp);
    k_mix<<<dim3(D_B, N_B), 256>>>(inp, wq, wk);
    k_attn<<<nsm, TPB, SMEM3>>>(inp, lam, out);
}

// round 7
// speedup vs baseline: 1.0422x; 1.0079x over previous
#include <cuda_runtime.h>

#define N_B 32
#define C_B 64
#define D_B 128
#define MAT (D_B*D_B)          // 16384
#define STR 132                // padded smem row stride (floats)
#define SMEM3 (3*D_B*STR*4)    // 202752 bytes dynamic smem for k_attn
#define TPB 256
#define NK_TOT (N_B*C_B)

typedef unsigned long long u64;

// ---------------- scratch (device globals; no allocations allowed) ----------
__device__ float g_rv[N_B*C_B*D_B];   // rsqrt(max(|diag|,1e-4)) per (n,c,i)
__device__ float g_XQ[N_B*C_B*MAT];   // X mixed by w_queries
__device__ float g_XK[N_B*C_B*MAT];   // X mixed by w_keys

// ---------------- packed f32x2 helpers (2x fp32 FMA throughput) -------------
__device__ __forceinline__ u64 bcast2(float x){
    u64 r; unsigned xi = __float_as_uint(x);
    asm("mov.b64 %0, {%1, %1};" : "=l"(r) : "r"(xi));
    return r;
}
__device__ __forceinline__ u64 pack2(float lo, float hi){
    u64 r;
    asm("mov.b64 %0, {%1, %2};" : "=l"(r) : "r"(__float_as_uint(lo)), "r"(__float_as_uint(hi)));
    return r;
}
__device__ __forceinline__ u64 ffma2(u64 a, u64 b, u64 c){
    u64 d;
    asm("fma.rn.f32x2 %0, %1, %2, %3;" : "=l"(d) : "l"(a), "l"(b), "l"(c));
    return d;
}
__device__ __forceinline__ u64 add2(u64 a, u64 b){
    u64 d;
    asm("add.rn.f32x2 %0, %1, %2;" : "=l"(d) : "l"(a), "l"(b));
    return d;
}
__device__ __forceinline__ u64 mul2(u64 a, u64 b){
    u64 d;
    asm("mul.rn.f32x2 %0, %1, %2;" : "=l"(d) : "l"(a), "l"(b));
    return d;
}
__device__ __forceinline__ void unpack2(u64 v, float& lo, float& hi){
    unsigned a, b;
    asm("mov.b64 {%0, %1}, %2;" : "=r"(a), "=r"(b) : "l"(v));
    lo = __uint_as_float(a); hi = __uint_as_float(b);
}
__device__ __forceinline__ void unpack2u(u64 v, unsigned& a, unsigned& b){
    asm("mov.b64 {%0, %1}, %2;" : "=r"(a), "=r"(b) : "l"(v));
}
union F4U { float4 f; u64 u[2]; };

__device__ __forceinline__ float clip1(float x){
    return fminf(1.f, fmaxf(-1.f, x));
}

// ---------------- cp.async helpers ------------------------------------------
__device__ __forceinline__ void cp16(unsigned saddr, const void* g){
    asm volatile("cp.async.cg.shared.global [%0], [%1], 16;" :: "r"(saddr), "l"(g));
}
__device__ __forceinline__ void cp_commit(){
    asm volatile("cp.async.commit_group;");
}
__device__ __forceinline__ void cp_wait0(){
    asm volatile("cp.async.wait_group 0;");
}

// async copy of a 128x128 tile into padded smem (stride STR)
__device__ __forceinline__ void tile_async(float* dst, const float* __restrict__ src, int tid){
    unsigned base = (unsigned)__cvta_generic_to_shared(dst);
    #pragma unroll
    for (int e = tid; e < MAT/4; e += TPB){
        int i = e >> 5, j = (e & 31) * 4;
        cp16(base + (i*STR + j)*4u, src + e*4);
    }
}

// fma-pipe exp of a packed pair (clamped to >= ~2^-127 at underflow)
__device__ __forceinline__ u64 exp_pair(u64 xb, u64 kL2E, u64 kMAG, u64 kNMAG,
                                        u64 kN1, u64 kC5, u64 kC4, u64 kC3,
                                        u64 kC2, u64 kC1, u64 kONE){
    u64 y = mul2(xb, kL2E);
    u64 z = add2(y, kMAG);
    u64 t = add2(z, kNMAG);
    u64 f = ffma2(t, kN1, y);
    u64 p = ffma2(kC5, f, kC4);
    p = ffma2(p, f, kC3);
    p = ffma2(p, f, kC2);
    p = ffma2(p, f, kC1);
    p = ffma2(p, f, kONE);
    unsigned zl, zh; unpack2u(z, zl, zh);
    int n0 = (int)(zl - 0x4B400000u); n0 = max(n0, -127);
    int n1 = (int)(zh - 0x4B400000u); n1 = max(n1, -127);
    unsigned s0 = (unsigned)(n0 + 127) << 23;
    unsigned s1 = (unsigned)(n1 + 127) << 23;
    u64 s;
    asm("mov.b64 %0, {%1, %2};" : "=l"(s) : "r"(s0), "r"(s1));
    return mul2(p, s);
}

// ============================================================================
// Kernel 0: per-(n,c) diagonal rsqrt factors
// ============================================================================
__global__ void k_rinv(const float* __restrict__ in){
    int nk = blockIdx.x;
    int t  = threadIdx.x;
    float v = in[(size_t)nk*MAT + t*D_B + t];
    g_rv[nk*D_B + t] = rsqrtf(fmaxf(fabsf(v), 1e-4f));
}

// ============================================================================
// Kernel 1: fused cov2cor + channel mixing (unchanged, validated)
// ============================================================================
__global__ __launch_bounds__(256, 1) void k_mix(const float* __restrict__ inp,
                                                const float* __restrict__ wq,
                                                const float* __restrict__ wk){
    __shared__ float sWQ[C_B*C_B];
    __shared__ float sWK[C_B*C_B];
    __shared__ float sX [8*D_B];
    __shared__ float sRV[8*D_B];
    int tid = threadIdx.x;
    int n   = blockIdx.y;
    int irow= blockIdx.x;
    for (int i = tid; i < C_B*C_B; i += 256){ sWQ[i] = wq[i]; sWK[i] = wk[i]; }
    int tx = tid & 31;
    int ty = tid >> 5;
    int k0 = ty * 8;
    u64 aQ[4][4], aK[4][4];
    #pragma unroll
    for (int p = 0; p < 4; p++)
        #pragma unroll
        for (int q = 0; q < 4; q++){ aQ[p][q] = 0ull; aK[p][q] = 0ull; }
    __syncthreads();
    for (int cc = 0; cc < C_B; cc += 8){
        {
            int idx = tid * 4;
            int cl = idx >> 7, j = idx & 127;
            *(float4*)&sRV[idx] = *(const float4*)&g_rv[((size_t)(n*C_B + cc + cl))*D_B + j];
        }
        __syncthreads();
        {
            int cl = tid >> 5, jj = (tid & 31) * 4;
            float4 v = *(const float4*)&inp[((size_t)(n*C_B + cc + cl))*MAT + irow*D_B + jj];
            float ri = sRV[cl*D_B + irow];
            v.x = clip1(v.x * ri * sRV[cl*D_B + jj+0]);
            v.y = clip1(v.y * ri * sRV[cl*D_B + jj+1]);
            v.z = clip1(v.z * ri * sRV[cl*D_B + jj+2]);
            v.w = clip1(v.w * ri * sRV[cl*D_B + jj+3]);
            *(float4*)&sX[cl*D_B + jj] = v;
        }
        __syncthreads();
        #pragma unroll
        for (int cl = 0; cl < 8; cl++){
            int c = cc + cl;
            float4 xv = *(const float4*)&sX[cl*D_B + tx*4];
            u64 xx[4] = { bcast2(xv.x), bcast2(xv.y), bcast2(xv.z), bcast2(xv.w) };
            F4U q0, q1, kk0, kk1;
            q0.f  = *(const float4*)&sWQ[c*C_B + k0];
            q1.f  = *(const float4*)&sWQ[c*C_B + k0 + 4];
            kk0.f = *(const float4*)&sWK[c*C_B + k0];
            kk1.f = *(const float4*)&sWK[c*C_B + k0 + 4];
            u64 bq[4] = { q0.u[0],  q0.u[1],  q1.u[0],  q1.u[1]  };
            u64 bk[4] = { kk0.u[0], kk0.u[1], kk1.u[0], kk1.u[1] };
            #pragma unroll
            for (int p = 0; p < 4; p++){
                #pragma unroll
                for (int q = 0; q < 4; q++){
                    aQ[p][q] = ffma2(xx[p], bq[q], aQ[p][q]);
                    aK[p][q] = ffma2(xx[p], bk[q], aK[p][q]);
                }
            }
        }
        __syncthreads();
    }
    #pragma unroll
    for (int q = 0; q < 4; q++){
        #pragma unroll
        for (int h = 0; h < 2; h++){
            int k = k0 + q*2 + h;
            float vq[4], vk[4];
            #pragma unroll
            for (int p = 0; p < 4; p++){
                float lo, hi;
                unpack2(aQ[p][q], lo, hi); vq[p] = h ? hi : lo;
                unpack2(aK[p][q], lo, hi); vk[p] = h ? hi : lo;
            }
            size_t base = ((size_t)(n*C_B + k))*MAT + irow*D_B + tx*4;
            *(float4*)&g_XQ[base] = make_float4(vq[0], vq[1], vq[2], vq[3]);
            *(float4*)&g_XK[base] = make_float4(vk[0], vk[1], vk[2], vk[3]);
        }
    }
}

// ============================================================================
// k_attn helpers (256 threads, 8x8 register tiles)
// ============================================================================

// C[i][j] = sum_m A[m][i] * B[m][j]
__device__ __forceinline__ void mm_atb(float* __restrict__ C, const float* __restrict__ A,
                                       const float* __restrict__ B, int tid){
    int tx = tid & 15, ty = tid >> 4;
    int i0 = ty*8, j0 = tx*8;
    u64 acc[8][4];
    #pragma unroll
    for (int p = 0; p < 8; p++)
        #pragma unroll
        for (int q = 0; q < 4; q++) acc[p][q] = 0ull;
    #pragma unroll 2
    for (int m = 0; m < D_B; m++){
        float4 a0 = *(const float4*)&A[m*STR + i0];
        float4 a1 = *(const float4*)&A[m*STR + i0 + 4];
        F4U b0v, b1v;
        b0v.f = *(const float4*)&B[m*STR + j0];
        b1v.f = *(const float4*)&B[m*STR + j0 + 4];
        u64 bb[4] = { b0v.u[0], b0v.u[1], b1v.u[0], b1v.u[1] };
        float av[8] = { a0.x, a0.y, a0.z, a0.w, a1.x, a1.y, a1.z, a1.w };
        #pragma unroll
        for (int p = 0; p < 8; p++){
            u64 ap = bcast2(av[p]);
            #pragma unroll
            for (int q = 0; q < 4; q++) acc[p][q] = ffma2(ap, bb[q], acc[p][q]);
        }
    }
    #pragma unroll
    for (int p = 0; p < 8; p++){
        F4U o0, o1;
        o0.u[0] = acc[p][0]; o0.u[1] = acc[p][1];
        o1.u[0] = acc[p][2]; o1.u[1] = acc[p][3];
        *(float4*)&C[(i0+p)*STR + j0]     = o0.f;
        *(float4*)&C[(i0+p)*STR + j0 + 4] = o1.f;
    }
}

// mm_atb + per-warp output max into s_red[warp]
__device__ __forceinline__ void mm_atb_mx(float* __restrict__ C, const float* __restrict__ A,
                                          const float* __restrict__ B, int tid,
                                          float* s_red){
    int tx = tid & 15, ty = tid >> 4;
    int i0 = ty*8, j0 = tx*8;
    u64 acc[8][4];
    #pragma unroll
    for (int p = 0; p < 8; p++)
        #pragma unroll
        for (int q = 0; q < 4; q++) acc[p][q] = 0ull;
    #pragma unroll 2
    for (int m = 0; m < D_B; m++){
        float4 a0 = *(const float4*)&A[m*STR + i0];
        float4 a1 = *(const float4*)&A[m*STR + i0 + 4];
        F4U b0v, b1v;
        b0v.f = *(const float4*)&B[m*STR + j0];
        b1v.f = *(const float4*)&B[m*STR + j0 + 4];
        u64 bb[4] = { b0v.u[0], b0v.u[1], b1v.u[0], b1v.u[1] };
        float av[8] = { a0.x, a0.y, a0.z, a0.w, a1.x, a1.y, a1.z, a1.w };
        #pragma unroll
        for (int p = 0; p < 8; p++){
            u64 ap = bcast2(av[p]);
            #pragma unroll
            for (int q = 0; q < 4; q++) acc[p][q] = ffma2(ap, bb[q], acc[p][q]);
        }
    }
    float mx = -3.4e38f;
    #pragma unroll
    for (int p = 0; p < 8; p++){
        F4U o0, o1;
        o0.u[0] = acc[p][0]; o0.u[1] = acc[p][1];
        o1.u[0] = acc[p][2]; o1.u[1] = acc[p][3];
        *(float4*)&C[(i0+p)*STR + j0]     = o0.f;
        *(float4*)&C[(i0+p)*STR + j0 + 4] = o1.f;
        mx = fmaxf(mx, fmaxf(fmaxf(o0.f.x, o0.f.y), fmaxf(o0.f.z, o0.f.w)));
        mx = fmaxf(mx, fmaxf(fmaxf(o1.f.x, o1.f.y), fmaxf(o1.f.z, o1.f.w)));
    }
    #pragma unroll
    for (int o = 16; o; o >>= 1) mx = fmaxf(mx, __shfl_xor_sync(0xffffffffu, mx, o));
    if ((tid & 31) == 0) s_red[tid >> 5] = mx;
}

// C[i][j] = sum_m A[i][m] * B[m][j]
__device__ __forceinline__ void mm_ab(float* __restrict__ C, const float* __restrict__ A,
                                      const float* __restrict__ B, int tid){
    int tx = tid & 15, ty = tid >> 4;
    int i0 = ty*8, j0 = tx*8;
    u64 acc[8][4];
    #pragma unroll
    for (int p = 0; p < 8; p++)
        #pragma unroll
        for (int q = 0; q < 4; q++) acc[p][q] = 0ull;
    for (int m = 0; m < D_B; m += 4){
        float4 a4[8];
        #pragma unroll
        for (int p = 0; p < 8; p++) a4[p] = *(const float4*)&A[(i0+p)*STR + m];
        #pragma unroll
        for (int s = 0; s < 4; s++){
            F4U b0v, b1v;
            b0v.f = *(const float4*)&B[(m+s)*STR + j0];
            b1v.f = *(const float4*)&B[(m+s)*STR + j0 + 4];
            u64 bb[4] = { b0v.u[0], b0v.u[1], b1v.u[0], b1v.u[1] };
            #pragma unroll
            for (int p = 0; p < 8; p++){
                float as = (s == 0) ? a4[p].x : (s == 1) ? a4[p].y
                         : (s == 2) ? a4[p].z : a4[p].w;
                u64 ap = bcast2(as);
                #pragma unroll
                for (int q = 0; q < 4; q++) acc[p][q] = ffma2(ap, bb[q], acc[p][q]);
            }
        }
    }
    #pragma unroll
    for (int p = 0; p < 8; p++){
        F4U o0, o1;
        o0.u[0] = acc[p][0]; o0.u[1] = acc[p][1];
        o1.u[0] = acc[p][2]; o1.u[1] = acc[p][3];
        *(float4*)&C[(i0+p)*STR + j0]     = o0.f;
        *(float4*)&C[(i0+p)*STR + j0 + 4] = o1.f;
    }
}

// out = inputs + lam * sr_i * (A*B)[i][j] * sr_j, streamed to gmem
__device__ __forceinline__ void mm_ab_out(const float* __restrict__ A, const float* __restrict__ B,
                                          const float* __restrict__ inp, float* __restrict__ out,
                                          float lam, const float* __restrict__ sr, int tid){
    int tx = tid & 15, ty = tid >> 4;
    int i0 = ty*8, j0 = tx*8;
    u64 acc[8][4];
    #pragma unroll
    for (int p = 0; p < 8; p++)
        #pragma unroll
        for (int q = 0; q < 4; q++) acc[p][q] = 0ull;
    for (int m = 0; m < D_B; m += 4){
        float4 a4[8];
        #pragma unroll
        for (int p = 0; p < 8; p++) a4[p] = *(const float4*)&A[(i0+p)*STR + m];
        #pragma unroll
        for (int s = 0; s < 4; s++){
            F4U b0v, b1v;
            b0v.f = *(const float4*)&B[(m+s)*STR + j0];
            b1v.f = *(const float4*)&B[(m+s)*STR + j0 + 4];
            u64 bb[4] = { b0v.u[0], b0v.u[1], b1v.u[0], b1v.u[1] };
            #pragma unroll
            for (int p = 0; p < 8; p++){
                float as = (s == 0) ? a4[p].x : (s == 1) ? a4[p].y
                         : (s == 2) ? a4[p].z : a4[p].w;
                u64 ap = bcast2(as);
                #pragma unroll
                for (int q = 0; q < 4; q++) acc[p][q] = ffma2(ap, bb[q], acc[p][q]);
            }
        }
    }
    float4 sj0 = *(const float4*)&sr[j0];
    float4 sj1 = *(const float4*)&sr[j0 + 4];
    #pragma unroll
    for (int p = 0; p < 8; p++){
        int row = i0 + p;
        float li = lam * sr[row];
        float4 iv0 = *(const float4*)&inp[row*D_B + j0];
        float4 iv1 = *(const float4*)&inp[row*D_B + j0 + 4];
        float r[8];
        unpack2(acc[p][0], r[0], r[1]); unpack2(acc[p][1], r[2], r[3]);
        unpack2(acc[p][2], r[4], r[5]); unpack2(acc[p][3], r[6], r[7]);
        float4 o0 = make_float4(iv0.x + li*sj0.x*r[0], iv0.y + li*sj0.y*r[1],
                                iv0.z + li*sj0.z*r[2], iv0.w + li*sj0.w*r[3]);
        float4 o1 = make_float4(iv1.x + li*sj1.x*r[4], iv1.y + li*sj1.y*r[5],
                                iv1.z + li*sj1.z*r[6], iv1.w + li*sj1.w*r[7]);
        *(float4*)&out[row*D_B + j0]     = o0;
        *(float4*)&out[row*D_B + j0 + 4] = o1;
    }
}

// exp pass (in place, dual-pipe) + row sums + s_rinv. NO final rescale pass
// (the S-scalings are folded into the X transform and epilogue). Ends synced.
__device__ __forceinline__ void soft_pd2(float* M, int tid, float* s_dia,
                                         float* s_rinv, float* s_red){
    float bmax = s_red[8];
    u64 kL2E = bcast2(1.4426950408889634f);
    u64 kMAG = bcast2(12582912.0f);
    u64 kNMAG= bcast2(-12582912.0f);
    u64 kN1  = bcast2(-1.0f);
    u64 kC5  = bcast2(1.3333558146e-3f);
    u64 kC4  = bcast2(9.6181291076e-3f);
    u64 kC3  = bcast2(5.5504108664e-2f);
    u64 kC2  = bcast2(2.4022650695e-1f);
    u64 kC1  = bcast2(6.9314718055e-1f);
    u64 kONE = bcast2(1.0f);
    u64 kNB  = bcast2(-bmax);
    #pragma unroll
    for (int k = 0; k < 16; k++){
        int e = tid + k*TPB;
        int i = e >> 5, j = (e & 31) * 4;
        float4 v = *(const float4*)&M[i*STR + j];
        float4 r;
        if ((k & 1) == 0 && k < 14){
            u64 xb0 = add2(pack2(v.x, v.y), kNB);
            u64 xb1 = add2(pack2(v.z, v.w), kNB);
            u64 r0 = exp_pair(xb0, kL2E, kMAG, kNMAG, kN1, kC5, kC4, kC3, kC2, kC1, kONE);
            u64 r1 = exp_pair(xb1, kL2E, kMAG, kNMAG, kN1, kC5, kC4, kC3, kC2, kC1, kONE);
            unpack2(r0, r.x, r.y); unpack2(r1, r.z, r.w);
        } else {
            r.x = __expf(v.x - bmax); r.y = __expf(v.y - bmax);
            r.z = __expf(v.z - bmax); r.w = __expf(v.w - bmax);
        }
        *(float4*)&M[i*STR + j] = r;
    }
    __syncthreads();
    if (tid < D_B){
        const float* r = M + tid*STR;
        float s = 0.f;
        #pragma unroll
        for (int j4 = 0; j4 < D_B/4; j4++){
            float4 v = *(const float4*)&r[j4*4];
            s += (v.x + v.y) + (v.z + v.w);
        }
        s_dia[tid] = s;
    }
    __syncthreads();
    if (tid < 32){
        float t = s_dia[tid] + s_dia[tid+32] + s_dia[tid+64] + s_dia[tid+96];
        #pragma unroll
        for (int o = 16; o; o >>= 1) t += __shfl_xor_sync(0xffffffffu, t, o);
        if (tid == 0) s_red[9] = t;
    }
    __syncthreads();
    if (tid < D_B){
        float total = s_red[9];
        float d = fmaxf(fmaxf(s_dia[tid], total / 100000.0f), 1e-5f);
        s_rinv[tid] = rsqrtf(d);
    }
    __syncthreads();
}

// ============================================================================
// Kernel 2: persistent, cp.async-pipelined per-(n,k) chain.
//   A_pre = K^T Q K; e = exp(A_pre - max); sr from row sums;
//   out = inp + lam * S (e (S X S) e^T) S
// Buffer rotation per iter:  b1:XQ->e   b0:XK->P   b2:St->X''->e^T
// ============================================================================
__global__ __launch_bounds__(TPB, 1) void k_attn(const float* __restrict__ inp,
                                                 const float* __restrict__ lam,
                                                 float* __restrict__ out){
    extern __shared__ float sm[];
    float* b0 = sm;
    float* b1 = sm +     D_B*STR;
    float* b2 = sm + 2 * D_B*STR;
    __shared__ float s_dia[D_B], s_rinvd[D_B], s_rv[D_B], s_red[16];
    int tid = threadIdx.x;
    int stride = gridDim.x;
    int nk = blockIdx.x;
    if (nk >= NK_TOT) return;

    tile_async(b1, g_XQ + (size_t)nk*MAT, tid);  // prefetch first XQ
    cp_commit();

    for (; nk < NK_TOT; nk += stride){
        size_t base = (size_t)nk * MAT;
        tile_async(b0, g_XK + base, tid);
        cp_commit();
        if (tid < D_B) s_rv[tid] = g_rv[nk*D_B + tid];
        cp_wait0();
        __syncthreads();

        mm_atb(b2, b1, b0, tid);               // St = Q^T K
        __syncthreads();
        mm_atb_mx(b1, b2, b0, tid, s_red);     // A_pre = St^T K (b1), warp maxes
        __syncthreads();
        if (tid == 0){
            float m2 = s_red[0];
            #pragma unroll
            for (int w = 1; w < TPB/32; w++) m2 = fmaxf(m2, s_red[w]);
            s_red[8] = m2;
        }
        tile_async(b2, inp + base, tid);       // raw X tile, lands during soft_pd2
        cp_commit();
        __syncthreads();                       // bmax visible

        soft_pd2(b1, tid, s_dia, s_rinvd, s_red);  // b1 = e, s_rinvd ready
        cp_wait0();                            // X arrived

        // X'' = sr_i * sr_j * clip(inp * rv_i * rv_j), in place on b2
        #pragma unroll
        for (int e = tid; e < MAT/4; e += TPB){
            int i = e >> 5, j = (e & 31) * 4;
            float4 v = *(float4*)&b2[i*STR + j];
            float ai = s_rv[i], bi = s_rinvd[i];
            v.x = clip1(v.x * ai * s_rv[j+0]) * bi * s_rinvd[j+0];
            v.y = clip1(v.y * ai * s_rv[j+1]) * bi * s_rinvd[j+1];
            v.z = clip1(v.z * ai * s_rv[j+2]) * bi * s_rinvd[j+2];
            v.w = clip1(v.w * ai * s_rv[j+3]) * bi * s_rinvd[j+3];
            *(float4*)&b2[i*STR + j] = v;
        }
        __syncthreads();

        mm_ab(b0, b1, b2, tid);                // P = e * X''  (b0)
        __syncthreads();
        for (int e = tid; e < MAT; e += TPB){  // b2 = e^T
            int i = e >> 7, j = e & 127;
            b2[j*STR + i] = b1[i*STR + j];
        }
        __syncthreads();
        int nk2 = nk + stride;
        if (nk2 < NK_TOT){                     // prefetch next XQ during epilogue
            tile_async(b1, g_XQ + (size_t)nk2*MAT, tid);
            cp_commit();
        }
        mm_ab_out(b0, b2, inp + base, out + base,
                  lam[nk & (C_B - 1)], s_rinvd, tid);
        __syncthreads();
    }
}

// ============================================================================
extern "C" void kernel_launch(void* const* d_in, const int* in_sizes, int n_in,
                              void* d_out, int out_size){
    const float* inp = (const float*)d_in[0];
    const float* wq  = (const float*)d_in[1];
    const float* wk  = (const float*)d_in[2];
    const float* lam = (const float*)d_in[3];
    float* out = (float*)d_out;

    int nsm = 148;
    cudaDeviceGetAttribute(&nsm, cudaDevAttrMultiProcessorCount, 0);
    if (nsm <= 0 || nsm > NK_TOT) nsm = 148;

    cudaFuncSetAttribute(k_attn, cudaFuncAttributeMaxDynamicSharedMemorySize, SMEM3);

    k_rinv<<<N_B*C_B, D_B>>>(inp);
    k_mix<<<dim3(D_B, N_B), 256>>>(inp, wq, wk);
    k_attn<<<nsm, TPB, SMEM3>>>(inp, lam, out);
}

// round 9
// speedup vs baseline: 1.6609x; 1.5937x over previous
#include <cuda_runtime.h>
#include <cuda_bf16.h>

#define N_B 32
#define C_B 64
#define D_B 128
#define MAT 16384
#define NK_TOT 2048
#define TPB 256

// bf16 tile geometry for k_attn
#define SSTR 136                 // halves per row (272B, conflict-free for ldmatrix)
#define TILEB 34816              // one 128x136 bf16 tile
#define SBYTES 69632             // hi+lo pair
#define DSM (3*SBYTES)           // 208896 B dynamic smem

typedef unsigned long long u64;
typedef unsigned int u32;
typedef unsigned short u16;

__device__ float g_rv[NK_TOT*D_B];
__device__ float g_XQ[NK_TOT*MAT];
__device__ float g_XK[NK_TOT*MAT];

// ---------- f32x2 helpers ----------
__device__ __forceinline__ u64 bcast2(float x){
    u64 r; asm("mov.b64 %0, {%1, %1};" : "=l"(r) : "r"(__float_as_uint(x))); return r;
}
__device__ __forceinline__ u64 pack2(float a, float b){
    u64 r; asm("mov.b64 %0, {%1, %2};" : "=l"(r) : "r"(__float_as_uint(a)), "r"(__float_as_uint(b))); return r;
}
__device__ __forceinline__ u64 ffma2(u64 a, u64 b, u64 c){
    u64 d; asm("fma.rn.f32x2 %0, %1, %2, %3;" : "=l"(d) : "l"(a), "l"(b), "l"(c)); return d;
}
__device__ __forceinline__ u64 add2(u64 a, u64 b){
    u64 d; asm("add.rn.f32x2 %0, %1, %2;" : "=l"(d) : "l"(a), "l"(b)); return d;
}
__device__ __forceinline__ u64 mul2(u64 a, u64 b){
    u64 d; asm("mul.rn.f32x2 %0, %1, %2;" : "=l"(d) : "l"(a), "l"(b)); return d;
}
__device__ __forceinline__ void unpack2(u64 v, float& lo, float& hi){
    u32 a, b; asm("mov.b64 {%0, %1}, %2;" : "=r"(a), "=r"(b) : "l"(v));
    lo = __uint_as_float(a); hi = __uint_as_float(b);
}
__device__ __forceinline__ void unpack2u(u64 v, u32& a, u32& b){
    asm("mov.b64 {%0, %1}, %2;" : "=r"(a), "=r"(b) : "l"(v));
}
union F4U { float4 f; u64 u[2]; };
__device__ __forceinline__ float clip1(float x){ return fminf(1.f, fmaxf(-1.f, x)); }

// fma-pipe exp (magic rounding + deg-5 Taylor), underflow-clamped
__device__ __forceinline__ u64 exp_pair(u64 xb, u64 kL2E, u64 kMAG, u64 kNMAG, u64 kN1,
                                        u64 kC5, u64 kC4, u64 kC3, u64 kC2, u64 kC1, u64 kONE){
    u64 y = mul2(xb, kL2E);
    u64 z = add2(y, kMAG);
    u64 t = add2(z, kNMAG);
    u64 f = ffma2(t, kN1, y);
    u64 p = ffma2(kC5, f, kC4);
    p = ffma2(p, f, kC3); p = ffma2(p, f, kC2); p = ffma2(p, f, kC1); p = ffma2(p, f, kONE);
    u32 zl, zh; unpack2u(z, zl, zh);
    int n0 = max((int)(zl - 0x4B400000u), -127), n1 = max((int)(zh - 0x4B400000u), -127);
    u64 s; asm("mov.b64 %0, {%1, %2};" : "=l"(s)
               : "r"((u32)(n0 + 127) << 23), "r"((u32)(n1 + 127) << 23));
    return mul2(p, s);
}

// ---------- async / mma primitives (arch-generic, sm_80+) ----------
__device__ __forceinline__ void cp16(u32 s, const void* g){
    asm volatile("cp.async.cg.shared.global [%0], [%1], 16;" :: "r"(s), "l"(g));
}
__device__ __forceinline__ void cp_commit(){ asm volatile("cp.async.commit_group;"); }
__device__ __forceinline__ void cp_wait0(){ asm volatile("cp.async.wait_group 0;"); }
__device__ __forceinline__ u32 smem_u32(const void* p){
    u32 a; asm("{ .reg .u64 t; cvta.to.shared.u64 t, %1; cvt.u32.u64 %0, t; }" : "=r"(a) : "l"(p));
    return a;
}
__device__ __forceinline__ void ldsm4(u32 a, u32* r){
    asm volatile("ldmatrix.sync.aligned.m8n8.x4.shared.b16 {%0,%1,%2,%3}, [%4];"
        : "=r"(r[0]), "=r"(r[1]), "=r"(r[2]), "=r"(r[3]) : "r"(a));
}
__device__ __forceinline__ void ldsm4t(u32 a, u32* r){
    asm volatile("ldmatrix.sync.aligned.m8n8.x4.trans.shared.b16 {%0,%1,%2,%3}, [%4];"
        : "=r"(r[0]), "=r"(r[1]), "=r"(r[2]), "=r"(r[3]) : "r"(a));
}
__device__ __forceinline__ void ldsm2(u32 a, u32* r){
    asm volatile("ldmatrix.sync.aligned.m8n8.x2.shared.b16 {%0,%1}, [%2];"
        : "=r"(r[0]), "=r"(r[1]) : "r"(a));
}
__device__ __forceinline__ void ldsm2t(u32 a, u32* r){
    asm volatile("ldmatrix.sync.aligned.m8n8.x2.trans.shared.b16 {%0,%1}, [%2];"
        : "=r"(r[0]), "=r"(r[1]) : "r"(a));
}
__device__ __forceinline__ void mmab(float* d, const u32* a, const u32* b){
    asm volatile("mma.sync.aligned.m16n8k16.row.col.f32.bf16.bf16.f32 "
        "{%0,%1,%2,%3},{%4,%5,%6,%7},{%8,%9},{%0,%1,%2,%3};"
        : "+f"(d[0]), "+f"(d[1]), "+f"(d[2]), "+f"(d[3])
        : "r"(a[0]), "r"(a[1]), "r"(a[2]), "r"(a[3]), "r"(b[0]), "r"(b[1]));
}
// pack two floats to bf16x2 (lo in low half)
__device__ __forceinline__ u32 cvt2bf(float lo, float hi){
    u32 r; asm("cvt.rn.bf16x2.f32 %0, %1, %2;" : "=r"(r) : "f"(hi), "f"(lo)); return r;
}
// split-2: returns hi-pair; lo residual pair via out param
__device__ __forceinline__ u32 split2(float v0, float v1, u32& lopair){
    u32 hp = cvt2bf(v0, v1);
    float h0 = __uint_as_float(hp << 16);
    float h1 = __uint_as_float(hp & 0xffff0000u);
    lopair = cvt2bf(v0 - h0, v1 - h1);
    return hp;
}

// warp-tile split-2 matmul: acc[4][4][4] (+zeroed) = (Ah+Al)(Bh+Bl) minus Al*Bl.
// am/bm: 0 = plain row-major fragment, 1 = transposed (ldmatrix.trans).
__device__ __forceinline__ void wmm(u32 aB, u32 bB, int am, int bm,
                                    int wm, int wn, int l, float acc[4][4][4]){
    #pragma unroll
    for (int mt = 0; mt < 4; mt++)
        #pragma unroll
        for (int nt = 0; nt < 4; nt++)
            #pragma unroll
            for (int q = 0; q < 4; q++) acc[mt][nt][q] = 0.f;
    #pragma unroll
    for (int ks = 0; ks < 8; ks++){
        int k0 = ks*16;
        u32 Ah[4][4], Al[4][4], Bh[4][2], Bl[4][2];
        #pragma unroll
        for (int mt = 0; mt < 4; mt++){
            int i0 = wm*64 + mt*16;
            u32 ad;
            if (am == 0) ad = aB + (u32)(((i0 + (l&7) + ((l>>3)&1)*8)*SSTR + k0 + (l>>4)*8)*2);
            else         ad = aB + (u32)(((k0 + (l>>4)*8 + (l&7))*SSTR + i0 + ((l>>3)&1)*8)*2);
            if (am == 0){ ldsm4(ad, Ah[mt]);  ldsm4(ad + TILEB, Al[mt]); }
            else        { ldsm4t(ad, Ah[mt]); ldsm4t(ad + TILEB, Al[mt]); }
        }
        #pragma unroll
        for (int nt = 0; nt < 4; nt++){
            int j0 = wn*32 + nt*8;
            u32 bd;
            if (bm == 0) bd = bB + (u32)(((j0 + (l&7))*SSTR + k0 + ((l>>3)&1)*8)*2);
            else         bd = bB + (u32)(((k0 + (l&15))*SSTR + j0)*2);
            if (bm == 0){ ldsm2(bd, Bh[nt]);  ldsm2(bd + TILEB, Bl[nt]); }
            else        { ldsm2t(bd, Bh[nt]); ldsm2t(bd + TILEB, Bl[nt]); }
        }
        #pragma unroll
        for (int mt = 0; mt < 4; mt++)
            #pragma unroll
            for (int nt = 0; nt < 4; nt++){
                mmab(acc[mt][nt], Ah[mt], Bh[nt]);
                mmab(acc[mt][nt], Ah[mt], Bl[nt]);
                mmab(acc[mt][nt], Al[mt], Bh[nt]);
            }
    }
}

// store warp acc -> bf16 hi/lo tile at dstOff, optional per-column scale
__device__ __forceinline__ void store_acc(char* smc, u32 dstOff, int wm, int wn, int l,
                                          float acc[4][4][4], const float* colscale){
    int r0 = l >> 2, c0 = (l & 3)*2;
    #pragma unroll
    for (int mt = 0; mt < 4; mt++)
        #pragma unroll
        for (int nt = 0; nt < 4; nt++){
            int row = wm*64 + mt*16 + r0, col = wn*32 + nt*8 + c0;
            float s0 = 1.f, s1 = 1.f;
            if (colscale){ s0 = colscale[col]; s1 = colscale[col+1]; }
            #pragma unroll
            for (int h = 0; h < 2; h++){
                float v0 = acc[mt][nt][h*2] * s0, v1 = acc[mt][nt][h*2+1] * s1;
                u32 lp, hp = split2(v0, v1, lp);
                u32 off = dstOff + (u32)((((row + h*8)*SSTR) + col)*2);
                *(u32*)(smc + off) = hp;
                *(u32*)(smc + off + TILEB) = lp;
            }
        }
}

// ============================================================================
__global__ void k_rinv(const float* __restrict__ in){
    int nk = blockIdx.x, t = threadIdx.x;
    float v = in[(size_t)nk*MAT + t*D_B + t];
    g_rv[nk*D_B + t] = rsqrtf(fmaxf(fabsf(v), 1e-4f));
}

// fused cov2cor + channel mixing (validated, unchanged; fp32 outputs)
__global__ __launch_bounds__(256, 1) void k_mix(const float* __restrict__ inp,
                                                const float* __restrict__ wq,
                                                const float* __restrict__ wk){
    __shared__ float sWQ[C_B*C_B], sWK[C_B*C_B], sX[8*D_B], sRV[8*D_B];
    int tid = threadIdx.x, n = blockIdx.y, irow = blockIdx.x;
    for (int i = tid; i < C_B*C_B; i += 256){ sWQ[i] = wq[i]; sWK[i] = wk[i]; }
    int tx = tid & 31, ty = tid >> 5, k0 = ty*8;
    u64 aQ[4][4], aK[4][4];
    #pragma unroll
    for (int p = 0; p < 4; p++)
        #pragma unroll
        for (int q = 0; q < 4; q++){ aQ[p][q] = 0ull; aK[p][q] = 0ull; }
    __syncthreads();
    for (int cc = 0; cc < C_B; cc += 8){
        {
            int idx = tid*4, cl = idx >> 7, j = idx & 127;
            *(float4*)&sRV[idx] = *(const float4*)&g_rv[((size_t)(n*C_B + cc + cl))*D_B + j];
        }
        __syncthreads();
        {
            int cl = tid >> 5, jj = (tid & 31)*4;
            float4 v = *(const float4*)&inp[((size_t)(n*C_B + cc + cl))*MAT + irow*D_B + jj];
            float ri = sRV[cl*D_B + irow];
            v.x = clip1(v.x*ri*sRV[cl*D_B + jj+0]); v.y = clip1(v.y*ri*sRV[cl*D_B + jj+1]);
            v.z = clip1(v.z*ri*sRV[cl*D_B + jj+2]); v.w = clip1(v.w*ri*sRV[cl*D_B + jj+3]);
            *(float4*)&sX[cl*D_B + jj] = v;
        }
        __syncthreads();
        #pragma unroll
        for (int cl = 0; cl < 8; cl++){
            int c = cc + cl;
            float4 xv = *(const float4*)&sX[cl*D_B + tx*4];
            u64 xx[4] = { bcast2(xv.x), bcast2(xv.y), bcast2(xv.z), bcast2(xv.w) };
            F4U q0, q1, kk0, kk1;
            q0.f = *(const float4*)&sWQ[c*C_B + k0];  q1.f = *(const float4*)&sWQ[c*C_B + k0 + 4];
            kk0.f = *(const float4*)&sWK[c*C_B + k0]; kk1.f = *(const float4*)&sWK[c*C_B + k0 + 4];
            u64 bq[4] = { q0.u[0], q0.u[1], q1.u[0], q1.u[1] };
            u64 bk[4] = { kk0.u[0], kk0.u[1], kk1.u[0], kk1.u[1] };
            #pragma unroll
            for (int p = 0; p < 4; p++)
                #pragma unroll
                for (int q = 0; q < 4; q++){
                    aQ[p][q] = ffma2(xx[p], bq[q], aQ[p][q]);
                    aK[p][q] = ffma2(xx[p], bk[q], aK[p][q]);
                }
        }
        __syncthreads();
    }
    #pragma unroll
    for (int q = 0; q < 4; q++)
        #pragma unroll
        for (int h = 0; h < 2; h++){
            int k = k0 + q*2 + h;
            float vq[4], vk[4];
            #pragma unroll
            for (int p = 0; p < 4; p++){
                float lo, hi;
                unpack2(aQ[p][q], lo, hi); vq[p] = h ? hi : lo;
                unpack2(aK[p][q], lo, hi); vk[p] = h ? hi : lo;
            }
            size_t base = ((size_t)(n*C_B + k))*MAT + irow*D_B + tx*4;
            *(float4*)&g_XQ[base] = make_float4(vq[0], vq[1], vq[2], vq[3]);
            *(float4*)&g_XK[base] = make_float4(vk[0], vk[1], vk[2], vk[3]);
        }
}

// ============================================================================
// k_attn: HMMA (mma.sync bf16 split-2) chain, one CTA per (n,k).
//   St = Q^T K; Apre = St^T K; e = exp(Apre - max); sr from rowsums;
//   e~ = e*diag(sr); X''' = clip(cov2cor(inp)); P = e~ X'''; O = P e~^T;
//   out = inp + lam*sr_i*sr_j*O
// Buffers: B0: Q -> inp(fp32 flat) -> P | B1: K -> X''' | B2: St -> e~
// ============================================================================
__global__ __launch_bounds__(TPB, 1) void k_attn(const float* __restrict__ inp,
                                                 const float* __restrict__ lam,
                                                 float* __restrict__ out){
    extern __shared__ char smc[];
    float* B0f = (float*)smc;
    u32 sb = smem_u32(smc);
    u32 B0 = sb, B1 = sb + SBYTES, B2 = sb + 2*SBYTES;
    __shared__ float s_rv[D_B], s_sr[D_B], s_dia[D_B], s_part[D_B][4], s_red[12];
    int tid = threadIdx.x, w = tid >> 5, l = tid & 31;
    int wm = w >> 2, wn = w & 3;
    int r0 = l >> 2, c0 = (l & 3)*2;
    int nk = blockIdx.x;
    size_t gb = (size_t)nk * MAT;

    if (tid < D_B) s_rv[tid] = g_rv[nk*D_B + tid];
    // convert Q -> B0, K -> B1 (bf16 hi/lo)
    for (int g = tid; g < 2048; g += TPB){
        int m = g >> 4, c = (g & 15)*8;
        u32 off = (u32)((m*SSTR + c)*2);
        #pragma unroll
        for (int s = 0; s < 2; s++){
            const float* src = s ? (g_XK + gb) : (g_XQ + gb);
            u32 dst = s ? B1 : B0;
            float4 v0 = *(const float4*)&src[m*128 + c];
            float4 v1 = *(const float4*)&src[m*128 + c + 4];
            u32 l0, l1, l2, l3;
            u32 h0 = split2(v0.x, v0.y, l0), h1 = split2(v0.z, v0.w, l1);
            u32 h2 = split2(v1.x, v1.y, l2), h3 = split2(v1.z, v1.w, l3);
            *(uint4*)(smc + (dst - sb) + off) = make_uint4(h0, h1, h2, h3);
            *(uint4*)(smc + (dst - sb) + off + TILEB) = make_uint4(l0, l1, l2, l3);
        }
    }
    __syncthreads();

    float acc[4][4][4];
    wmm(B0, B1, 1, 1, wm, wn, l, acc);              // St = Q^T K
    store_acc(smc, B2 - sb, wm, wn, l, acc, 0);
    __syncthreads();

    // prefetch raw inp tile (fp32 flat) into B0 while mm2 runs
    for (int e = tid; e < 4096; e += TPB) cp16(B0 + e*16, inp + gb + e*4);
    cp_commit();

    wmm(B2, B1, 1, 1, wm, wn, l, acc);              // Apre = St^T K
    cp_wait0();
    // block max
    float mx = -3.4e38f;
    #pragma unroll
    for (int mt = 0; mt < 4; mt++)
        #pragma unroll
        for (int nt = 0; nt < 4; nt++)
            #pragma unroll
            for (int q = 0; q < 4; q++) mx = fmaxf(mx, acc[mt][nt][q]);
    #pragma unroll
    for (int o = 16; o; o >>= 1) mx = fmaxf(mx, __shfl_xor_sync(0xffffffffu, mx, o));
    if (l == 0) s_red[w] = mx;
    __syncthreads();
    if (tid == 0){
        float m2 = s_red[0];
        #pragma unroll
        for (int q = 1; q < 8; q++) m2 = fmaxf(m2, s_red[q]);
        s_red[8] = m2;
    }
    __syncthreads();
    float bmax = s_red[8];
    {   // exp (all-poly, fma pipe) in place + row partial sums
        const u64 kL2E = bcast2(1.4426950408889634f), kMAG = bcast2(12582912.0f),
                  kNMAG = bcast2(-12582912.0f), kN1 = bcast2(-1.0f),
                  kC5 = bcast2(1.3333558146e-3f), kC4 = bcast2(9.6181291076e-3f),
                  kC3 = bcast2(5.5504108664e-2f), kC2 = bcast2(2.4022650695e-1f),
                  kC1 = bcast2(6.9314718055e-1f), kONE = bcast2(1.0f),
                  kNB = bcast2(-bmax);
        float part[4][2] = {};
        #pragma unroll
        for (int mt = 0; mt < 4; mt++)
            #pragma unroll
            for (int nt = 0; nt < 4; nt++){
                u64 p0 = exp_pair(add2(pack2(acc[mt][nt][0], acc[mt][nt][1]), kNB),
                                  kL2E,kMAG,kNMAG,kN1,kC5,kC4,kC3,kC2,kC1,kONE);
                u64 p1 = exp_pair(add2(pack2(acc[mt][nt][2], acc[mt][nt][3]), kNB),
                                  kL2E,kMAG,kNMAG,kN1,kC5,kC4,kC3,kC2,kC1,kONE);
                unpack2(p0, acc[mt][nt][0], acc[mt][nt][1]);
                unpack2(p1, acc[mt][nt][2], acc[mt][nt][3]);
                part[mt][0] += acc[mt][nt][0] + acc[mt][nt][1];
                part[mt][1] += acc[mt][nt][2] + acc[mt][nt][3];
            }
        #pragma unroll
        for (int mt = 0; mt < 4; mt++)
            #pragma unroll
            for (int h = 0; h < 2; h++){
                float t = part[mt][h];
                t += __shfl_xor_sync(0xffffffffu, t, 1);
                t += __shfl_xor_sync(0xffffffffu, t, 2);
                if ((l & 3) == 0) s_part[wm*64 + mt*16 + h*8 + r0][wn] = t;
            }
    }
    __syncthreads();                                 // mm2 done; partials visible
    // X''' = clip(inp*rv_i*rv_j) from B0 flat -> B1 (bf16 hi/lo)
    for (int e = tid; e < 4096; e += TPB){
        int i = e >> 5, j = (e & 31)*4;
        float4 v = *(float4*)(B0f + e*4);
        float ri = s_rv[i];
        v.x = clip1(v.x*ri*s_rv[j+0]); v.y = clip1(v.y*ri*s_rv[j+1]);
        v.z = clip1(v.z*ri*s_rv[j+2]); v.w = clip1(v.w*ri*s_rv[j+3]);
        u32 lp0, lp1;
        u32 hp0 = split2(v.x, v.y, lp0), hp1 = split2(v.z, v.w, lp1);
        u32 off = (u32)((i*SSTR + j)*2);
        *(u32*)(smc + SBYTES + off) = hp0;  *(u32*)(smc + SBYTES + off + 4) = hp1;
        *(u32*)(smc + SBYTES + off + TILEB) = lp0;  *(u32*)(smc + SBYTES + off + TILEB + 4) = lp1;
    }
    if (tid < D_B)
        s_dia[tid] = s_part[tid][0] + s_part[tid][1] + s_part[tid][2] + s_part[tid][3];
    __syncthreads();
    if (tid < 32){
        float t = s_dia[tid] + s_dia[tid+32] + s_dia[tid+64] + s_dia[tid+96];
        #pragma unroll
        for (int o = 16; o; o >>= 1) t += __shfl_xor_sync(0xffffffffu, t, o);
        if (tid == 0) s_red[9] = t;
    }
    __syncthreads();
    if (tid < D_B){
        float d = fmaxf(fmaxf(s_dia[tid], s_red[9]/100000.0f), 1e-5f);
        s_sr[tid] = rsqrtf(d);
    }
    __syncthreads();
    store_acc(smc, B2 - sb, wm, wn, l, acc, s_sr);   // e~ = e * sr_col
    __syncthreads();

    wmm(B2, B1, 0, 1, wm, wn, l, acc);               // P = e~ X'''
    store_acc(smc, 0, wm, wn, l, acc, 0);            // P -> B0
    __syncthreads();

    wmm(B0, B2, 0, 0, wm, wn, l, acc);               // O = P e~^T
    {   // epilogue: out = inp + lam*sr_i*sr_j*O
        float lamv = lam[nk & (C_B - 1)];
        #pragma unroll
        for (int mt = 0; mt < 4; mt++)
            #pragma unroll
            for (int nt = 0; nt < 4; nt++){
                int row = wm*64 + mt*16 + r0, col = wn*32 + nt*8 + c0;
                float sc0 = s_sr[col], sc1 = s_sr[col+1];
                #pragma unroll
                for (int h = 0; h < 2; h++){
                    int rr = row + h*8;
                    float li = lamv * s_sr[rr];
                    float2 iv = *(const float2*)&inp[gb + rr*128 + col];
                    float2 o;
                    o.x = iv.x + li*sc0*acc[mt][nt][h*2+0];
                    o.y = iv.y + li*sc1*acc[mt][nt][h*2+1];
                    *(float2*)&out[gb + rr*128 + col] = o;
                }
            }
    }
}

// ============================================================================
extern "C" void kernel_launch(void* const* d_in, const int* in_sizes, int n_in,
                              void* d_out, int out_size){
    const float* inp = (const float*)d_in[0];
    const float* wq  = (const float*)d_in[1];
    const float* wk  = (const float*)d_in[2];
    const float* lam = (const float*)d_in[3];
    float* out = (float*)d_out;

    cudaFuncSetAttribute(k_attn, cudaFuncAttributeMaxDynamicSharedMemorySize, DSM);

    k_rinv<<<NK_TOT, D_B>>>(inp);
    k_mix<<<dim3(D_B, N_B), 256>>>(inp, wq, wk);
    k_attn<<<NK_TOT, TPB, DSM>>>(inp, lam, out);
}

// round 10
// speedup vs baseline: 1.7493x; 1.0532x over previous
#include <cuda_runtime.h>
#include <cuda_bf16.h>

#define N_B 32
#define C_B 64
#define D_B 128
#define MAT 16384
#define NK_TOT 2048
#define TPB 256

// bf16 tile geometry for k_attn
#define SSTR 136                 // halves per row (272B, conflict-free for ldmatrix)
#define TILEB 34816              // one 128x136 bf16 tile
#define SBYTES 69632             // hi+lo pair
#define DSM (3*SBYTES)           // 208896 B dynamic smem

typedef unsigned long long u64;
typedef unsigned int u32;
typedef unsigned short u16;

__device__ float g_rv[NK_TOT*D_B];
// Q/K pre-split to bf16 hi/lo by k_mix (same total bytes as fp32)
__device__ u16 g_Qh[NK_TOT*MAT], g_Ql[NK_TOT*MAT];
__device__ u16 g_Kh[NK_TOT*MAT], g_Kl[NK_TOT*MAT];

// ---------- f32x2 helpers ----------
__device__ __forceinline__ u64 bcast2(float x){
    u64 r; asm("mov.b64 %0, {%1, %1};" : "=l"(r) : "r"(__float_as_uint(x))); return r;
}
__device__ __forceinline__ u64 pack2(float a, float b){
    u64 r; asm("mov.b64 %0, {%1, %2};" : "=l"(r) : "r"(__float_as_uint(a)), "r"(__float_as_uint(b))); return r;
}
__device__ __forceinline__ u64 ffma2(u64 a, u64 b, u64 c){
    u64 d; asm("fma.rn.f32x2 %0, %1, %2, %3;" : "=l"(d) : "l"(a), "l"(b), "l"(c)); return d;
}
__device__ __forceinline__ u64 add2(u64 a, u64 b){
    u64 d; asm("add.rn.f32x2 %0, %1, %2;" : "=l"(d) : "l"(a), "l"(b)); return d;
}
__device__ __forceinline__ u64 mul2(u64 a, u64 b){
    u64 d; asm("mul.rn.f32x2 %0, %1, %2;" : "=l"(d) : "l"(a), "l"(b)); return d;
}
__device__ __forceinline__ void unpack2(u64 v, float& lo, float& hi){
    u32 a, b; asm("mov.b64 {%0, %1}, %2;" : "=r"(a), "=r"(b) : "l"(v));
    lo = __uint_as_float(a); hi = __uint_as_float(b);
}
__device__ __forceinline__ void unpack2u(u64 v, u32& a, u32& b){
    asm("mov.b64 {%0, %1}, %2;" : "=r"(a), "=r"(b) : "l"(v));
}
union F4U { float4 f; u64 u[2]; };
__device__ __forceinline__ float clip1(float x){ return fminf(1.f, fmaxf(-1.f, x)); }

// fma-pipe exp (magic rounding + deg-5 Taylor), underflow-clamped
__device__ __forceinline__ u64 exp_pair(u64 xb, u64 kL2E, u64 kMAG, u64 kNMAG, u64 kN1,
                                        u64 kC5, u64 kC4, u64 kC3, u64 kC2, u64 kC1, u64 kONE){
    u64 y = mul2(xb, kL2E);
    u64 z = add2(y, kMAG);
    u64 t = add2(z, kNMAG);
    u64 f = ffma2(t, kN1, y);
    u64 p = ffma2(kC5, f, kC4);
    p = ffma2(p, f, kC3); p = ffma2(p, f, kC2); p = ffma2(p, f, kC1); p = ffma2(p, f, kONE);
    u32 zl, zh; unpack2u(z, zl, zh);
    int n0 = max((int)(zl - 0x4B400000u), -127), n1 = max((int)(zh - 0x4B400000u), -127);
    u64 s; asm("mov.b64 %0, {%1, %2};" : "=l"(s)
               : "r"((u32)(n0 + 127) << 23), "r"((u32)(n1 + 127) << 23));
    return mul2(p, s);
}

// ---------- async / mma primitives (arch-generic, sm_80+) ----------
__device__ __forceinline__ void cp16(u32 s, const void* g){
    asm volatile("cp.async.cg.shared.global [%0], [%1], 16;" :: "r"(s), "l"(g));
}
__device__ __forceinline__ void cp_commit(){ asm volatile("cp.async.commit_group;"); }
__device__ __forceinline__ void cp_wait0(){ asm volatile("cp.async.wait_group 0;"); }
__device__ __forceinline__ u32 smem_u32(const void* p){
    u32 a; asm("{ .reg .u64 t; cvta.to.shared.u64 t, %1; cvt.u32.u64 %0, t; }" : "=r"(a) : "l"(p));
    return a;
}
__device__ __forceinline__ void ldsm4(u32 a, u32* r){
    asm volatile("ldmatrix.sync.aligned.m8n8.x4.shared.b16 {%0,%1,%2,%3}, [%4];"
        : "=r"(r[0]), "=r"(r[1]), "=r"(r[2]), "=r"(r[3]) : "r"(a));
}
__device__ __forceinline__ void ldsm4t(u32 a, u32* r){
    asm volatile("ldmatrix.sync.aligned.m8n8.x4.trans.shared.b16 {%0,%1,%2,%3}, [%4];"
        : "=r"(r[0]), "=r"(r[1]), "=r"(r[2]), "=r"(r[3]) : "r"(a));
}
__device__ __forceinline__ void ldsm2(u32 a, u32* r){
    asm volatile("ldmatrix.sync.aligned.m8n8.x2.shared.b16 {%0,%1}, [%2];"
        : "=r"(r[0]), "=r"(r[1]) : "r"(a));
}
__device__ __forceinline__ void ldsm2t(u32 a, u32* r){
    asm volatile("ldmatrix.sync.aligned.m8n8.x2.trans.shared.b16 {%0,%1}, [%2];"
        : "=r"(r[0]), "=r"(r[1]) : "r"(a));
}
__device__ __forceinline__ void mmab(float* d, const u32* a, const u32* b){
    asm volatile("mma.sync.aligned.m16n8k16.row.col.f32.bf16.bf16.f32 "
        "{%0,%1,%2,%3},{%4,%5,%6,%7},{%8,%9},{%0,%1,%2,%3};"
        : "+f"(d[0]), "+f"(d[1]), "+f"(d[2]), "+f"(d[3])
        : "r"(a[0]), "r"(a[1]), "r"(a[2]), "r"(a[3]), "r"(b[0]), "r"(b[1]));
}
// pack two floats to bf16x2 (lo value in low half)
__device__ __forceinline__ u32 cvt2bf(float lo, float hi){
    u32 r; asm("cvt.rn.bf16x2.f32 %0, %1, %2;" : "=r"(r) : "f"(hi), "f"(lo)); return r;
}
// split-2: returns hi-pair; lo residual pair via out param
__device__ __forceinline__ u32 split2(float v0, float v1, u32& lopair){
    u32 hp = cvt2bf(v0, v1);
    float h0 = __uint_as_float(hp << 16);
    float h1 = __uint_as_float(hp & 0xffff0000u);
    lopair = cvt2bf(v0 - h0, v1 - h1);
    return hp;
}

// warp-tile split-2 matmul: acc[4][4][4] (+zeroed) = (Ah+Al)(Bh+Bl) minus Al*Bl.
// am/bm: 0 = plain row-major fragment, 1 = transposed (ldmatrix.trans).
__device__ __forceinline__ void wmm(u32 aB, u32 bB, int am, int bm,
                                    int wm, int wn, int l, float acc[4][4][4]){
    #pragma unroll
    for (int mt = 0; mt < 4; mt++)
        #pragma unroll
        for (int nt = 0; nt < 4; nt++)
            #pragma unroll
            for (int q = 0; q < 4; q++) acc[mt][nt][q] = 0.f;
    #pragma unroll
    for (int ks = 0; ks < 8; ks++){
        int k0 = ks*16;
        u32 Ah[4][4], Al[4][4], Bh[4][2], Bl[4][2];
        #pragma unroll
        for (int mt = 0; mt < 4; mt++){
            int i0 = wm*64 + mt*16;
            u32 ad;
            if (am == 0) ad = aB + (u32)(((i0 + (l&7) + ((l>>3)&1)*8)*SSTR + k0 + (l>>4)*8)*2);
            else         ad = aB + (u32)(((k0 + (l>>4)*8 + (l&7))*SSTR + i0 + ((l>>3)&1)*8)*2);
            if (am == 0){ ldsm4(ad, Ah[mt]);  ldsm4(ad + TILEB, Al[mt]); }
            else        { ldsm4t(ad, Ah[mt]); ldsm4t(ad + TILEB, Al[mt]); }
        }
        #pragma unroll
        for (int nt = 0; nt < 4; nt++){
            int j0 = wn*32 + nt*8;
            u32 bd;
            if (bm == 0) bd = bB + (u32)(((j0 + (l&7))*SSTR + k0 + ((l>>3)&1)*8)*2);
            else         bd = bB + (u32)(((k0 + (l&15))*SSTR + j0)*2);
            if (bm == 0){ ldsm2(bd, Bh[nt]);  ldsm2(bd + TILEB, Bl[nt]); }
            else        { ldsm2t(bd, Bh[nt]); ldsm2t(bd + TILEB, Bl[nt]); }
        }
        #pragma unroll
        for (int mt = 0; mt < 4; mt++)
            #pragma unroll
            for (int nt = 0; nt < 4; nt++){
                mmab(acc[mt][nt], Ah[mt], Bh[nt]);
                mmab(acc[mt][nt], Ah[mt], Bl[nt]);
                mmab(acc[mt][nt], Al[mt], Bh[nt]);
            }
    }
}

// store warp acc -> bf16 hi/lo tile at dstOff, optional per-column scale
__device__ __forceinline__ void store_acc(char* smc, u32 dstOff, int wm, int wn, int l,
                                          float acc[4][4][4], const float* colscale){
    int r0 = l >> 2, c0 = (l & 3)*2;
    #pragma unroll
    for (int mt = 0; mt < 4; mt++)
        #pragma unroll
        for (int nt = 0; nt < 4; nt++){
            int row = wm*64 + mt*16 + r0, col = wn*32 + nt*8 + c0;
            float s0 = 1.f, s1 = 1.f;
            if (colscale){ s0 = colscale[col]; s1 = colscale[col+1]; }
            #pragma unroll
            for (int h = 0; h < 2; h++){
                float v0 = acc[mt][nt][h*2] * s0, v1 = acc[mt][nt][h*2+1] * s1;
                u32 lp, hp = split2(v0, v1, lp);
                u32 off = dstOff + (u32)((((row + h*8)*SSTR) + col)*2);
                *(u32*)(smc + off) = hp;
                *(u32*)(smc + off + TILEB) = lp;
            }
        }
}

// ============================================================================
__global__ void k_rinv(const float* __restrict__ in){
    int nk = blockIdx.x, t = threadIdx.x;
    float v = in[(size_t)nk*MAT + t*D_B + t];
    g_rv[nk*D_B + t] = rsqrtf(fmaxf(fabsf(v), 1e-4f));
}

// fused cov2cor + channel mixing; outputs bf16 hi/lo pairs (split-2 at source)
__global__ __launch_bounds__(256, 1) void k_mix(const float* __restrict__ inp,
                                                const float* __restrict__ wq,
                                                const float* __restrict__ wk){
    __shared__ float sWQ[C_B*C_B], sWK[C_B*C_B], sX[8*D_B], sRV[8*D_B];
    int tid = threadIdx.x, n = blockIdx.y, irow = blockIdx.x;
    for (int i = tid; i < C_B*C_B; i += 256){ sWQ[i] = wq[i]; sWK[i] = wk[i]; }
    int tx = tid & 31, ty = tid >> 5, k0 = ty*8;
    u64 aQ[4][4], aK[4][4];
    #pragma unroll
    for (int p = 0; p < 4; p++)
        #pragma unroll
        for (int q = 0; q < 4; q++){ aQ[p][q] = 0ull; aK[p][q] = 0ull; }
    __syncthreads();
    for (int cc = 0; cc < C_B; cc += 8){
        {
            int idx = tid*4, cl = idx >> 7, j = idx & 127;
            *(float4*)&sRV[idx] = *(const float4*)&g_rv[((size_t)(n*C_B + cc + cl))*D_B + j];
        }
        __syncthreads();
        {
            int cl = tid >> 5, jj = (tid & 31)*4;
            float4 v = *(const float4*)&inp[((size_t)(n*C_B + cc + cl))*MAT + irow*D_B + jj];
            float ri = sRV[cl*D_B + irow];
            v.x = clip1(v.x*ri*sRV[cl*D_B + jj+0]); v.y = clip1(v.y*ri*sRV[cl*D_B + jj+1]);
            v.z = clip1(v.z*ri*sRV[cl*D_B + jj+2]); v.w = clip1(v.w*ri*sRV[cl*D_B + jj+3]);
            *(float4*)&sX[cl*D_B + jj] = v;
        }
        __syncthreads();
        #pragma unroll
        for (int cl = 0; cl < 8; cl++){
            int c = cc + cl;
            float4 xv = *(const float4*)&sX[cl*D_B + tx*4];
            u64 xx[4] = { bcast2(xv.x), bcast2(xv.y), bcast2(xv.z), bcast2(xv.w) };
            F4U q0, q1, kk0, kk1;
            q0.f = *(const float4*)&sWQ[c*C_B + k0];  q1.f = *(const float4*)&sWQ[c*C_B + k0 + 4];
            kk0.f = *(const float4*)&sWK[c*C_B + k0]; kk1.f = *(const float4*)&sWK[c*C_B + k0 + 4];
            u64 bq[4] = { q0.u[0], q0.u[1], q1.u[0], q1.u[1] };
            u64 bk[4] = { kk0.u[0], kk0.u[1], kk1.u[0], kk1.u[1] };
            #pragma unroll
            for (int p = 0; p < 4; p++)
                #pragma unroll
                for (int q = 0; q < 4; q++){
                    aQ[p][q] = ffma2(xx[p], bq[q], aQ[p][q]);
                    aK[p][q] = ffma2(xx[p], bk[q], aK[p][q]);
                }
        }
        __syncthreads();
    }
    #pragma unroll
    for (int q = 0; q < 4; q++)
        #pragma unroll
        for (int h = 0; h < 2; h++){
            int k = k0 + q*2 + h;
            float vq[4], vk[4];
            #pragma unroll
            for (int p = 0; p < 4; p++){
                float lo, hi;
                unpack2(aQ[p][q], lo, hi); vq[p] = h ? hi : lo;
                unpack2(aK[p][q], lo, hi); vk[p] = h ? hi : lo;
            }
            size_t base = ((size_t)(n*C_B + k))*MAT + irow*D_B + tx*4;
            u32 l0, l1;
            u32 h0 = split2(vq[0], vq[1], l0), h1 = split2(vq[2], vq[3], l1);
            *(uint2*)&g_Qh[base] = make_uint2(h0, h1);
            *(uint2*)&g_Ql[base] = make_uint2(l0, l1);
            h0 = split2(vk[0], vk[1], l0); h1 = split2(vk[2], vk[3], l1);
            *(uint2*)&g_Kh[base] = make_uint2(h0, h1);
            *(uint2*)&g_Kl[base] = make_uint2(l0, l1);
        }
}

// ============================================================================
// k_attn: HMMA (mma.sync bf16 split-2) chain, one CTA per (n,k).
//   St = Q^T K; Apre = St^T K; e = exp(Apre - max); sr from rowsums;
//   e~ = e*diag(sr); X''' = clip(cov2cor(inp)); P = e~ X'''; O = P e~^T;
//   out = inp + lam*sr_i*sr_j*O
// Buffers: B0: Q -> inp(fp32 flat) -> P | B1: K -> X''' | B2: St -> e~
// ============================================================================
__global__ __launch_bounds__(TPB, 1) void k_attn(const float* __restrict__ inp,
                                                 const float* __restrict__ lam,
                                                 float* __restrict__ out){
    extern __shared__ char smc[];
    float* B0f = (float*)smc;
    u32 sb = smem_u32(smc);
    u32 B0 = sb, B1 = sb + SBYTES, B2 = sb + 2*SBYTES;
    __shared__ float s_rv[D_B], s_sr[D_B], s_dia[D_B], s_part[D_B][4], s_red[12];
    int tid = threadIdx.x, w = tid >> 5, l = tid & 31;
    int wm = w >> 2, wn = w & 3;
    int r0 = l >> 2, c0 = (l & 3)*2;
    int nk = blockIdx.x;
    size_t gb = (size_t)nk * MAT;

    // pure cp.async prologue: Qh/Ql -> B0, Kh/Kl -> B1 (no conversion math)
    {
        const u16* srcs[4] = { g_Qh + gb, g_Ql + gb, g_Kh + gb, g_Kl + gb };
        u32 dsts[4] = { B0, B0 + TILEB, B1, B1 + TILEB };
        #pragma unroll
        for (int t = 0; t < 4; t++)
            for (int g = tid; g < 2048; g += TPB){
                int m = g >> 4, c = (g & 15)*8;
                cp16(dsts[t] + (u32)((m*SSTR + c)*2), srcs[t] + m*128 + c);
            }
        cp_commit();
    }
    if (tid < D_B) s_rv[tid] = g_rv[nk*D_B + tid];
    cp_wait0();
    __syncthreads();

    float acc[4][4][4];
    wmm(B0, B1, 1, 1, wm, wn, l, acc);              // St = Q^T K
    store_acc(smc, B2 - sb, wm, wn, l, acc, 0);
    __syncthreads();

    // prefetch raw inp tile (fp32 flat) into B0 while mm2 runs
    for (int e = tid; e < 4096; e += TPB) cp16(B0 + e*16, inp + gb + e*4);
    cp_commit();

    wmm(B2, B1, 1, 1, wm, wn, l, acc);              // Apre = St^T K
    cp_wait0();
    // block max
    float mx = -3.4e38f;
    #pragma unroll
    for (int mt = 0; mt < 4; mt++)
        #pragma unroll
        for (int nt = 0; nt < 4; nt++)
            #pragma unroll
            for (int q = 0; q < 4; q++) mx = fmaxf(mx, acc[mt][nt][q]);
    #pragma unroll
    for (int o = 16; o; o >>= 1) mx = fmaxf(mx, __shfl_xor_sync(0xffffffffu, mx, o));
    if (l == 0) s_red[w] = mx;
    __syncthreads();
    if (tid == 0){
        float m2 = s_red[0];
        #pragma unroll
        for (int q = 1; q < 8; q++) m2 = fmaxf(m2, s_red[q]);
        s_red[8] = m2;
    }
    __syncthreads();
    float bmax = s_red[8];
    {   // exp (all-poly, fma pipe) in place + row partial sums
        const u64 kL2E = bcast2(1.4426950408889634f), kMAG = bcast2(12582912.0f),
                  kNMAG = bcast2(-12582912.0f), kN1 = bcast2(-1.0f),
                  kC5 = bcast2(1.3333558146e-3f), kC4 = bcast2(9.6181291076e-3f),
                  kC3 = bcast2(5.5504108664e-2f), kC2 = bcast2(2.4022650695e-1f),
                  kC1 = bcast2(6.9314718055e-1f), kONE = bcast2(1.0f),
                  kNB = bcast2(-bmax);
        float part[4][2] = {};
        #pragma unroll
        for (int mt = 0; mt < 4; mt++)
            #pragma unroll
            for (int nt = 0; nt < 4; nt++){
                u64 p0 = exp_pair(add2(pack2(acc[mt][nt][0], acc[mt][nt][1]), kNB),
                                  kL2E,kMAG,kNMAG,kN1,kC5,kC4,kC3,kC2,kC1,kONE);
                u64 p1 = exp_pair(add2(pack2(acc[mt][nt][2], acc[mt][nt][3]), kNB),
                                  kL2E,kMAG,kNMAG,kN1,kC5,kC4,kC3,kC2,kC1,kONE);
                unpack2(p0, acc[mt][nt][0], acc[mt][nt][1]);
                unpack2(p1, acc[mt][nt][2], acc[mt][nt][3]);
                part[mt][0] += acc[mt][nt][0] + acc[mt][nt][1];
                part[mt][1] += acc[mt][nt][2] + acc[mt][nt][3];
            }
        #pragma unroll
        for (int mt = 0; mt < 4; mt++)
            #pragma unroll
            for (int h = 0; h < 2; h++){
                float t = part[mt][h];
                t += __shfl_xor_sync(0xffffffffu, t, 1);
                t += __shfl_xor_sync(0xffffffffu, t, 2);
                if ((l & 3) == 0) s_part[wm*64 + mt*16 + h*8 + r0][wn] = t;
            }
    }
    __syncthreads();                                 // mm2 done; partials visible
    // X''' = clip(inp*rv_i*rv_j) from B0 flat -> B1 (bf16 hi/lo)
    for (int e = tid; e < 4096; e += TPB){
        int i = e >> 5, j = (e & 31)*4;
        float4 v = *(float4*)(B0f + e*4);
        float ri = s_rv[i];
        v.x = clip1(v.x*ri*s_rv[j+0]); v.y = clip1(v.y*ri*s_rv[j+1]);
        v.z = clip1(v.z*ri*s_rv[j+2]); v.w = clip1(v.w*ri*s_rv[j+3]);
        u32 lp0, lp1;
        u32 hp0 = split2(v.x, v.y, lp0), hp1 = split2(v.z, v.w, lp1);
        u32 off = (u32)((i*SSTR + j)*2);
        *(u32*)(smc + SBYTES + off) = hp0;  *(u32*)(smc + SBYTES + off + 4) = hp1;
        *(u32*)(smc + SBYTES + off + TILEB) = lp0;  *(u32*)(smc + SBYTES + off + TILEB + 4) = lp1;
    }
    if (tid < D_B)
        s_dia[tid] = s_part[tid][0] + s_part[tid][1] + s_part[tid][2] + s_part[tid][3];
    __syncthreads();
    if (tid < 32){
        float t = s_dia[tid] + s_dia[tid+32] + s_dia[tid+64] + s_dia[tid+96];
        #pragma unroll
        for (int o = 16; o; o >>= 1) t += __shfl_xor_sync(0xffffffffu, t, o);
        if (tid == 0) s_red[9] = t;
    }
    __syncthreads();
    if (tid < D_B){
        float d = fmaxf(fmaxf(s_dia[tid], s_red[9]/100000.0f), 1e-5f);
        s_sr[tid] = rsqrtf(d);
    }
    __syncthreads();
    store_acc(smc, B2 - sb, wm, wn, l, acc, s_sr);   // e~ = e * sr_col
    __syncthreads();

    wmm(B2, B1, 0, 1, wm, wn, l, acc);               // P = e~ X'''
    store_acc(smc, 0, wm, wn, l, acc, 0);            // P -> B0
    __syncthreads();

    wmm(B0, B2, 0, 0, wm, wn, l, acc);               // O = P e~^T
    {   // epilogue: out = inp + lam*sr_i*sr_j*O
        float lamv = lam[nk & (C_B - 1)];
        #pragma unroll
        for (int mt = 0; mt < 4; mt++)
            #pragma unroll
            for (int nt = 0; nt < 4; nt++){
                int row = wm*64 + mt*16 + r0, col = wn*32 + nt*8 + c0;
                float sc0 = s_sr[col], sc1 = s_sr[col+1];
                #pragma unroll
                for (int h = 0; h < 2; h++){
                    int rr = row + h*8;
                    float li = lamv * s_sr[rr];
                    float2 iv = *(const float2*)&inp[gb + rr*128 + col];
                    float2 o;
                    o.x = iv.x + li*sc0*acc[mt][nt][h*2+0];
                    o.y = iv.y + li*sc1*acc[mt][nt][h*2+1];
                    *(float2*)&out[gb + rr*128 + col] = o;
                }
            }
    }
}

// ============================================================================
extern "C" void kernel_launch(void* const* d_in, const int* in_sizes, int n_in,
                              void* d_out, int out_size){
    const float* inp = (const float*)d_in[0];
    const float* wq  = (const float*)d_in[1];
    const float* wk  = (const float*)d_in[2];
    const float* lam = (const float*)d_in[3];
    float* out = (float*)d_out;

    cudaFuncSetAttribute(k_attn, cudaFuncAttributeMaxDynamicSharedMemorySize, DSM);

    k_rinv<<<NK_TOT, D_B>>>(inp);
    k_mix<<<dim3(D_B, N_B), 256>>>(inp, wq, wk);
    k_attn<<<NK_TOT, TPB, DSM>>>(inp, lam, out);
}

// round 11
// speedup vs baseline: 1.8818x; 1.0757x over previous
#include <cuda_runtime.h>
#include <cuda_bf16.h>

#define N_B 32
#define C_B 64
#define D_B 128
#define MAT 16384
#define NK_TOT 2048
#define TPB 256

// bf16/fp16 tile geometry for k_attn
#define SSTR 136                 // halves per row (272B, conflict-free for ldmatrix)
#define TILEB 34816              // one 128x136 b16 tile
#define SBYTES 69632             // hi+lo pair
#define DSM (3*SBYTES)           // 208896 B dynamic smem
#define PSCL 0.03125f            // P storage scale (overflow guard)
#define PSCLI 32.0f

typedef unsigned long long u64;
typedef unsigned int u32;
typedef unsigned short u16;

__device__ float g_rv[NK_TOT*D_B];
// Q/K pre-split to bf16 hi/lo by k_mix (same total bytes as fp32)
__device__ u16 g_Qh[NK_TOT*MAT], g_Ql[NK_TOT*MAT];
__device__ u16 g_Kh[NK_TOT*MAT], g_Kl[NK_TOT*MAT];

// ---------- f32x2 helpers ----------
__device__ __forceinline__ u64 bcast2(float x){
    u64 r; asm("mov.b64 %0, {%1, %1};" : "=l"(r) : "r"(__float_as_uint(x))); return r;
}
__device__ __forceinline__ u64 pack2(float a, float b){
    u64 r; asm("mov.b64 %0, {%1, %2};" : "=l"(r) : "r"(__float_as_uint(a)), "r"(__float_as_uint(b))); return r;
}
__device__ __forceinline__ u64 ffma2(u64 a, u64 b, u64 c){
    u64 d; asm("fma.rn.f32x2 %0, %1, %2, %3;" : "=l"(d) : "l"(a), "l"(b), "l"(c)); return d;
}
__device__ __forceinline__ u64 add2(u64 a, u64 b){
    u64 d; asm("add.rn.f32x2 %0, %1, %2;" : "=l"(d) : "l"(a), "l"(b)); return d;
}
__device__ __forceinline__ u64 mul2(u64 a, u64 b){
    u64 d; asm("mul.rn.f32x2 %0, %1, %2;" : "=l"(d) : "l"(a), "l"(b)); return d;
}
__device__ __forceinline__ void unpack2(u64 v, float& lo, float& hi){
    u32 a, b; asm("mov.b64 {%0, %1}, %2;" : "=r"(a), "=r"(b) : "l"(v));
    lo = __uint_as_float(a); hi = __uint_as_float(b);
}
__device__ __forceinline__ void unpack2u(u64 v, u32& a, u32& b){
    asm("mov.b64 {%0, %1}, %2;" : "=r"(a), "=r"(b) : "l"(v));
}
union F4U { float4 f; u64 u[2]; };
__device__ __forceinline__ float clip1(float x){ return fminf(1.f, fmaxf(-1.f, x)); }

// fma-pipe exp (magic rounding + deg-5 Taylor), underflow-clamped
__device__ __forceinline__ u64 exp_pair(u64 xb, u64 kL2E, u64 kMAG, u64 kNMAG, u64 kN1,
                                        u64 kC5, u64 kC4, u64 kC3, u64 kC2, u64 kC1, u64 kONE){
    u64 y = mul2(xb, kL2E);
    u64 z = add2(y, kMAG);
    u64 t = add2(z, kNMAG);
    u64 f = ffma2(t, kN1, y);
    u64 p = ffma2(kC5, f, kC4);
    p = ffma2(p, f, kC3); p = ffma2(p, f, kC2); p = ffma2(p, f, kC1); p = ffma2(p, f, kONE);
    u32 zl, zh; unpack2u(z, zl, zh);
    int n0 = max((int)(zl - 0x4B400000u), -127), n1 = max((int)(zh - 0x4B400000u), -127);
    u64 s; asm("mov.b64 %0, {%1, %2};" : "=l"(s)
               : "r"((u32)(n0 + 127) << 23), "r"((u32)(n1 + 127) << 23));
    return mul2(p, s);
}

// ---------- async / mma primitives (arch-generic, sm_80+) ----------
__device__ __forceinline__ void cp16(u32 s, const void* g){
    asm volatile("cp.async.cg.shared.global [%0], [%1], 16;" :: "r"(s), "l"(g));
}
__device__ __forceinline__ void cp_commit(){ asm volatile("cp.async.commit_group;"); }
__device__ __forceinline__ void cp_wait0(){ asm volatile("cp.async.wait_group 0;"); }
__device__ __forceinline__ u32 smem_u32(const void* p){
    u32 a; asm("{ .reg .u64 t; cvta.to.shared.u64 t, %1; cvt.u32.u64 %0, t; }" : "=r"(a) : "l"(p));
    return a;
}
__device__ __forceinline__ void ldsm4(u32 a, u32* r){
    asm volatile("ldmatrix.sync.aligned.m8n8.x4.shared.b16 {%0,%1,%2,%3}, [%4];"
        : "=r"(r[0]), "=r"(r[1]), "=r"(r[2]), "=r"(r[3]) : "r"(a));
}
__device__ __forceinline__ void ldsm4t(u32 a, u32* r){
    asm volatile("ldmatrix.sync.aligned.m8n8.x4.trans.shared.b16 {%0,%1,%2,%3}, [%4];"
        : "=r"(r[0]), "=r"(r[1]), "=r"(r[2]), "=r"(r[3]) : "r"(a));
}
__device__ __forceinline__ void ldsm2(u32 a, u32* r){
    asm volatile("ldmatrix.sync.aligned.m8n8.x2.shared.b16 {%0,%1}, [%2];"
        : "=r"(r[0]), "=r"(r[1]) : "r"(a));
}
__device__ __forceinline__ void ldsm2t(u32 a, u32* r){
    asm volatile("ldmatrix.sync.aligned.m8n8.x2.trans.shared.b16 {%0,%1}, [%2];"
        : "=r"(r[0]), "=r"(r[1]) : "r"(a));
}
__device__ __forceinline__ void mmab(float* d, const u32* a, const u32* b){
    asm volatile("mma.sync.aligned.m16n8k16.row.col.f32.bf16.bf16.f32 "
        "{%0,%1,%2,%3},{%4,%5,%6,%7},{%8,%9},{%0,%1,%2,%3};"
        : "+f"(d[0]), "+f"(d[1]), "+f"(d[2]), "+f"(d[3])
        : "r"(a[0]), "r"(a[1]), "r"(a[2]), "r"(a[3]), "r"(b[0]), "r"(b[1]));
}
__device__ __forceinline__ void mmah(float* d, const u32* a, const u32* b){
    asm volatile("mma.sync.aligned.m16n8k16.row.col.f32.f16.f16.f32 "
        "{%0,%1,%2,%3},{%4,%5,%6,%7},{%8,%9},{%0,%1,%2,%3};"
        : "+f"(d[0]), "+f"(d[1]), "+f"(d[2]), "+f"(d[3])
        : "r"(a[0]), "r"(a[1]), "r"(a[2]), "r"(a[3]), "r"(b[0]), "r"(b[1]));
}
// pack two floats to bf16x2 (first arg in low half)
__device__ __forceinline__ u32 cvt2bf(float lo, float hi){
    u32 r; asm("cvt.rn.bf16x2.f32 %0, %1, %2;" : "=r"(r) : "f"(hi), "f"(lo)); return r;
}
// pack two floats to f16x2 (first arg in low half)
__device__ __forceinline__ u32 cvt2h(float lo, float hi){
    u32 r; asm("cvt.rn.f16x2.f32 %0, %1, %2;" : "=r"(r) : "f"(hi), "f"(lo)); return r;
}
// split-2: returns hi-pair; lo residual pair via out param
__device__ __forceinline__ u32 split2(float v0, float v1, u32& lopair){
    u32 hp = cvt2bf(v0, v1);
    float h0 = __uint_as_float(hp << 16);
    float h1 = __uint_as_float(hp & 0xffff0000u);
    lopair = cvt2bf(v0 - h0, v1 - h1);
    return hp;
}

// warp-tile split-2 bf16 matmul: acc = (Ah+Al)(Bh+Bl) minus Al*Bl (3 products).
__device__ __forceinline__ void wmm(u32 aB, u32 bB, int am, int bm,
                                    int wm, int wn, int l, float acc[4][4][4]){
    #pragma unroll
    for (int mt = 0; mt < 4; mt++)
        #pragma unroll
        for (int nt = 0; nt < 4; nt++)
            #pragma unroll
            for (int q = 0; q < 4; q++) acc[mt][nt][q] = 0.f;
    #pragma unroll
    for (int ks = 0; ks < 8; ks++){
        int k0 = ks*16;
        u32 Ah[4][4], Al[4][4], Bh[4][2], Bl[4][2];
        #pragma unroll
        for (int mt = 0; mt < 4; mt++){
            int i0 = wm*64 + mt*16;
            u32 ad;
            if (am == 0) ad = aB + (u32)(((i0 + (l&7) + ((l>>3)&1)*8)*SSTR + k0 + (l>>4)*8)*2);
            else         ad = aB + (u32)(((k0 + (l>>4)*8 + (l&7))*SSTR + i0 + ((l>>3)&1)*8)*2);
            if (am == 0){ ldsm4(ad, Ah[mt]);  ldsm4(ad + TILEB, Al[mt]); }
            else        { ldsm4t(ad, Ah[mt]); ldsm4t(ad + TILEB, Al[mt]); }
        }
        #pragma unroll
        for (int nt = 0; nt < 4; nt++){
            int j0 = wn*32 + nt*8;
            u32 bd;
            if (bm == 0) bd = bB + (u32)(((j0 + (l&7))*SSTR + k0 + ((l>>3)&1)*8)*2);
            else         bd = bB + (u32)(((k0 + (l&15))*SSTR + j0)*2);
            if (bm == 0){ ldsm2(bd, Bh[nt]);  ldsm2(bd + TILEB, Bl[nt]); }
            else        { ldsm2t(bd, Bh[nt]); ldsm2t(bd + TILEB, Bl[nt]); }
        }
        #pragma unroll
        for (int mt = 0; mt < 4; mt++)
            #pragma unroll
            for (int nt = 0; nt < 4; nt++){
                mmab(acc[mt][nt], Ah[mt], Bh[nt]);
                mmab(acc[mt][nt], Ah[mt], Bl[nt]);
                mmab(acc[mt][nt], Al[mt], Bh[nt]);
            }
    }
}

// warp-tile single-product fp16 matmul (relative-error path: P, O)
__device__ __forceinline__ void wmm_h(u32 aB, u32 bB, int am, int bm,
                                      int wm, int wn, int l, float acc[4][4][4]){
    #pragma unroll
    for (int mt = 0; mt < 4; mt++)
        #pragma unroll
        for (int nt = 0; nt < 4; nt++)
            #pragma unroll
            for (int q = 0; q < 4; q++) acc[mt][nt][q] = 0.f;
    #pragma unroll
    for (int ks = 0; ks < 8; ks++){
        int k0 = ks*16;
        u32 Ah[4][4], Bh[4][2];
        #pragma unroll
        for (int mt = 0; mt < 4; mt++){
            int i0 = wm*64 + mt*16;
            u32 ad;
            if (am == 0) ad = aB + (u32)(((i0 + (l&7) + ((l>>3)&1)*8)*SSTR + k0 + (l>>4)*8)*2);
            else         ad = aB + (u32)(((k0 + (l>>4)*8 + (l&7))*SSTR + i0 + ((l>>3)&1)*8)*2);
            if (am == 0) ldsm4(ad, Ah[mt]);
            else         ldsm4t(ad, Ah[mt]);
        }
        #pragma unroll
        for (int nt = 0; nt < 4; nt++){
            int j0 = wn*32 + nt*8;
            u32 bd;
            if (bm == 0) bd = bB + (u32)(((j0 + (l&7))*SSTR + k0 + ((l>>3)&1)*8)*2);
            else         bd = bB + (u32)(((k0 + (l&15))*SSTR + j0)*2);
            if (bm == 0) ldsm2(bd, Bh[nt]);
            else         ldsm2t(bd, Bh[nt]);
        }
        #pragma unroll
        for (int mt = 0; mt < 4; mt++)
            #pragma unroll
            for (int nt = 0; nt < 4; nt++)
                mmah(acc[mt][nt], Ah[mt], Bh[nt]);
    }
}

// store warp acc -> bf16 hi/lo tile (split-2), optional per-column scale
__device__ __forceinline__ void store_acc(char* smc, u32 dstOff, int wm, int wn, int l,
                                          float acc[4][4][4], const float* colscale){
    int r0 = l >> 2, c0 = (l & 3)*2;
    #pragma unroll
    for (int mt = 0; mt < 4; mt++)
        #pragma unroll
        for (int nt = 0; nt < 4; nt++){
            int row = wm*64 + mt*16 + r0, col = wn*32 + nt*8 + c0;
            float s0 = 1.f, s1 = 1.f;
            if (colscale){ s0 = colscale[col]; s1 = colscale[col+1]; }
            #pragma unroll
            for (int h = 0; h < 2; h++){
                float v0 = acc[mt][nt][h*2] * s0, v1 = acc[mt][nt][h*2+1] * s1;
                u32 lp, hp = split2(v0, v1, lp);
                u32 off = dstOff + (u32)((((row + h*8)*SSTR) + col)*2);
                *(u32*)(smc + off) = hp;
                *(u32*)(smc + off + TILEB) = lp;
            }
        }
}

// store warp acc -> single fp16 tile, optional per-column scale + global scale
__device__ __forceinline__ void store_acc_h(char* smc, u32 dstOff, int wm, int wn, int l,
                                            float acc[4][4][4], const float* colscale,
                                            float gs){
    int r0 = l >> 2, c0 = (l & 3)*2;
    #pragma unroll
    for (int mt = 0; mt < 4; mt++)
        #pragma unroll
        for (int nt = 0; nt < 4; nt++){
            int row = wm*64 + mt*16 + r0, col = wn*32 + nt*8 + c0;
            float s0 = gs, s1 = gs;
            if (colscale){ s0 *= colscale[col]; s1 *= colscale[col+1]; }
            #pragma unroll
            for (int h = 0; h < 2; h++){
                u32 hp = cvt2h(acc[mt][nt][h*2] * s0, acc[mt][nt][h*2+1] * s1);
                *(u32*)(smc + dstOff + (u32)((((row + h*8)*SSTR) + col)*2)) = hp;
            }
        }
}

// ============================================================================
__global__ void k_rinv(const float* __restrict__ in){
    int nk = blockIdx.x, t = threadIdx.x;
    float v = in[(size_t)nk*MAT + t*D_B + t];
    g_rv[nk*D_B + t] = rsqrtf(fmaxf(fabsf(v), 1e-4f));
}

// fused cov2cor + channel mixing; outputs bf16 hi/lo pairs (validated, frozen)
__global__ __launch_bounds__(256, 1) void k_mix(const float* __restrict__ inp,
                                                const float* __restrict__ wq,
                                                const float* __restrict__ wk){
    __shared__ float sWQ[C_B*C_B], sWK[C_B*C_B], sX[8*D_B], sRV[8*D_B];
    int tid = threadIdx.x, n = blockIdx.y, irow = blockIdx.x;
    for (int i = tid; i < C_B*C_B; i += 256){ sWQ[i] = wq[i]; sWK[i] = wk[i]; }
    int tx = tid & 31, ty = tid >> 5, k0 = ty*8;
    u64 aQ[4][4], aK[4][4];
    #pragma unroll
    for (int p = 0; p < 4; p++)
        #pragma unroll
        for (int q = 0; q < 4; q++){ aQ[p][q] = 0ull; aK[p][q] = 0ull; }
    __syncthreads();
    for (int cc = 0; cc < C_B; cc += 8){
        {
            int idx = tid*4, cl = idx >> 7, j = idx & 127;
            *(float4*)&sRV[idx] = *(const float4*)&g_rv[((size_t)(n*C_B + cc + cl))*D_B + j];
        }
        __syncthreads();
        {
            int cl = tid >> 5, jj = (tid & 31)*4;
            float4 v = *(const float4*)&inp[((size_t)(n*C_B + cc + cl))*MAT + irow*D_B + jj];
            float ri = sRV[cl*D_B + irow];
            v.x = clip1(v.x*ri*sRV[cl*D_B + jj+0]); v.y = clip1(v.y*ri*sRV[cl*D_B + jj+1]);
            v.z = clip1(v.z*ri*sRV[cl*D_B + jj+2]); v.w = clip1(v.w*ri*sRV[cl*D_B + jj+3]);
            *(float4*)&sX[cl*D_B + jj] = v;
        }
        __syncthreads();
        #pragma unroll
        for (int cl = 0; cl < 8; cl++){
            int c = cc + cl;
            float4 xv = *(const float4*)&sX[cl*D_B + tx*4];
            u64 xx[4] = { bcast2(xv.x), bcast2(xv.y), bcast2(xv.z), bcast2(xv.w) };
            F4U q0, q1, kk0, kk1;
            q0.f = *(const float4*)&sWQ[c*C_B + k0];  q1.f = *(const float4*)&sWQ[c*C_B + k0 + 4];
            kk0.f = *(const float4*)&sWK[c*C_B + k0]; kk1.f = *(const float4*)&sWK[c*C_B + k0 + 4];
            u64 bq[4] = { q0.u[0], q0.u[1], q1.u[0], q1.u[1] };
            u64 bk[4] = { kk0.u[0], kk0.u[1], kk1.u[0], kk1.u[1] };
            #pragma unroll
            for (int p = 0; p < 4; p++)
                #pragma unroll
                for (int q = 0; q < 4; q++){
                    aQ[p][q] = ffma2(xx[p], bq[q], aQ[p][q]);
                    aK[p][q] = ffma2(xx[p], bk[q], aK[p][q]);
                }
        }
        __syncthreads();
    }
    #pragma unroll
    for (int q = 0; q < 4; q++)
        #pragma unroll
        for (int h = 0; h < 2; h++){
            int k = k0 + q*2 + h;
            float vq[4], vk[4];
            #pragma unroll
            for (int p = 0; p < 4; p++){
                float lo, hi;
                unpack2(aQ[p][q], lo, hi); vq[p] = h ? hi : lo;
                unpack2(aK[p][q], lo, hi); vk[p] = h ? hi : lo;
            }
            size_t base = ((size_t)(n*C_B + k))*MAT + irow*D_B + tx*4;
            u32 l0, l1;
            u32 h0 = split2(vq[0], vq[1], l0), h1 = split2(vq[2], vq[3], l1);
            *(uint2*)&g_Qh[base] = make_uint2(h0, h1);
            *(uint2*)&g_Ql[base] = make_uint2(l0, l1);
            h0 = split2(vk[0], vk[1], l0); h1 = split2(vk[2], vk[3], l1);
            *(uint2*)&g_Kh[base] = make_uint2(h0, h1);
            *(uint2*)&g_Kl[base] = make_uint2(l0, l1);
        }
}

// ============================================================================
// k_attn: mm1/mm2 bf16 split-2 (exp-critical); mm3/mm4 fp16 single-product.
//   St = Q^T K; Apre = St^T K; e = exp(Apre - max); sr from rowsums;
//   e~ = e*diag(sr) [fp16]; X''' = clip(cov2cor(inp)) [fp16];
//   P = e~ X''' (stored fp16, x1/32); O = P e~^T;
//   out = inp + lam*32*sr_i*sr_j*O
// Buffers: B0: Qhi/lo -> inp(fp32 flat) -> P(fp16) | B1: Khi/lo -> X'''(fp16)
//          B2: St(hi/lo) -> e~(fp16)
// ============================================================================
__global__ __launch_bounds__(TPB, 1) void k_attn(const float* __restrict__ inp,
                                                 const float* __restrict__ lam,
                                                 float* __restrict__ out){
    extern __shared__ char smc[];
    float* B0f = (float*)smc;
    u32 sb = smem_u32(smc);
    u32 B0 = sb, B1 = sb + SBYTES, B2 = sb + 2*SBYTES;
    __shared__ float s_rv[D_B], s_sr[D_B], s_dia[D_B], s_part[D_B][4], s_red[12];
    int tid = threadIdx.x, w = tid >> 5, l = tid & 31;
    int wm = w >> 2, wn = w & 3;
    int r0 = l >> 2, c0 = (l & 3)*2;
    int nk = blockIdx.x;
    size_t gb = (size_t)nk * MAT;

    // pure cp.async prologue: Qh/Ql -> B0, Kh/Kl -> B1
    {
        const u16* srcs[4] = { g_Qh + gb, g_Ql + gb, g_Kh + gb, g_Kl + gb };
        u32 dsts[4] = { B0, B0 + TILEB, B1, B1 + TILEB };
        #pragma unroll
        for (int t = 0; t < 4; t++)
            for (int g = tid; g < 2048; g += TPB){
                int m = g >> 4, c = (g & 15)*8;
                cp16(dsts[t] + (u32)((m*SSTR + c)*2), srcs[t] + m*128 + c);
            }
        cp_commit();
    }
    if (tid < D_B) s_rv[tid] = g_rv[nk*D_B + tid];
    cp_wait0();
    __syncthreads();

    float acc[4][4][4];
    wmm(B0, B1, 1, 1, wm, wn, l, acc);              // St = Q^T K
    store_acc(smc, B2 - sb, wm, wn, l, acc, 0);
    __syncthreads();

    // prefetch raw inp tile (fp32 flat) into B0 while mm2 runs
    for (int e = tid; e < 4096; e += TPB) cp16(B0 + e*16, inp + gb + e*4);
    cp_commit();

    wmm(B2, B1, 1, 1, wm, wn, l, acc);              // Apre = St^T K
    cp_wait0();
    // block max
    float mx = -3.4e38f;
    #pragma unroll
    for (int mt = 0; mt < 4; mt++)
        #pragma unroll
        for (int nt = 0; nt < 4; nt++)
            #pragma unroll
            for (int q = 0; q < 4; q++) mx = fmaxf(mx, acc[mt][nt][q]);
    #pragma unroll
    for (int o = 16; o; o >>= 1) mx = fmaxf(mx, __shfl_xor_sync(0xffffffffu, mx, o));
    if (l == 0) s_red[w] = mx;
    __syncthreads();
    if (tid == 0){
        float m2 = s_red[0];
        #pragma unroll
        for (int q = 1; q < 8; q++) m2 = fmaxf(m2, s_red[q]);
        s_red[8] = m2;
    }
    __syncthreads();
    float bmax = s_red[8];
    {   // exp (all-poly, fma pipe) in place + row partial sums
        const u64 kL2E = bcast2(1.4426950408889634f), kMAG = bcast2(12582912.0f),
                  kNMAG = bcast2(-12582912.0f), kN1 = bcast2(-1.0f),
                  kC5 = bcast2(1.3333558146e-3f), kC4 = bcast2(9.6181291076e-3f),
                  kC3 = bcast2(5.5504108664e-2f), kC2 = bcast2(2.4022650695e-1f),
                  kC1 = bcast2(6.9314718055e-1f), kONE = bcast2(1.0f),
                  kNB = bcast2(-bmax);
        float part[4][2] = {};
        #pragma unroll
        for (int mt = 0; mt < 4; mt++)
            #pragma unroll
            for (int nt = 0; nt < 4; nt++){
                u64 p0 = exp_pair(add2(pack2(acc[mt][nt][0], acc[mt][nt][1]), kNB),
                                  kL2E,kMAG,kNMAG,kN1,kC5,kC4,kC3,kC2,kC1,kONE);
                u64 p1 = exp_pair(add2(pack2(acc[mt][nt][2], acc[mt][nt][3]), kNB),
                                  kL2E,kMAG,kNMAG,kN1,kC5,kC4,kC3,kC2,kC1,kONE);
                unpack2(p0, acc[mt][nt][0], acc[mt][nt][1]);
                unpack2(p1, acc[mt][nt][2], acc[mt][nt][3]);
                part[mt][0] += acc[mt][nt][0] + acc[mt][nt][1];
                part[mt][1] += acc[mt][nt][2] + acc[mt][nt][3];
            }
        #pragma unroll
        for (int mt = 0; mt < 4; mt++)
            #pragma unroll
            for (int h = 0; h < 2; h++){
                float t = part[mt][h];
                t += __shfl_xor_sync(0xffffffffu, t, 1);
                t += __shfl_xor_sync(0xffffffffu, t, 2);
                if ((l & 3) == 0) s_part[wm*64 + mt*16 + h*8 + r0][wn] = t;
            }
    }
    __syncthreads();                                 // mm2 done; partials visible
    // X''' = clip(inp*rv_i*rv_j) from B0 flat -> B1 as single fp16 tile
    for (int e = tid; e < 4096; e += TPB){
        int i = e >> 5, j = (e & 31)*4;
        float4 v = *(float4*)(B0f + e*4);
        float ri = s_rv[i];
        v.x = clip1(v.x*ri*s_rv[j+0]); v.y = clip1(v.y*ri*s_rv[j+1]);
        v.z = clip1(v.z*ri*s_rv[j+2]); v.w = clip1(v.w*ri*s_rv[j+3]);
        u32 off = (u32)((i*SSTR + j)*2);
        *(u32*)(smc + SBYTES + off)     = cvt2h(v.x, v.y);
        *(u32*)(smc + SBYTES + off + 4) = cvt2h(v.z, v.w);
    }
    if (tid < D_B)
        s_dia[tid] = s_part[tid][0] + s_part[tid][1] + s_part[tid][2] + s_part[tid][3];
    __syncthreads();
    if (tid < 32){
        float t = s_dia[tid] + s_dia[tid+32] + s_dia[tid+64] + s_dia[tid+96];
        #pragma unroll
        for (int o = 16; o; o >>= 1) t += __shfl_xor_sync(0xffffffffu, t, o);
        if (tid == 0) s_red[9] = t;
    }
    __syncthreads();
    if (tid < D_B){
        float d = fmaxf(fmaxf(s_dia[tid], s_red[9]/100000.0f), 1e-5f);
        s_sr[tid] = rsqrtf(d);
    }
    __syncthreads();
    store_acc_h(smc, B2 - sb, wm, wn, l, acc, s_sr, 1.0f);  // e~ = e*sr_col (fp16)
    __syncthreads();

    wmm_h(B2, B1, 0, 1, wm, wn, l, acc);             // P = e~ X''' (fp16 path)
    store_acc_h(smc, 0, wm, wn, l, acc, 0, PSCL);    // P/32 -> B0 (fp16)
    __syncthreads();

    wmm_h(B0, B2, 0, 0, wm, wn, l, acc);             // O = (P/32) e~^T
    {   // epilogue: out = inp + lam*32*sr_i*sr_j*O
        float lamv = lam[nk & (C_B - 1)] * PSCLI;
        #pragma unroll
        for (int mt = 0; mt < 4; mt++)
            #pragma unroll
            for (int nt = 0; nt < 4; nt++){
                int row = wm*64 + mt*16 + r0, col = wn*32 + nt*8 + c0;
                float sc0 = s_sr[col], sc1 = s_sr[col+1];
                #pragma unroll
                for (int h = 0; h < 2; h++){
                    int rr = row + h*8;
                    float li = lamv * s_sr[rr];
                    float2 iv = *(const float2*)&inp[gb + rr*128 + col];
                    float2 o;
                    o.x = iv.x + li*sc0*acc[mt][nt][h*2+0];
                    o.y = iv.y + li*sc1*acc[mt][nt][h*2+1];
                    *(float2*)&out[gb + rr*128 + col] = o;
                }
            }
    }
}

// ============================================================================
extern "C" void kernel_launch(void* const* d_in, const int* in_sizes, int n_in,
                              void* d_out, int out_size){
    const float* inp = (const float*)d_in[0];
    const float* wq  = (const float*)d_in[1];
    const float* wk  = (const float*)d_in[2];
    const float* lam = (const float*)d_in[3];
    float* out = (float*)d_out;

    cudaFuncSetAttribute(k_attn, cudaFuncAttributeMaxDynamicSharedMemorySize, DSM);

    k_rinv<<<NK_TOT, D_B>>>(inp);
    k_mix<<<dim3(D_B, N_B), 256>>>(inp, wq, wk);
    k_attn<<<NK_TOT, TPB, DSM>>>(inp, lam, out);
}

// round 12
// speedup vs baseline: 2.0273x; 1.0773x over previous
#include <cuda_runtime.h>
#include <cuda_bf16.h>

#define N_B 32
#define C_B 64
#define D_B 128
#define MAT 16384
#define NK_TOT 2048
#define TPB 256

// bf16/fp16 tile geometry for k_attn
#define SSTR 136                 // halves per row (272B, conflict-free for ldmatrix)
#define TILEB 34816              // one 128x136 b16 tile
#define SBYTES 69632             // hi+lo pair
#define DSM (3*SBYTES)           // 208896 B dynamic smem
#define PSCL 0.03125f            // P storage scale (overflow guard)
#define PSCLI 32.0f

typedef unsigned long long u64;
typedef unsigned int u32;
typedef unsigned short u16;

__device__ float g_rv[NK_TOT*D_B];
// Q/K pre-split to bf16 hi/lo by k_mix (same total bytes as fp32)
__device__ u16 g_Qh[NK_TOT*MAT], g_Ql[NK_TOT*MAT];
__device__ u16 g_Kh[NK_TOT*MAT], g_Kl[NK_TOT*MAT];

// ---------- f32x2 helpers ----------
__device__ __forceinline__ u64 bcast2(float x){
    u64 r; asm("mov.b64 %0, {%1, %1};" : "=l"(r) : "r"(__float_as_uint(x))); return r;
}
__device__ __forceinline__ u64 pack2(float a, float b){
    u64 r; asm("mov.b64 %0, {%1, %2};" : "=l"(r) : "r"(__float_as_uint(a)), "r"(__float_as_uint(b))); return r;
}
__device__ __forceinline__ u64 ffma2(u64 a, u64 b, u64 c){
    u64 d; asm("fma.rn.f32x2 %0, %1, %2, %3;" : "=l"(d) : "l"(a), "l"(b), "l"(c)); return d;
}
__device__ __forceinline__ u64 add2(u64 a, u64 b){
    u64 d; asm("add.rn.f32x2 %0, %1, %2;" : "=l"(d) : "l"(a), "l"(b)); return d;
}
__device__ __forceinline__ u64 mul2(u64 a, u64 b){
    u64 d; asm("mul.rn.f32x2 %0, %1, %2;" : "=l"(d) : "l"(a), "l"(b)); return d;
}
__device__ __forceinline__ void unpack2(u64 v, float& lo, float& hi){
    u32 a, b; asm("mov.b64 {%0, %1}, %2;" : "=r"(a), "=r"(b) : "l"(v));
    lo = __uint_as_float(a); hi = __uint_as_float(b);
}
__device__ __forceinline__ void unpack2u(u64 v, u32& a, u32& b){
    asm("mov.b64 {%0, %1}, %2;" : "=r"(a), "=r"(b) : "l"(v));
}
union F4U { float4 f; u64 u[2]; };
__device__ __forceinline__ float clip1(float x){ return fminf(1.f, fmaxf(-1.f, x)); }

// fma-pipe exp (magic rounding + deg-5 Taylor), underflow-clamped
__device__ __forceinline__ u64 exp_pair(u64 xb, u64 kL2E, u64 kMAG, u64 kNMAG, u64 kN1,
                                        u64 kC5, u64 kC4, u64 kC3, u64 kC2, u64 kC1, u64 kONE){
    u64 y = mul2(xb, kL2E);
    u64 z = add2(y, kMAG);
    u64 t = add2(z, kNMAG);
    u64 f = ffma2(t, kN1, y);
    u64 p = ffma2(kC5, f, kC4);
    p = ffma2(p, f, kC3); p = ffma2(p, f, kC2); p = ffma2(p, f, kC1); p = ffma2(p, f, kONE);
    u32 zl, zh; unpack2u(z, zl, zh);
    int n0 = max((int)(zl - 0x4B400000u), -127), n1 = max((int)(zh - 0x4B400000u), -127);
    u64 s; asm("mov.b64 %0, {%1, %2};" : "=l"(s)
               : "r"((u32)(n0 + 127) << 23), "r"((u32)(n1 + 127) << 23));
    return mul2(p, s);
}

// ---------- async / mma primitives (arch-generic, sm_80+) ----------
__device__ __forceinline__ void cp16(u32 s, const void* g){
    asm volatile("cp.async.cg.shared.global [%0], [%1], 16;" :: "r"(s), "l"(g));
}
__device__ __forceinline__ void cp_commit(){ asm volatile("cp.async.commit_group;"); }
__device__ __forceinline__ void cp_wait0(){ asm volatile("cp.async.wait_group 0;"); }
__device__ __forceinline__ u32 smem_u32(const void* p){
    u32 a; asm("{ .reg .u64 t; cvta.to.shared.u64 t, %1; cvt.u32.u64 %0, t; }" : "=r"(a) : "l"(p));
    return a;
}
__device__ __forceinline__ void ldsm4(u32 a, u32* r){
    asm volatile("ldmatrix.sync.aligned.m8n8.x4.shared.b16 {%0,%1,%2,%3}, [%4];"
        : "=r"(r[0]), "=r"(r[1]), "=r"(r[2]), "=r"(r[3]) : "r"(a));
}
__device__ __forceinline__ void ldsm4t(u32 a, u32* r){
    asm volatile("ldmatrix.sync.aligned.m8n8.x4.trans.shared.b16 {%0,%1,%2,%3}, [%4];"
        : "=r"(r[0]), "=r"(r[1]), "=r"(r[2]), "=r"(r[3]) : "r"(a));
}
__device__ __forceinline__ void ldsm2(u32 a, u32* r){
    asm volatile("ldmatrix.sync.aligned.m8n8.x2.shared.b16 {%0,%1}, [%2];"
        : "=r"(r[0]), "=r"(r[1]) : "r"(a));
}
__device__ __forceinline__ void ldsm2t(u32 a, u32* r){
    asm volatile("ldmatrix.sync.aligned.m8n8.x2.trans.shared.b16 {%0,%1}, [%2];"
        : "=r"(r[0]), "=r"(r[1]) : "r"(a));
}
__device__ __forceinline__ void mmab(float* d, const u32* a, const u32* b){
    asm volatile("mma.sync.aligned.m16n8k16.row.col.f32.bf16.bf16.f32 "
        "{%0,%1,%2,%3},{%4,%5,%6,%7},{%8,%9},{%0,%1,%2,%3};"
        : "+f"(d[0]), "+f"(d[1]), "+f"(d[2]), "+f"(d[3])
        : "r"(a[0]), "r"(a[1]), "r"(a[2]), "r"(a[3]), "r"(b[0]), "r"(b[1]));
}
__device__ __forceinline__ void mmah(float* d, const u32* a, const u32* b){
    asm volatile("mma.sync.aligned.m16n8k16.row.col.f32.f16.f16.f32 "
        "{%0,%1,%2,%3},{%4,%5,%6,%7},{%8,%9},{%0,%1,%2,%3};"
        : "+f"(d[0]), "+f"(d[1]), "+f"(d[2]), "+f"(d[3])
        : "r"(a[0]), "r"(a[1]), "r"(a[2]), "r"(a[3]), "r"(b[0]), "r"(b[1]));
}
// pack two floats to bf16x2 (first arg in low half)
__device__ __forceinline__ u32 cvt2bf(float lo, float hi){
    u32 r; asm("cvt.rn.bf16x2.f32 %0, %1, %2;" : "=r"(r) : "f"(hi), "f"(lo)); return r;
}
// pack two floats to f16x2 (first arg in low half)
__device__ __forceinline__ u32 cvt2h(float lo, float hi){
    u32 r; asm("cvt.rn.f16x2.f32 %0, %1, %2;" : "=r"(r) : "f"(hi), "f"(lo)); return r;
}
// split-2: returns hi-pair; lo residual pair via out param
__device__ __forceinline__ u32 split2(float v0, float v1, u32& lopair){
    u32 hp = cvt2bf(v0, v1);
    float h0 = __uint_as_float(hp << 16);
    float h1 = __uint_as_float(hp & 0xffff0000u);
    lopair = cvt2bf(v0 - h0, v1 - h1);
    return hp;
}

// warp-tile split-2 bf16 matmul: acc = (Ah+Al)(Bh+Bl) minus Al*Bl (3 products).
__device__ __forceinline__ void wmm(u32 aB, u32 bB, int am, int bm,
                                    int wm, int wn, int l, float acc[4][4][4]){
    #pragma unroll
    for (int mt = 0; mt < 4; mt++)
        #pragma unroll
        for (int nt = 0; nt < 4; nt++)
            #pragma unroll
            for (int q = 0; q < 4; q++) acc[mt][nt][q] = 0.f;
    #pragma unroll
    for (int ks = 0; ks < 8; ks++){
        int k0 = ks*16;
        u32 Ah[4][4], Al[4][4], Bh[4][2], Bl[4][2];
        #pragma unroll
        for (int mt = 0; mt < 4; mt++){
            int i0 = wm*64 + mt*16;
            u32 ad;
            if (am == 0) ad = aB + (u32)(((i0 + (l&7) + ((l>>3)&1)*8)*SSTR + k0 + (l>>4)*8)*2);
            else         ad = aB + (u32)(((k0 + (l>>4)*8 + (l&7))*SSTR + i0 + ((l>>3)&1)*8)*2);
            if (am == 0){ ldsm4(ad, Ah[mt]);  ldsm4(ad + TILEB, Al[mt]); }
            else        { ldsm4t(ad, Ah[mt]); ldsm4t(ad + TILEB, Al[mt]); }
        }
        #pragma unroll
        for (int nt = 0; nt < 4; nt++){
            int j0 = wn*32 + nt*8;
            u32 bd;
            if (bm == 0) bd = bB + (u32)(((j0 + (l&7))*SSTR + k0 + ((l>>3)&1)*8)*2);
            else         bd = bB + (u32)(((k0 + (l&15))*SSTR + j0)*2);
            if (bm == 0){ ldsm2(bd, Bh[nt]);  ldsm2(bd + TILEB, Bl[nt]); }
            else        { ldsm2t(bd, Bh[nt]); ldsm2t(bd + TILEB, Bl[nt]); }
        }
        #pragma unroll
        for (int mt = 0; mt < 4; mt++)
            #pragma unroll
            for (int nt = 0; nt < 4; nt++){
                mmab(acc[mt][nt], Ah[mt], Bh[nt]);
                mmab(acc[mt][nt], Ah[mt], Bl[nt]);
                mmab(acc[mt][nt], Al[mt], Bh[nt]);
            }
    }
}

// warp-tile single-product fp16 matmul (relative-error path: P, O)
__device__ __forceinline__ void wmm_h(u32 aB, u32 bB, int am, int bm,
                                      int wm, int wn, int l, float acc[4][4][4]){
    #pragma unroll
    for (int mt = 0; mt < 4; mt++)
        #pragma unroll
        for (int nt = 0; nt < 4; nt++)
            #pragma unroll
            for (int q = 0; q < 4; q++) acc[mt][nt][q] = 0.f;
    #pragma unroll
    for (int ks = 0; ks < 8; ks++){
        int k0 = ks*16;
        u32 Ah[4][4], Bh[4][2];
        #pragma unroll
        for (int mt = 0; mt < 4; mt++){
            int i0 = wm*64 + mt*16;
            u32 ad;
            if (am == 0) ad = aB + (u32)(((i0 + (l&7) + ((l>>3)&1)*8)*SSTR + k0 + (l>>4)*8)*2);
            else         ad = aB + (u32)(((k0 + (l>>4)*8 + (l&7))*SSTR + i0 + ((l>>3)&1)*8)*2);
            if (am == 0) ldsm4(ad, Ah[mt]);
            else         ldsm4t(ad, Ah[mt]);
        }
        #pragma unroll
        for (int nt = 0; nt < 4; nt++){
            int j0 = wn*32 + nt*8;
            u32 bd;
            if (bm == 0) bd = bB + (u32)(((j0 + (l&7))*SSTR + k0 + ((l>>3)&1)*8)*2);
            else         bd = bB + (u32)(((k0 + (l&15))*SSTR + j0)*2);
            if (bm == 0) ldsm2(bd, Bh[nt]);
            else         ldsm2t(bd, Bh[nt]);
        }
        #pragma unroll
        for (int mt = 0; mt < 4; mt++)
            #pragma unroll
            for (int nt = 0; nt < 4; nt++)
                mmah(acc[mt][nt], Ah[mt], Bh[nt]);
    }
}

// store warp acc -> bf16 hi/lo tile (split-2), optional per-column scale
__device__ __forceinline__ void store_acc(char* smc, u32 dstOff, int wm, int wn, int l,
                                          float acc[4][4][4], const float* colscale){
    int r0 = l >> 2, c0 = (l & 3)*2;
    #pragma unroll
    for (int mt = 0; mt < 4; mt++)
        #pragma unroll
        for (int nt = 0; nt < 4; nt++){
            int row = wm*64 + mt*16 + r0, col = wn*32 + nt*8 + c0;
            float s0 = 1.f, s1 = 1.f;
            if (colscale){ s0 = colscale[col]; s1 = colscale[col+1]; }
            #pragma unroll
            for (int h = 0; h < 2; h++){
                float v0 = acc[mt][nt][h*2] * s0, v1 = acc[mt][nt][h*2+1] * s1;
                u32 lp, hp = split2(v0, v1, lp);
                u32 off = dstOff + (u32)((((row + h*8)*SSTR) + col)*2);
                *(u32*)(smc + off) = hp;
                *(u32*)(smc + off + TILEB) = lp;
            }
        }
}

// store warp acc -> single fp16 tile, optional per-column scale + global scale
__device__ __forceinline__ void store_acc_h(char* smc, u32 dstOff, int wm, int wn, int l,
                                            float acc[4][4][4], const float* colscale,
                                            float gs){
    int r0 = l >> 2, c0 = (l & 3)*2;
    #pragma unroll
    for (int mt = 0; mt < 4; mt++)
        #pragma unroll
        for (int nt = 0; nt < 4; nt++){
            int row = wm*64 + mt*16 + r0, col = wn*32 + nt*8 + c0;
            float s0 = gs, s1 = gs;
            if (colscale){ s0 *= colscale[col]; s1 *= colscale[col+1]; }
            #pragma unroll
            for (int h = 0; h < 2; h++){
                u32 hp = cvt2h(acc[mt][nt][h*2] * s0, acc[mt][nt][h*2+1] * s1);
                *(u32*)(smc + dstOff + (u32)((((row + h*8)*SSTR) + col)*2)) = hp;
            }
        }
}

// cp.async one pre-split tensor (hi or lo) into a tile region
__device__ __forceinline__ void pf_tile(u32 dst, const u16* __restrict__ src, int tid){
    for (int g = tid; g < 2048; g += TPB){
        int m = g >> 4, c = (g & 15)*8;
        cp16(dst + (u32)((m*SSTR + c)*2), src + m*128 + c);
    }
}

// ============================================================================
__global__ void k_rinv(const float* __restrict__ in){
    int nk = blockIdx.x, t = threadIdx.x;
    float v = in[(size_t)nk*MAT + t*D_B + t];
    g_rv[nk*D_B + t] = rsqrtf(fmaxf(fabsf(v), 1e-4f));
}

// fused cov2cor + channel mixing; outputs bf16 hi/lo pairs (validated, frozen)
__global__ __launch_bounds__(256, 1) void k_mix(const float* __restrict__ inp,
                                                const float* __restrict__ wq,
                                                const float* __restrict__ wk){
    __shared__ float sWQ[C_B*C_B], sWK[C_B*C_B], sX[8*D_B], sRV[8*D_B];
    int tid = threadIdx.x, n = blockIdx.y, irow = blockIdx.x;
    for (int i = tid; i < C_B*C_B; i += 256){ sWQ[i] = wq[i]; sWK[i] = wk[i]; }
    int tx = tid & 31, ty = tid >> 5, k0 = ty*8;
    u64 aQ[4][4], aK[4][4];
    #pragma unroll
    for (int p = 0; p < 4; p++)
        #pragma unroll
        for (int q = 0; q < 4; q++){ aQ[p][q] = 0ull; aK[p][q] = 0ull; }
    __syncthreads();
    for (int cc = 0; cc < C_B; cc += 8){
        {
            int idx = tid*4, cl = idx >> 7, j = idx & 127;
            *(float4*)&sRV[idx] = *(const float4*)&g_rv[((size_t)(n*C_B + cc + cl))*D_B + j];
        }
        __syncthreads();
        {
            int cl = tid >> 5, jj = (tid & 31)*4;
            float4 v = *(const float4*)&inp[((size_t)(n*C_B + cc + cl))*MAT + irow*D_B + jj];
            float ri = sRV[cl*D_B + irow];
            v.x = clip1(v.x*ri*sRV[cl*D_B + jj+0]); v.y = clip1(v.y*ri*sRV[cl*D_B + jj+1]);
            v.z = clip1(v.z*ri*sRV[cl*D_B + jj+2]); v.w = clip1(v.w*ri*sRV[cl*D_B + jj+3]);
            *(float4*)&sX[cl*D_B + jj] = v;
        }
        __syncthreads();
        #pragma unroll
        for (int cl = 0; cl < 8; cl++){
            int c = cc + cl;
            float4 xv = *(const float4*)&sX[cl*D_B + tx*4];
            u64 xx[4] = { bcast2(xv.x), bcast2(xv.y), bcast2(xv.z), bcast2(xv.w) };
            F4U q0, q1, kk0, kk1;
            q0.f = *(const float4*)&sWQ[c*C_B + k0];  q1.f = *(const float4*)&sWQ[c*C_B + k0 + 4];
            kk0.f = *(const float4*)&sWK[c*C_B + k0]; kk1.f = *(const float4*)&sWK[c*C_B + k0 + 4];
            u64 bq[4] = { q0.u[0], q0.u[1], q1.u[0], q1.u[1] };
            u64 bk[4] = { kk0.u[0], kk0.u[1], kk1.u[0], kk1.u[1] };
            #pragma unroll
            for (int p = 0; p < 4; p++)
                #pragma unroll
                for (int q = 0; q < 4; q++){
                    aQ[p][q] = ffma2(xx[p], bq[q], aQ[p][q]);
                    aK[p][q] = ffma2(xx[p], bk[q], aK[p][q]);
                }
        }
        __syncthreads();
    }
    #pragma unroll
    for (int q = 0; q < 4; q++)
        #pragma unroll
        for (int h = 0; h < 2; h++){
            int k = k0 + q*2 + h;
            float vq[4], vk[4];
            #pragma unroll
            for (int p = 0; p < 4; p++){
                float lo, hi;
                unpack2(aQ[p][q], lo, hi); vq[p] = h ? hi : lo;
                unpack2(aK[p][q], lo, hi); vk[p] = h ? hi : lo;
            }
            size_t base = ((size_t)(n*C_B + k))*MAT + irow*D_B + tx*4;
            u32 l0, l1;
            u32 h0 = split2(vq[0], vq[1], l0), h1 = split2(vq[2], vq[3], l1);
            *(uint2*)&g_Qh[base] = make_uint2(h0, h1);
            *(uint2*)&g_Ql[base] = make_uint2(l0, l1);
            h0 = split2(vk[0], vk[1], l0); h1 = split2(vk[2], vk[3], l1);
            *(uint2*)&g_Kh[base] = make_uint2(h0, h1);
            *(uint2*)&g_Kl[base] = make_uint2(l0, l1);
        }
}

// ============================================================================
// k_attn: PERSISTENT. mm1/mm2 bf16 split-2; mm3/mm4 fp16 single-product.
// Buffer lifetimes (per iteration):
//   B0: Q(i) [dead after mm1] -> prefetch Q(i+1)
//   B1: K(i) [dead after mm2] -> prefetch K(i+1)
//   B2: St hi/lo -> e~ (fp16, over St.hi); X'''/P (fp16, over St.lo at +TILEB)
// X''' built from direct gmem LDG (inp re-read in epilogue is L2-hot).
// ============================================================================
__global__ __launch_bounds__(TPB, 1) void k_attn(const float* __restrict__ inp,
                                                 const float* __restrict__ lam,
                                                 float* __restrict__ out){
    extern __shared__ char smc[];
    u32 sb = smem_u32(smc);
    u32 B0 = sb, B1 = sb + SBYTES, B2 = sb + 2*SBYTES;
    u32 B2t = B2 + TILEB;                      // St.lo -> X''' -> P
    __shared__ float s_rv[D_B], s_sr[D_B], s_dia[D_B], s_part[D_B][4], s_red[12];
    int tid = threadIdx.x, w = tid >> 5, l = tid & 31;
    int wm = w >> 2, wn = w & 3;
    int r0 = l >> 2, c0 = (l & 3)*2;
    int stride = gridDim.x;

    // prime first iteration's Q/K
    {
        size_t gb0 = (size_t)blockIdx.x * MAT;
        pf_tile(B0,         g_Qh + gb0, tid);
        pf_tile(B0 + TILEB, g_Ql + gb0, tid);
        pf_tile(B1,         g_Kh + gb0, tid);
        pf_tile(B1 + TILEB, g_Kl + gb0, tid);
        cp_commit();
    }

    for (int nk = blockIdx.x; nk < NK_TOT; nk += stride){
        size_t gb = (size_t)nk * MAT;
        int nk2 = nk + stride;
        if (tid < D_B) s_rv[tid] = g_rv[nk*D_B + tid];
        cp_wait0();
        __syncthreads();                       // Q/K ready; prev iter fully done

        float acc[4][4][4];
        wmm(B0, B1, 1, 1, wm, wn, l, acc);     // St = Q^T K
        store_acc(smc, B2 - sb, wm, wn, l, acc, 0);
        __syncthreads();                       // St ready; all warps past mm1 (B0 dead)

        if (nk2 < NK_TOT){                     // prefetch Q(i+1) during mm2..epilogue
            size_t gn = (size_t)nk2 * MAT;
            pf_tile(B0,         g_Qh + gn, tid);
            pf_tile(B0 + TILEB, g_Ql + gn, tid);
            cp_commit();
        }

        wmm(B2, B1, 1, 1, wm, wn, l, acc);     // Apre = St^T K
        // block max
        float mx = -3.4e38f;
        #pragma unroll
        for (int mt = 0; mt < 4; mt++)
            #pragma unroll
            for (int nt = 0; nt < 4; nt++)
                #pragma unroll
                for (int q = 0; q < 4; q++) mx = fmaxf(mx, acc[mt][nt][q]);
        #pragma unroll
        for (int o = 16; o; o >>= 1) mx = fmaxf(mx, __shfl_xor_sync(0xffffffffu, mx, o));
        if (l == 0) s_red[w] = mx;
        __syncthreads();                       // all warps past mm2 (B1 dead)
        if (tid == 0){
            float m2 = s_red[0];
            #pragma unroll
            for (int q = 1; q < 8; q++) m2 = fmaxf(m2, s_red[q]);
            s_red[8] = m2;
        }
        if (nk2 < NK_TOT){                     // prefetch K(i+1) during softmax..epilogue
            size_t gn = (size_t)nk2 * MAT;
            pf_tile(B1,         g_Kh + gn, tid);
            pf_tile(B1 + TILEB, g_Kl + gn, tid);
            cp_commit();
        }
        __syncthreads();
        float bmax = s_red[8];
        {   // exp (all-poly, fma pipe) in place + row partial sums
            const u64 kL2E = bcast2(1.4426950408889634f), kMAG = bcast2(12582912.0f),
                      kNMAG = bcast2(-12582912.0f), kN1 = bcast2(-1.0f),
                      kC5 = bcast2(1.3333558146e-3f), kC4 = bcast2(9.6181291076e-3f),
                      kC3 = bcast2(5.5504108664e-2f), kC2 = bcast2(2.4022650695e-1f),
                      kC1 = bcast2(6.9314718055e-1f), kONE = bcast2(1.0f),
                      kNB = bcast2(-bmax);
            float part[4][2] = {};
            #pragma unroll
            for (int mt = 0; mt < 4; mt++)
                #pragma unroll
                for (int nt = 0; nt < 4; nt++){
                    u64 p0 = exp_pair(add2(pack2(acc[mt][nt][0], acc[mt][nt][1]), kNB),
                                      kL2E,kMAG,kNMAG,kN1,kC5,kC4,kC3,kC2,kC1,kONE);
                    u64 p1 = exp_pair(add2(pack2(acc[mt][nt][2], acc[mt][nt][3]), kNB),
                                      kL2E,kMAG,kNMAG,kN1,kC5,kC4,kC3,kC2,kC1,kONE);
                    unpack2(p0, acc[mt][nt][0], acc[mt][nt][1]);
                    unpack2(p1, acc[mt][nt][2], acc[mt][nt][3]);
                    part[mt][0] += acc[mt][nt][0] + acc[mt][nt][1];
                    part[mt][1] += acc[mt][nt][2] + acc[mt][nt][3];
                }
            #pragma unroll
            for (int mt = 0; mt < 4; mt++)
                #pragma unroll
                for (int h = 0; h < 2; h++){
                    float t = part[mt][h];
                    t += __shfl_xor_sync(0xffffffffu, t, 1);
                    t += __shfl_xor_sync(0xffffffffu, t, 2);
                    if ((l & 3) == 0) s_part[wm*64 + mt*16 + h*8 + r0][wn] = t;
                }
        }
        // X''' = clip(inp*rv_i*rv_j) straight from gmem -> B2t (fp16 single)
        for (int e = tid; e < 4096; e += TPB){
            int i = e >> 5, j = (e & 31)*4;
            float4 v = *(const float4*)&inp[gb + i*128 + j];
            float ri = s_rv[i];
            v.x = clip1(v.x*ri*s_rv[j+0]); v.y = clip1(v.y*ri*s_rv[j+1]);
            v.z = clip1(v.z*ri*s_rv[j+2]); v.w = clip1(v.w*ri*s_rv[j+3]);
            u32 off = (B2t - sb) + (u32)((i*SSTR + j)*2);
            *(u32*)(smc + off)     = cvt2h(v.x, v.y);
            *(u32*)(smc + off + 4) = cvt2h(v.z, v.w);
        }
        if (tid < D_B){
            // s_part written under the preceding sync pair; safe to read after next sync
        }
        __syncthreads();
        if (tid < D_B)
            s_dia[tid] = s_part[tid][0] + s_part[tid][1] + s_part[tid][2] + s_part[tid][3];
        __syncthreads();
        if (tid < 32){
            float t = s_dia[tid] + s_dia[tid+32] + s_dia[tid+64] + s_dia[tid+96];
            #pragma unroll
            for (int o = 16; o; o >>= 1) t += __shfl_xor_sync(0xffffffffu, t, o);
            if (tid == 0) s_red[9] = t;
        }
        __syncthreads();
        if (tid < D_B){
            float d = fmaxf(fmaxf(s_dia[tid], s_red[9]/100000.0f), 1e-5f);
            s_sr[tid] = rsqrtf(d);
        }
        __syncthreads();
        store_acc_h(smc, B2 - sb, wm, wn, l, acc, s_sr, 1.0f);  // e~ (over St.hi)
        __syncthreads();

        wmm_h(B2, B2t, 0, 1, wm, wn, l, acc);            // P = e~ X'''
        __syncthreads();                                 // all warps done reading X'''
        store_acc_h(smc, B2t - sb, wm, wn, l, acc, 0, PSCL);  // P/32 (over X''')
        __syncthreads();

        wmm_h(B2t, B2, 0, 0, wm, wn, l, acc);            // O = (P/32) e~^T
        {   // epilogue: out = inp + lam*32*sr_i*sr_j*O   (inp L2-hot)
            float lamv = lam[nk & (C_B - 1)] * PSCLI;
            #pragma unroll
            for (int mt = 0; mt < 4; mt++)
                #pragma unroll
                for (int nt = 0; nt < 4; nt++){
                    int row = wm*64 + mt*16 + r0, col = wn*32 + nt*8 + c0;
                    float sc0 = s_sr[col], sc1 = s_sr[col+1];
                    #pragma unroll
                    for (int h = 0; h < 2; h++){
                        int rr = row + h*8;
                        float li = lamv * s_sr[rr];
                        float2 iv = *(const float2*)&inp[gb + rr*128 + col];
                        float2 o;
                        o.x = iv.x + li*sc0*acc[mt][nt][h*2+0];
                        o.y = iv.y + li*sc1*acc[mt][nt][h*2+1];
                        *(float2*)&out[gb + rr*128 + col] = o;
                    }
                }
        }
    }
}

// ============================================================================
extern "C" void kernel_launch(void* const* d_in, const int* in_sizes, int n_in,
                              void* d_out, int out_size){
    const float* inp = (const float*)d_in[0];
    const float* wq  = (const float*)d_in[1];
    const float* wk  = (const float*)d_in[2];
    const float* lam = (const float*)d_in[3];
    float* out = (float*)d_out;

    int nsm = 148;
    cudaDeviceGetAttribute(&nsm, cudaDevAttrMultiProcessorCount, 0);
    if (nsm <= 0 || nsm > NK_TOT) nsm = 148;

    cudaFuncSetAttribute(k_attn, cudaFuncAttributeMaxDynamicSharedMemorySize, DSM);

    k_rinv<<<NK_TOT, D_B>>>(inp);
    k_mix<<<dim3(D_B, N_B), 256>>>(inp, wq, wk);
    k_attn<<<nsm, TPB, DSM>>>(inp, lam, out);
}

// round 13
// speedup vs baseline: 2.1630x; 1.0669x over previous
#include <cuda_runtime.h>
#include <cuda_bf16.h>

#define N_B 32
#define C_B 64
#define D_B 128
#define MAT 16384
#define NK_TOT 2048
#define TPB 256

// bf16/fp16 tile geometry for k_attn
#define SSTR 136                 // halves per row (272B, conflict-free for ldmatrix)
#define TILEB 34816              // one 128x136 b16 tile
#define SBYTES 69632             // hi+lo pair
#define DSM (3*SBYTES)           // 208896 B dynamic smem
#define PSCL 0.03125f            // P storage scale (overflow guard)
#define PSCLI 32.0f

typedef unsigned long long u64;
typedef unsigned int u32;
typedef unsigned short u16;

__device__ float g_rv[NK_TOT*D_B];
// Q/K pre-split to bf16 hi/lo by k_mix (same total bytes as fp32)
__device__ u16 g_Qh[NK_TOT*MAT], g_Ql[NK_TOT*MAT];
__device__ u16 g_Kh[NK_TOT*MAT], g_Kl[NK_TOT*MAT];

// ---------- f32x2 helpers ----------
__device__ __forceinline__ u64 bcast2(float x){
    u64 r; asm("mov.b64 %0, {%1, %1};" : "=l"(r) : "r"(__float_as_uint(x))); return r;
}
__device__ __forceinline__ u64 pack2(float a, float b){
    u64 r; asm("mov.b64 %0, {%1, %2};" : "=l"(r) : "r"(__float_as_uint(a)), "r"(__float_as_uint(b))); return r;
}
__device__ __forceinline__ u64 ffma2(u64 a, u64 b, u64 c){
    u64 d; asm("fma.rn.f32x2 %0, %1, %2, %3;" : "=l"(d) : "l"(a), "l"(b), "l"(c)); return d;
}
__device__ __forceinline__ u64 add2(u64 a, u64 b){
    u64 d; asm("add.rn.f32x2 %0, %1, %2;" : "=l"(d) : "l"(a), "l"(b)); return d;
}
__device__ __forceinline__ u64 mul2(u64 a, u64 b){
    u64 d; asm("mul.rn.f32x2 %0, %1, %2;" : "=l"(d) : "l"(a), "l"(b)); return d;
}
__device__ __forceinline__ void unpack2(u64 v, float& lo, float& hi){
    u32 a, b; asm("mov.b64 {%0, %1}, %2;" : "=r"(a), "=r"(b) : "l"(v));
    lo = __uint_as_float(a); hi = __uint_as_float(b);
}
__device__ __forceinline__ void unpack2u(u64 v, u32& a, u32& b){
    asm("mov.b64 {%0, %1}, %2;" : "=r"(a), "=r"(b) : "l"(v));
}
union F4U { float4 f; u64 u[2]; };
__device__ __forceinline__ float clip1(float x){ return fminf(1.f, fmaxf(-1.f, x)); }

// fma-pipe exp (magic rounding + deg-5 Taylor), underflow-clamped
__device__ __forceinline__ u64 exp_pair(u64 xb, u64 kL2E, u64 kMAG, u64 kNMAG, u64 kN1,
                                        u64 kC5, u64 kC4, u64 kC3, u64 kC2, u64 kC1, u64 kONE){
    u64 y = mul2(xb, kL2E);
    u64 z = add2(y, kMAG);
    u64 t = add2(z, kNMAG);
    u64 f = ffma2(t, kN1, y);
    u64 p = ffma2(kC5, f, kC4);
    p = ffma2(p, f, kC3); p = ffma2(p, f, kC2); p = ffma2(p, f, kC1); p = ffma2(p, f, kONE);
    u32 zl, zh; unpack2u(z, zl, zh);
    int n0 = max((int)(zl - 0x4B400000u), -127), n1 = max((int)(zh - 0x4B400000u), -127);
    u64 s; asm("mov.b64 %0, {%1, %2};" : "=l"(s)
               : "r"((u32)(n0 + 127) << 23), "r"((u32)(n1 + 127) << 23));
    return mul2(p, s);
}

// ---------- async / mma primitives (arch-generic, sm_80+) ----------
__device__ __forceinline__ void cp16(u32 s, const void* g){
    asm volatile("cp.async.cg.shared.global [%0], [%1], 16;" :: "r"(s), "l"(g));
}
__device__ __forceinline__ void cp_commit(){ asm volatile("cp.async.commit_group;"); }
__device__ __forceinline__ void cp_wait0(){ asm volatile("cp.async.wait_group 0;"); }
__device__ __forceinline__ void cp_wait1(){ asm volatile("cp.async.wait_group 1;"); }
__device__ __forceinline__ u32 smem_u32(const void* p){
    u32 a; asm("{ .reg .u64 t; cvta.to.shared.u64 t, %1; cvt.u32.u64 %0, t; }" : "=r"(a) : "l"(p));
    return a;
}
__device__ __forceinline__ void ldsm4(u32 a, u32* r){
    asm volatile("ldmatrix.sync.aligned.m8n8.x4.shared.b16 {%0,%1,%2,%3}, [%4];"
        : "=r"(r[0]), "=r"(r[1]), "=r"(r[2]), "=r"(r[3]) : "r"(a));
}
__device__ __forceinline__ void ldsm4t(u32 a, u32* r){
    asm volatile("ldmatrix.sync.aligned.m8n8.x4.trans.shared.b16 {%0,%1,%2,%3}, [%4];"
        : "=r"(r[0]), "=r"(r[1]), "=r"(r[2]), "=r"(r[3]) : "r"(a));
}
__device__ __forceinline__ void ldsm2(u32 a, u32* r){
    asm volatile("ldmatrix.sync.aligned.m8n8.x2.shared.b16 {%0,%1}, [%2];"
        : "=r"(r[0]), "=r"(r[1]) : "r"(a));
}
__device__ __forceinline__ void ldsm2t(u32 a, u32* r){
    asm volatile("ldmatrix.sync.aligned.m8n8.x2.trans.shared.b16 {%0,%1}, [%2];"
        : "=r"(r[0]), "=r"(r[1]) : "r"(a));
}
__device__ __forceinline__ void mmab(float* d, const u32* a, const u32* b){
    asm volatile("mma.sync.aligned.m16n8k16.row.col.f32.bf16.bf16.f32 "
        "{%0,%1,%2,%3},{%4,%5,%6,%7},{%8,%9},{%0,%1,%2,%3};"
        : "+f"(d[0]), "+f"(d[1]), "+f"(d[2]), "+f"(d[3])
        : "r"(a[0]), "r"(a[1]), "r"(a[2]), "r"(a[3]), "r"(b[0]), "r"(b[1]));
}
__device__ __forceinline__ void mmah(float* d, const u32* a, const u32* b){
    asm volatile("mma.sync.aligned.m16n8k16.row.col.f32.f16.f16.f32 "
        "{%0,%1,%2,%3},{%4,%5,%6,%7},{%8,%9},{%0,%1,%2,%3};"
        : "+f"(d[0]), "+f"(d[1]), "+f"(d[2]), "+f"(d[3])
        : "r"(a[0]), "r"(a[1]), "r"(a[2]), "r"(a[3]), "r"(b[0]), "r"(b[1]));
}
// pack two floats to bf16x2 (first arg in low half)
__device__ __forceinline__ u32 cvt2bf(float lo, float hi){
    u32 r; asm("cvt.rn.bf16x2.f32 %0, %1, %2;" : "=r"(r) : "f"(hi), "f"(lo)); return r;
}
// pack two floats to f16x2 (first arg in low half)
__device__ __forceinline__ u32 cvt2h(float lo, float hi){
    u32 r; asm("cvt.rn.f16x2.f32 %0, %1, %2;" : "=r"(r) : "f"(hi), "f"(lo)); return r;
}
// split-2: returns hi-pair; lo residual pair via out param
__device__ __forceinline__ u32 split2(float v0, float v1, u32& lopair){
    u32 hp = cvt2bf(v0, v1);
    float h0 = __uint_as_float(hp << 16);
    float h1 = __uint_as_float(hp & 0xffff0000u);
    lopair = cvt2bf(v0 - h0, v1 - h1);
    return hp;
}

// warp-tile split-2 bf16 matmul: acc = (Ah+Al)(Bh+Bl) minus Al*Bl (3 products).
__device__ __forceinline__ void wmm(u32 aB, u32 bB, int am, int bm,
                                    int wm, int wn, int l, float acc[4][4][4]){
    #pragma unroll
    for (int mt = 0; mt < 4; mt++)
        #pragma unroll
        for (int nt = 0; nt < 4; nt++)
            #pragma unroll
            for (int q = 0; q < 4; q++) acc[mt][nt][q] = 0.f;
    #pragma unroll
    for (int ks = 0; ks < 8; ks++){
        int k0 = ks*16;
        u32 Ah[4][4], Al[4][4], Bh[4][2], Bl[4][2];
        #pragma unroll
        for (int mt = 0; mt < 4; mt++){
            int i0 = wm*64 + mt*16;
            u32 ad;
            if (am == 0) ad = aB + (u32)(((i0 + (l&7) + ((l>>3)&1)*8)*SSTR + k0 + (l>>4)*8)*2);
            else         ad = aB + (u32)(((k0 + (l>>4)*8 + (l&7))*SSTR + i0 + ((l>>3)&1)*8)*2);
            if (am == 0){ ldsm4(ad, Ah[mt]);  ldsm4(ad + TILEB, Al[mt]); }
            else        { ldsm4t(ad, Ah[mt]); ldsm4t(ad + TILEB, Al[mt]); }
        }
        #pragma unroll
        for (int nt = 0; nt < 4; nt++){
            int j0 = wn*32 + nt*8;
            u32 bd;
            if (bm == 0) bd = bB + (u32)(((j0 + (l&7))*SSTR + k0 + ((l>>3)&1)*8)*2);
            else         bd = bB + (u32)(((k0 + (l&15))*SSTR + j0)*2);
            if (bm == 0){ ldsm2(bd, Bh[nt]);  ldsm2(bd + TILEB, Bl[nt]); }
            else        { ldsm2t(bd, Bh[nt]); ldsm2t(bd + TILEB, Bl[nt]); }
        }
        #pragma unroll
        for (int mt = 0; mt < 4; mt++)
            #pragma unroll
            for (int nt = 0; nt < 4; nt++){
                mmab(acc[mt][nt], Ah[mt], Bh[nt]);
                mmab(acc[mt][nt], Ah[mt], Bl[nt]);
                mmab(acc[mt][nt], Al[mt], Bh[nt]);
            }
    }
}

// warp-tile single-product fp16 matmul (relative-error path: P, O)
__device__ __forceinline__ void wmm_h(u32 aB, u32 bB, int am, int bm,
                                      int wm, int wn, int l, float acc[4][4][4]){
    #pragma unroll
    for (int mt = 0; mt < 4; mt++)
        #pragma unroll
        for (int nt = 0; nt < 4; nt++)
            #pragma unroll
            for (int q = 0; q < 4; q++) acc[mt][nt][q] = 0.f;
    #pragma unroll
    for (int ks = 0; ks < 8; ks++){
        int k0 = ks*16;
        u32 Ah[4][4], Bh[4][2];
        #pragma unroll
        for (int mt = 0; mt < 4; mt++){
            int i0 = wm*64 + mt*16;
            u32 ad;
            if (am == 0) ad = aB + (u32)(((i0 + (l&7) + ((l>>3)&1)*8)*SSTR + k0 + (l>>4)*8)*2);
            else         ad = aB + (u32)(((k0 + (l>>4)*8 + (l&7))*SSTR + i0 + ((l>>3)&1)*8)*2);
            if (am == 0) ldsm4(ad, Ah[mt]);
            else         ldsm4t(ad, Ah[mt]);
        }
        #pragma unroll
        for (int nt = 0; nt < 4; nt++){
            int j0 = wn*32 + nt*8;
            u32 bd;
            if (bm == 0) bd = bB + (u32)(((j0 + (l&7))*SSTR + k0 + ((l>>3)&1)*8)*2);
            else         bd = bB + (u32)(((k0 + (l&15))*SSTR + j0)*2);
            if (bm == 0) ldsm2(bd, Bh[nt]);
            else         ldsm2t(bd, Bh[nt]);
        }
        #pragma unroll
        for (int mt = 0; mt < 4; mt++)
            #pragma unroll
            for (int nt = 0; nt < 4; nt++)
                mmah(acc[mt][nt], Ah[mt], Bh[nt]);
    }
}

// store warp acc -> bf16 hi/lo tile (split-2), optional per-column scale
__device__ __forceinline__ void store_acc(char* smc, u32 dstOff, int wm, int wn, int l,
                                          float acc[4][4][4], const float* colscale){
    int r0 = l >> 2, c0 = (l & 3)*2;
    #pragma unroll
    for (int mt = 0; mt < 4; mt++)
        #pragma unroll
        for (int nt = 0; nt < 4; nt++){
            int row = wm*64 + mt*16 + r0, col = wn*32 + nt*8 + c0;
            float s0 = 1.f, s1 = 1.f;
            if (colscale){ s0 = colscale[col]; s1 = colscale[col+1]; }
            #pragma unroll
            for (int h = 0; h < 2; h++){
                float v0 = acc[mt][nt][h*2] * s0, v1 = acc[mt][nt][h*2+1] * s1;
                u32 lp, hp = split2(v0, v1, lp);
                u32 off = dstOff + (u32)((((row + h*8)*SSTR) + col)*2);
                *(u32*)(smc + off) = hp;
                *(u32*)(smc + off + TILEB) = lp;
            }
        }
}

// store warp acc -> single fp16 tile, optional per-column scale + global scale
__device__ __forceinline__ void store_acc_h(char* smc, u32 dstOff, int wm, int wn, int l,
                                            float acc[4][4][4], const float* colscale,
                                            float gs){
    int r0 = l >> 2, c0 = (l & 3)*2;
    #pragma unroll
    for (int mt = 0; mt < 4; mt++)
        #pragma unroll
        for (int nt = 0; nt < 4; nt++){
            int row = wm*64 + mt*16 + r0, col = wn*32 + nt*8 + c0;
            float s0 = gs, s1 = gs;
            if (colscale){ s0 *= colscale[col]; s1 *= colscale[col+1]; }
            #pragma unroll
            for (int h = 0; h < 2; h++){
                u32 hp = cvt2h(acc[mt][nt][h*2] * s0, acc[mt][nt][h*2+1] * s1);
                *(u32*)(smc + dstOff + (u32)((((row + h*8)*SSTR) + col)*2)) = hp;
            }
        }
}

// cp.async one pre-split tensor (hi or lo) into a tile region
__device__ __forceinline__ void pf_tile(u32 dst, const u16* __restrict__ src, int tid){
    for (int g = tid; g < 2048; g += TPB){
        int m = g >> 4, c = (g & 15)*8;
        cp16(dst + (u32)((m*SSTR + c)*2), src + m*128 + c);
    }
}

// ============================================================================
__global__ void k_rinv(const float* __restrict__ in){
    int nk = blockIdx.x, t = threadIdx.x;
    float v = in[(size_t)nk*MAT + t*D_B + t];
    g_rv[nk*D_B + t] = rsqrtf(fmaxf(fabsf(v), 1e-4f));
}

// fused cov2cor + channel mixing; cp.async double-buffered staging.
// Outputs bf16 hi/lo pairs. Arithmetic identical to prior rounds.
__global__ __launch_bounds__(256, 1) void k_mix(const float* __restrict__ inp,
                                                const float* __restrict__ wq,
                                                const float* __restrict__ wk){
    __shared__ float sWQ[C_B*C_B], sWK[C_B*C_B];
    __shared__ float sX [2][8*D_B];
    __shared__ float sRV[2][8*D_B];
    int tid = threadIdx.x, n = blockIdx.y, irow = blockIdx.x;
    int tx = tid & 31, ty = tid >> 5, k0 = ty*8;
    u32 sxA[2] = { smem_u32(&sX[0][0]),  smem_u32(&sX[1][0])  };
    u32 rvA[2] = { smem_u32(&sRV[0][0]), smem_u32(&sRV[1][0]) };

    // issue block 0 loads (raw inp rows + rv rows), then load W synchronously
    {
        int cl = tid >> 5, jj = (tid & 31)*4;
        cp16(sxA[0] + (u32)((cl*D_B + jj)*4),
             inp + ((size_t)(n*C_B + cl))*MAT + irow*D_B + jj);
        int idx = tid*4, cl2 = idx >> 7, j2 = idx & 127;
        cp16(rvA[0] + (u32)(idx*4), g_rv + ((size_t)(n*C_B + cl2))*D_B + j2);
        cp_commit();
    }
    for (int i = tid; i < C_B*C_B; i += 256){ sWQ[i] = wq[i]; sWK[i] = wk[i]; }

    u64 aQ[4][4], aK[4][4];
    #pragma unroll
    for (int p = 0; p < 4; p++)
        #pragma unroll
        for (int q = 0; q < 4; q++){ aQ[p][q] = 0ull; aK[p][q] = 0ull; }

    for (int cb = 0; cb < 8; cb++){
        int cur = cb & 1, cc = cb*8;
        if (cb < 7){   // issue block cb+1 into the other buffer
            int nb = cur ^ 1, ncc = cc + 8;
            int cl = tid >> 5, jj = (tid & 31)*4;
            cp16(sxA[nb] + (u32)((cl*D_B + jj)*4),
                 inp + ((size_t)(n*C_B + ncc + cl))*MAT + irow*D_B + jj);
            int idx = tid*4, cl2 = idx >> 7, j2 = idx & 127;
            cp16(rvA[nb] + (u32)(idx*4), g_rv + ((size_t)(n*C_B + ncc + cl2))*D_B + j2);
            cp_commit();
            cp_wait1();                        // block cb landed
        } else {
            cp_wait0();
        }
        __syncthreads();
        {   // in-smem cov2cor transform (same expression/order as before)
            int cl = tid >> 5, jj = (tid & 31)*4;
            float4 v = *(float4*)&sX[cur][cl*D_B + jj];
            float ri = sRV[cur][cl*D_B + irow];
            v.x = clip1(v.x*ri*sRV[cur][cl*D_B + jj+0]);
            v.y = clip1(v.y*ri*sRV[cur][cl*D_B + jj+1]);
            v.z = clip1(v.z*ri*sRV[cur][cl*D_B + jj+2]);
            v.w = clip1(v.w*ri*sRV[cur][cl*D_B + jj+3]);
            *(float4*)&sX[cur][cl*D_B + jj] = v;
        }
        __syncthreads();
        #pragma unroll
        for (int cl = 0; cl < 8; cl++){
            int c = cc + cl;
            float4 xv = *(const float4*)&sX[cur][cl*D_B + tx*4];
            u64 xx[4] = { bcast2(xv.x), bcast2(xv.y), bcast2(xv.z), bcast2(xv.w) };
            F4U q0, q1, kk0, kk1;
            q0.f = *(const float4*)&sWQ[c*C_B + k0];  q1.f = *(const float4*)&sWQ[c*C_B + k0 + 4];
            kk0.f = *(const float4*)&sWK[c*C_B + k0]; kk1.f = *(const float4*)&sWK[c*C_B + k0 + 4];
            u64 bq[4] = { q0.u[0], q0.u[1], q1.u[0], q1.u[1] };
            u64 bk[4] = { kk0.u[0], kk0.u[1], kk1.u[0], kk1.u[1] };
            #pragma unroll
            for (int p = 0; p < 4; p++)
                #pragma unroll
                for (int q = 0; q < 4; q++){
                    aQ[p][q] = ffma2(xx[p], bq[q], aQ[p][q]);
                    aK[p][q] = ffma2(xx[p], bk[q], aK[p][q]);
                }
        }
        __syncthreads();                       // compute done before reusing cur buffer
    }
    #pragma unroll
    for (int q = 0; q < 4; q++)
        #pragma unroll
        for (int h = 0; h < 2; h++){
            int k = k0 + q*2 + h;
            float vq[4], vk[4];
            #pragma unroll
            for (int p = 0; p < 4; p++){
                float lo, hi;
                unpack2(aQ[p][q], lo, hi); vq[p] = h ? hi : lo;
                unpack2(aK[p][q], lo, hi); vk[p] = h ? hi : lo;
            }
            size_t base = ((size_t)(n*C_B + k))*MAT + irow*D_B + tx*4;
            u32 l0, l1;
            u32 h0 = split2(vq[0], vq[1], l0), h1 = split2(vq[2], vq[3], l1);
            *(uint2*)&g_Qh[base] = make_uint2(h0, h1);
            *(uint2*)&g_Ql[base] = make_uint2(l0, l1);
            h0 = split2(vk[0], vk[1], l0); h1 = split2(vk[2], vk[3], l1);
            *(uint2*)&g_Kh[base] = make_uint2(h0, h1);
            *(uint2*)&g_Kl[base] = make_uint2(l0, l1);
        }
}

// ============================================================================
// k_attn: PERSISTENT (frozen from round 12). mm1/mm2 bf16 split-2;
// mm3/mm4 fp16 single-product.
// ============================================================================
__global__ __launch_bounds__(TPB, 1) void k_attn(const float* __restrict__ inp,
                                                 const float* __restrict__ lam,
                                                 float* __restrict__ out){
    extern __shared__ char smc[];
    u32 sb = smem_u32(smc);
    u32 B0 = sb, B1 = sb + SBYTES, B2 = sb + 2*SBYTES;
    u32 B2t = B2 + TILEB;                      // St.lo -> X''' -> P
    __shared__ float s_rv[D_B], s_sr[D_B], s_dia[D_B], s_part[D_B][4], s_red[12];
    int tid = threadIdx.x, w = tid >> 5, l = tid & 31;
    int wm = w >> 2, wn = w & 3;
    int r0 = l >> 2, c0 = (l & 3)*2;
    int stride = gridDim.x;

    {
        size_t gb0 = (size_t)blockIdx.x * MAT;
        pf_tile(B0,         g_Qh + gb0, tid);
        pf_tile(B0 + TILEB, g_Ql + gb0, tid);
        pf_tile(B1,         g_Kh + gb0, tid);
        pf_tile(B1 + TILEB, g_Kl + gb0, tid);
        cp_commit();
    }

    for (int nk = blockIdx.x; nk < NK_TOT; nk += stride){
        size_t gb = (size_t)nk * MAT;
        int nk2 = nk + stride;
        if (tid < D_B) s_rv[tid] = g_rv[nk*D_B + tid];
        cp_wait0();
        __syncthreads();

        float acc[4][4][4];
        wmm(B0, B1, 1, 1, wm, wn, l, acc);     // St = Q^T K
        store_acc(smc, B2 - sb, wm, wn, l, acc, 0);
        __syncthreads();

        if (nk2 < NK_TOT){
            size_t gn = (size_t)nk2 * MAT;
            pf_tile(B0,         g_Qh + gn, tid);
            pf_tile(B0 + TILEB, g_Ql + gn, tid);
            cp_commit();
        }

        wmm(B2, B1, 1, 1, wm, wn, l, acc);     // Apre = St^T K
        float mx = -3.4e38f;
        #pragma unroll
        for (int mt = 0; mt < 4; mt++)
            #pragma unroll
            for (int nt = 0; nt < 4; nt++)
                #pragma unroll
                for (int q = 0; q < 4; q++) mx = fmaxf(mx, acc[mt][nt][q]);
        #pragma unroll
        for (int o = 16; o; o >>= 1) mx = fmaxf(mx, __shfl_xor_sync(0xffffffffu, mx, o));
        if (l == 0) s_red[w] = mx;
        __syncthreads();
        if (tid == 0){
            float m2 = s_red[0];
            #pragma unroll
            for (int q = 1; q < 8; q++) m2 = fmaxf(m2, s_red[q]);
            s_red[8] = m2;
        }
        if (nk2 < NK_TOT){
            size_t gn = (size_t)nk2 * MAT;
            pf_tile(B1,         g_Kh + gn, tid);
            pf_tile(B1 + TILEB, g_Kl + gn, tid);
            cp_commit();
        }
        __syncthreads();
        float bmax = s_red[8];
        {   // exp (all-poly, fma pipe) in place + row partial sums
            const u64 kL2E = bcast2(1.4426950408889634f), kMAG = bcast2(12582912.0f),
                      kNMAG = bcast2(-12582912.0f), kN1 = bcast2(-1.0f),
                      kC5 = bcast2(1.3333558146e-3f), kC4 = bcast2(9.6181291076e-3f),
                      kC3 = bcast2(5.5504108664e-2f), kC2 = bcast2(2.4022650695e-1f),
                      kC1 = bcast2(6.9314718055e-1f), kONE = bcast2(1.0f),
                      kNB = bcast2(-bmax);
            float part[4][2] = {};
            #pragma unroll
            for (int mt = 0; mt < 4; mt++)
                #pragma unroll
                for (int nt = 0; nt < 4; nt++){
                    u64 p0 = exp_pair(add2(pack2(acc[mt][nt][0], acc[mt][nt][1]), kNB),
                                      kL2E,kMAG,kNMAG,kN1,kC5,kC4,kC3,kC2,kC1,kONE);
                    u64 p1 = exp_pair(add2(pack2(acc[mt][nt][2], acc[mt][nt][3]), kNB),
                                      kL2E,kMAG,kNMAG,kN1,kC5,kC4,kC3,kC2,kC1,kONE);
                    unpack2(p0, acc[mt][nt][0], acc[mt][nt][1]);
                    unpack2(p1, acc[mt][nt][2], acc[mt][nt][3]);
                    part[mt][0] += acc[mt][nt][0] + acc[mt][nt][1];
                    part[mt][1] += acc[mt][nt][2] + acc[mt][nt][3];
                }
            #pragma unroll
            for (int mt = 0; mt < 4; mt++)
                #pragma unroll
                for (int h = 0; h < 2; h++){
                    float t = part[mt][h];
                    t += __shfl_xor_sync(0xffffffffu, t, 1);
                    t += __shfl_xor_sync(0xffffffffu, t, 2);
                    if ((l & 3) == 0) s_part[wm*64 + mt*16 + h*8 + r0][wn] = t;
                }
        }
        // X''' = clip(inp*rv_i*rv_j) straight from gmem -> B2t (fp16 single)
        for (int e = tid; e < 4096; e += TPB){
            int i = e >> 5, j = (e & 31)*4;
            float4 v = *(const float4*)&inp[gb + i*128 + j];
            float ri = s_rv[i];
            v.x = clip1(v.x*ri*s_rv[j+0]); v.y = clip1(v.y*ri*s_rv[j+1]);
            v.z = clip1(v.z*ri*s_rv[j+2]); v.w = clip1(v.w*ri*s_rv[j+3]);
            u32 off = (B2t - sb) + (u32)((i*SSTR + j)*2);
            *(u32*)(smc + off)     = cvt2h(v.x, v.y);
            *(u32*)(smc + off + 4) = cvt2h(v.z, v.w);
        }
        __syncthreads();
        if (tid < D_B)
            s_dia[tid] = s_part[tid][0] + s_part[tid][1] + s_part[tid][2] + s_part[tid][3];
        __syncthreads();
        if (tid < 32){
            float t = s_dia[tid] + s_dia[tid+32] + s_dia[tid+64] + s_dia[tid+96];
            #pragma unroll
            for (int o = 16; o; o >>= 1) t += __shfl_xor_sync(0xffffffffu, t, o);
            if (tid == 0) s_red[9] = t;
        }
        __syncthreads();
        if (tid < D_B){
            float d = fmaxf(fmaxf(s_dia[tid], s_red[9]/100000.0f), 1e-5f);
            s_sr[tid] = rsqrtf(d);
        }
        __syncthreads();
        store_acc_h(smc, B2 - sb, wm, wn, l, acc, s_sr, 1.0f);  // e~ (over St.hi)
        __syncthreads();

        wmm_h(B2, B2t, 0, 1, wm, wn, l, acc);            // P = e~ X'''
        __syncthreads();
        store_acc_h(smc, B2t - sb, wm, wn, l, acc, 0, PSCL);  // P/32 (over X''')
        __syncthreads();

        wmm_h(B2t, B2, 0, 0, wm, wn, l, acc);            // O = (P/32) e~^T
        {
            float lamv = lam[nk & (C_B - 1)] * PSCLI;
            #pragma unroll
            for (int mt = 0; mt < 4; mt++)
                #pragma unroll
                for (int nt = 0; nt < 4; nt++){
                    int row = wm*64 + mt*16 + r0, col = wn*32 + nt*8 + c0;
                    float sc0 = s_sr[col], sc1 = s_sr[col+1];
                    #pragma unroll
                    for (int h = 0; h < 2; h++){
                        int rr = row + h*8;
                        float li = lamv * s_sr[rr];
                        float2 iv = *(const float2*)&inp[gb + rr*128 + col];
                        float2 o;
                        o.x = iv.x + li*sc0*acc[mt][nt][h*2+0];
                        o.y = iv.y + li*sc1*acc[mt][nt][h*2+1];
                        *(float2*)&out[gb + rr*128 + col] = o;
                    }
                }
        }
    }
}

// ============================================================================
extern "C" void kernel_launch(void* const* d_in, const int* in_sizes, int n_in,
                              void* d_out, int out_size){
    const float* inp = (const float*)d_in[0];
    const float* wq  = (const float*)d_in[1];
    const float* wk  = (const float*)d_in[2];
    const float* lam = (const float*)d_in[3];
    float* out = (float*)d_out;

    int nsm = 148;
    cudaDeviceGetAttribute(&nsm, cudaDevAttrMultiProcessorCount, 0);
    if (nsm <= 0 || nsm > NK_TOT) nsm = 148;

    cudaFuncSetAttribute(k_attn, cudaFuncAttributeMaxDynamicSharedMemorySize, DSM);

    k_rinv<<<NK_TOT, D_B>>>(inp);
    k_mix<<<dim3(D_B, N_B), 256>>>(inp, wq, wk);
    k_attn<<<nsm, TPB, DSM>>>(inp, lam, out);
}

// round 14
// speedup vs baseline: 2.1749x; 1.0055x over previous
#include <cuda_runtime.h>
#include <cuda_bf16.h>

#define N_B 32
#define C_B 64
#define D_B 128
#define MAT 16384
#define NK_TOT 2048
#define TPB 256                  // k_mix threads
#define ATPB 512                 // k_attn threads (16 warps, 4x4 warp grid)

// bf16/fp16 tile geometry for k_attn
#define SSTR 136                 // halves per row (272B, conflict-free for ldmatrix)
#define TILEB 34816              // one 128x136 b16 tile
#define SBYTES 69632             // hi+lo pair
#define DSM (3*SBYTES)           // 208896 B dynamic smem
#define PSCL 0.03125f            // P storage scale (overflow guard)
#define PSCLI 32.0f

typedef unsigned long long u64;
typedef unsigned int u32;
typedef unsigned short u16;

__device__ float g_rv[NK_TOT*D_B];
// Q/K pre-split to bf16 hi/lo by k_mix (same total bytes as fp32)
__device__ u16 g_Qh[NK_TOT*MAT], g_Ql[NK_TOT*MAT];
__device__ u16 g_Kh[NK_TOT*MAT], g_Kl[NK_TOT*MAT];

// ---------- f32x2 helpers ----------
__device__ __forceinline__ u64 bcast2(float x){
    u64 r; asm("mov.b64 %0, {%1, %1};" : "=l"(r) : "r"(__float_as_uint(x))); return r;
}
__device__ __forceinline__ u64 pack2(float a, float b){
    u64 r; asm("mov.b64 %0, {%1, %2};" : "=l"(r) : "r"(__float_as_uint(a)), "r"(__float_as_uint(b))); return r;
}
__device__ __forceinline__ u64 ffma2(u64 a, u64 b, u64 c){
    u64 d; asm("fma.rn.f32x2 %0, %1, %2, %3;" : "=l"(d) : "l"(a), "l"(b), "l"(c)); return d;
}
__device__ __forceinline__ u64 add2(u64 a, u64 b){
    u64 d; asm("add.rn.f32x2 %0, %1, %2;" : "=l"(d) : "l"(a), "l"(b)); return d;
}
__device__ __forceinline__ u64 mul2(u64 a, u64 b){
    u64 d; asm("mul.rn.f32x2 %0, %1, %2;" : "=l"(d) : "l"(a), "l"(b)); return d;
}
__device__ __forceinline__ void unpack2(u64 v, float& lo, float& hi){
    u32 a, b; asm("mov.b64 {%0, %1}, %2;" : "=r"(a), "=r"(b) : "l"(v));
    lo = __uint_as_float(a); hi = __uint_as_float(b);
}
__device__ __forceinline__ void unpack2u(u64 v, u32& a, u32& b){
    asm("mov.b64 {%0, %1}, %2;" : "=r"(a), "=r"(b) : "l"(v));
}
union F4U { float4 f; u64 u[2]; };
__device__ __forceinline__ float clip1(float x){ return fminf(1.f, fmaxf(-1.f, x)); }

// fma-pipe exp (magic rounding + deg-5 Taylor), underflow-clamped
__device__ __forceinline__ u64 exp_pair(u64 xb, u64 kL2E, u64 kMAG, u64 kNMAG, u64 kN1,
                                        u64 kC5, u64 kC4, u64 kC3, u64 kC2, u64 kC1, u64 kONE){
    u64 y = mul2(xb, kL2E);
    u64 z = add2(y, kMAG);
    u64 t = add2(z, kNMAG);
    u64 f = ffma2(t, kN1, y);
    u64 p = ffma2(kC5, f, kC4);
    p = ffma2(p, f, kC3); p = ffma2(p, f, kC2); p = ffma2(p, f, kC1); p = ffma2(p, f, kONE);
    u32 zl, zh; unpack2u(z, zl, zh);
    int n0 = max((int)(zl - 0x4B400000u), -127), n1 = max((int)(zh - 0x4B400000u), -127);
    u64 s; asm("mov.b64 %0, {%1, %2};" : "=l"(s)
               : "r"((u32)(n0 + 127) << 23), "r"((u32)(n1 + 127) << 23));
    return mul2(p, s);
}

// ---------- async / mma primitives (arch-generic, sm_80+) ----------
__device__ __forceinline__ void cp16(u32 s, const void* g){
    asm volatile("cp.async.cg.shared.global [%0], [%1], 16;" :: "r"(s), "l"(g));
}
__device__ __forceinline__ void cp_commit(){ asm volatile("cp.async.commit_group;"); }
__device__ __forceinline__ void cp_wait0(){ asm volatile("cp.async.wait_group 0;"); }
__device__ __forceinline__ void cp_wait1(){ asm volatile("cp.async.wait_group 1;"); }
__device__ __forceinline__ u32 smem_u32(const void* p){
    u32 a; asm("{ .reg .u64 t; cvta.to.shared.u64 t, %1; cvt.u32.u64 %0, t; }" : "=r"(a) : "l"(p));
    return a;
}
__device__ __forceinline__ void ldsm4(u32 a, u32* r){
    asm volatile("ldmatrix.sync.aligned.m8n8.x4.shared.b16 {%0,%1,%2,%3}, [%4];"
        : "=r"(r[0]), "=r"(r[1]), "=r"(r[2]), "=r"(r[3]) : "r"(a));
}
__device__ __forceinline__ void ldsm4t(u32 a, u32* r){
    asm volatile("ldmatrix.sync.aligned.m8n8.x4.trans.shared.b16 {%0,%1,%2,%3}, [%4];"
        : "=r"(r[0]), "=r"(r[1]), "=r"(r[2]), "=r"(r[3]) : "r"(a));
}
__device__ __forceinline__ void ldsm2(u32 a, u32* r){
    asm volatile("ldmatrix.sync.aligned.m8n8.x2.shared.b16 {%0,%1}, [%2];"
        : "=r"(r[0]), "=r"(r[1]) : "r"(a));
}
__device__ __forceinline__ void ldsm2t(u32 a, u32* r){
    asm volatile("ldmatrix.sync.aligned.m8n8.x2.trans.shared.b16 {%0,%1}, [%2];"
        : "=r"(r[0]), "=r"(r[1]) : "r"(a));
}
__device__ __forceinline__ void mmab(float* d, const u32* a, const u32* b){
    asm volatile("mma.sync.aligned.m16n8k16.row.col.f32.bf16.bf16.f32 "
        "{%0,%1,%2,%3},{%4,%5,%6,%7},{%8,%9},{%0,%1,%2,%3};"
        : "+f"(d[0]), "+f"(d[1]), "+f"(d[2]), "+f"(d[3])
        : "r"(a[0]), "r"(a[1]), "r"(a[2]), "r"(a[3]), "r"(b[0]), "r"(b[1]));
}
__device__ __forceinline__ void mmah(float* d, const u32* a, const u32* b){
    asm volatile("mma.sync.aligned.m16n8k16.row.col.f32.f16.f16.f32 "
        "{%0,%1,%2,%3},{%4,%5,%6,%7},{%8,%9},{%0,%1,%2,%3};"
        : "+f"(d[0]), "+f"(d[1]), "+f"(d[2]), "+f"(d[3])
        : "r"(a[0]), "r"(a[1]), "r"(a[2]), "r"(a[3]), "r"(b[0]), "r"(b[1]));
}
// pack two floats to bf16x2 (first arg in low half)
__device__ __forceinline__ u32 cvt2bf(float lo, float hi){
    u32 r; asm("cvt.rn.bf16x2.f32 %0, %1, %2;" : "=r"(r) : "f"(hi), "f"(lo)); return r;
}
// pack two floats to f16x2 (first arg in low half)
__device__ __forceinline__ u32 cvt2h(float lo, float hi){
    u32 r; asm("cvt.rn.f16x2.f32 %0, %1, %2;" : "=r"(r) : "f"(hi), "f"(lo)); return r;
}
// split-2: returns hi-pair; lo residual pair via out param
__device__ __forceinline__ u32 split2(float v0, float v1, u32& lopair){
    u32 hp = cvt2bf(v0, v1);
    float h0 = __uint_as_float(hp << 16);
    float h1 = __uint_as_float(hp & 0xffff0000u);
    lopair = cvt2bf(v0 - h0, v1 - h1);
    return hp;
}

// warp-tile split-2 bf16 matmul, 32x32 warp tile: acc[2][4][4].
// am/bm: 0 = plain row-major fragment, 1 = transposed (ldmatrix.trans).
__device__ __forceinline__ void wmm(u32 aB, u32 bB, int am, int bm,
                                    int wm, int wn, int l, float acc[2][4][4]){
    #pragma unroll
    for (int mt = 0; mt < 2; mt++)
        #pragma unroll
        for (int nt = 0; nt < 4; nt++)
            #pragma unroll
            for (int q = 0; q < 4; q++) acc[mt][nt][q] = 0.f;
    #pragma unroll
    for (int ks = 0; ks < 8; ks++){
        int k0 = ks*16;
        u32 Ah[2][4], Al[2][4], Bh[4][2], Bl[4][2];
        #pragma unroll
        for (int mt = 0; mt < 2; mt++){
            int i0 = wm*32 + mt*16;
            u32 ad;
            if (am == 0) ad = aB + (u32)(((i0 + (l&7) + ((l>>3)&1)*8)*SSTR + k0 + (l>>4)*8)*2);
            else         ad = aB + (u32)(((k0 + (l>>4)*8 + (l&7))*SSTR + i0 + ((l>>3)&1)*8)*2);
            if (am == 0){ ldsm4(ad, Ah[mt]);  ldsm4(ad + TILEB, Al[mt]); }
            else        { ldsm4t(ad, Ah[mt]); ldsm4t(ad + TILEB, Al[mt]); }
        }
        #pragma unroll
        for (int nt = 0; nt < 4; nt++){
            int j0 = wn*32 + nt*8;
            u32 bd;
            if (bm == 0) bd = bB + (u32)(((j0 + (l&7))*SSTR + k0 + ((l>>3)&1)*8)*2);
            else         bd = bB + (u32)(((k0 + (l&15))*SSTR + j0)*2);
            if (bm == 0){ ldsm2(bd, Bh[nt]);  ldsm2(bd + TILEB, Bl[nt]); }
            else        { ldsm2t(bd, Bh[nt]); ldsm2t(bd + TILEB, Bl[nt]); }
        }
        #pragma unroll
        for (int mt = 0; mt < 2; mt++)
            #pragma unroll
            for (int nt = 0; nt < 4; nt++){
                mmab(acc[mt][nt], Ah[mt], Bh[nt]);
                mmab(acc[mt][nt], Ah[mt], Bl[nt]);
                mmab(acc[mt][nt], Al[mt], Bh[nt]);
            }
    }
}

// warp-tile single-product fp16 matmul (relative-error path: P, O)
__device__ __forceinline__ void wmm_h(u32 aB, u32 bB, int am, int bm,
                                      int wm, int wn, int l, float acc[2][4][4]){
    #pragma unroll
    for (int mt = 0; mt < 2; mt++)
        #pragma unroll
        for (int nt = 0; nt < 4; nt++)
            #pragma unroll
            for (int q = 0; q < 4; q++) acc[mt][nt][q] = 0.f;
    #pragma unroll
    for (int ks = 0; ks < 8; ks++){
        int k0 = ks*16;
        u32 Ah[2][4], Bh[4][2];
        #pragma unroll
        for (int mt = 0; mt < 2; mt++){
            int i0 = wm*32 + mt*16;
            u32 ad;
            if (am == 0) ad = aB + (u32)(((i0 + (l&7) + ((l>>3)&1)*8)*SSTR + k0 + (l>>4)*8)*2);
            else         ad = aB + (u32)(((k0 + (l>>4)*8 + (l&7))*SSTR + i0 + ((l>>3)&1)*8)*2);
            if (am == 0) ldsm4(ad, Ah[mt]);
            else         ldsm4t(ad, Ah[mt]);
        }
        #pragma unroll
        for (int nt = 0; nt < 4; nt++){
            int j0 = wn*32 + nt*8;
            u32 bd;
            if (bm == 0) bd = bB + (u32)(((j0 + (l&7))*SSTR + k0 + ((l>>3)&1)*8)*2);
            else         bd = bB + (u32)(((k0 + (l&15))*SSTR + j0)*2);
            if (bm == 0) ldsm2(bd, Bh[nt]);
            else         ldsm2t(bd, Bh[nt]);
        }
        #pragma unroll
        for (int mt = 0; mt < 2; mt++)
            #pragma unroll
            for (int nt = 0; nt < 4; nt++)
                mmah(acc[mt][nt], Ah[mt], Bh[nt]);
    }
}

// store warp acc -> bf16 hi/lo tile (split-2), optional per-column scale
__device__ __forceinline__ void store_acc(char* smc, u32 dstOff, int wm, int wn, int l,
                                          float acc[2][4][4], const float* colscale){
    int r0 = l >> 2, c0 = (l & 3)*2;
    #pragma unroll
    for (int mt = 0; mt < 2; mt++)
        #pragma unroll
        for (int nt = 0; nt < 4; nt++){
            int row = wm*32 + mt*16 + r0, col = wn*32 + nt*8 + c0;
            float s0 = 1.f, s1 = 1.f;
            if (colscale){ s0 = colscale[col]; s1 = colscale[col+1]; }
            #pragma unroll
            for (int h = 0; h < 2; h++){
                float v0 = acc[mt][nt][h*2] * s0, v1 = acc[mt][nt][h*2+1] * s1;
                u32 lp, hp = split2(v0, v1, lp);
                u32 off = dstOff + (u32)((((row + h*8)*SSTR) + col)*2);
                *(u32*)(smc + off) = hp;
                *(u32*)(smc + off + TILEB) = lp;
            }
        }
}

// store warp acc -> single fp16 tile, optional per-column scale + global scale
__device__ __forceinline__ void store_acc_h(char* smc, u32 dstOff, int wm, int wn, int l,
                                            float acc[2][4][4], const float* colscale,
                                            float gs){
    int r0 = l >> 2, c0 = (l & 3)*2;
    #pragma unroll
    for (int mt = 0; mt < 2; mt++)
        #pragma unroll
        for (int nt = 0; nt < 4; nt++){
            int row = wm*32 + mt*16 + r0, col = wn*32 + nt*8 + c0;
            float s0 = gs, s1 = gs;
            if (colscale){ s0 *= colscale[col]; s1 *= colscale[col+1]; }
            #pragma unroll
            for (int h = 0; h < 2; h++){
                u32 hp = cvt2h(acc[mt][nt][h*2] * s0, acc[mt][nt][h*2+1] * s1);
                *(u32*)(smc + dstOff + (u32)((((row + h*8)*SSTR) + col)*2)) = hp;
            }
        }
}

// cp.async one pre-split tensor (hi or lo) into a tile region (ATPB threads)
__device__ __forceinline__ void pf_tile(u32 dst, const u16* __restrict__ src, int tid){
    for (int g = tid; g < 2048; g += ATPB){
        int m = g >> 4, c = (g & 15)*8;
        cp16(dst + (u32)((m*SSTR + c)*2), src + m*128 + c);
    }
}

// ============================================================================
__global__ void k_rinv(const float* __restrict__ in){
    int nk = blockIdx.x, t = threadIdx.x;
    float v = in[(size_t)nk*MAT + t*D_B + t];
    g_rv[nk*D_B + t] = rsqrtf(fmaxf(fabsf(v), 1e-4f));
}

// fused cov2cor + channel mixing; cp.async double-buffered staging (frozen).
__global__ __launch_bounds__(256, 1) void k_mix(const float* __restrict__ inp,
                                                const float* __restrict__ wq,
                                                const float* __restrict__ wk){
    __shared__ float sWQ[C_B*C_B], sWK[C_B*C_B];
    __shared__ float sX [2][8*D_B];
    __shared__ float sRV[2][8*D_B];
    int tid = threadIdx.x, n = blockIdx.y, irow = blockIdx.x;
    int tx = tid & 31, ty = tid >> 5, k0 = ty*8;
    u32 sxA[2] = { smem_u32(&sX[0][0]),  smem_u32(&sX[1][0])  };
    u32 rvA[2] = { smem_u32(&sRV[0][0]), smem_u32(&sRV[1][0]) };

    {
        int cl = tid >> 5, jj = (tid & 31)*4;
        cp16(sxA[0] + (u32)((cl*D_B + jj)*4),
             inp + ((size_t)(n*C_B + cl))*MAT + irow*D_B + jj);
        int idx = tid*4, cl2 = idx >> 7, j2 = idx & 127;
        cp16(rvA[0] + (u32)(idx*4), g_rv + ((size_t)(n*C_B + cl2))*D_B + j2);
        cp_commit();
    }
    for (int i = tid; i < C_B*C_B; i += 256){ sWQ[i] = wq[i]; sWK[i] = wk[i]; }

    u64 aQ[4][4], aK[4][4];
    #pragma unroll
    for (int p = 0; p < 4; p++)
        #pragma unroll
        for (int q = 0; q < 4; q++){ aQ[p][q] = 0ull; aK[p][q] = 0ull; }

    for (int cb = 0; cb < 8; cb++){
        int cur = cb & 1, cc = cb*8;
        if (cb < 7){
            int nb = cur ^ 1, ncc = cc + 8;
            int cl = tid >> 5, jj = (tid & 31)*4;
            cp16(sxA[nb] + (u32)((cl*D_B + jj)*4),
                 inp + ((size_t)(n*C_B + ncc + cl))*MAT + irow*D_B + jj);
            int idx = tid*4, cl2 = idx >> 7, j2 = idx & 127;
            cp16(rvA[nb] + (u32)(idx*4), g_rv + ((size_t)(n*C_B + ncc + cl2))*D_B + j2);
            cp_commit();
            cp_wait1();
        } else {
            cp_wait0();
        }
        __syncthreads();
        {
            int cl = tid >> 5, jj = (tid & 31)*4;
            float4 v = *(float4*)&sX[cur][cl*D_B + jj];
            float ri = sRV[cur][cl*D_B + irow];
            v.x = clip1(v.x*ri*sRV[cur][cl*D_B + jj+0]);
            v.y = clip1(v.y*ri*sRV[cur][cl*D_B + jj+1]);
            v.z = clip1(v.z*ri*sRV[cur][cl*D_B + jj+2]);
            v.w = clip1(v.w*ri*sRV[cur][cl*D_B + jj+3]);
            *(float4*)&sX[cur][cl*D_B + jj] = v;
        }
        __syncthreads();
        #pragma unroll
        for (int cl = 0; cl < 8; cl++){
            int c = cc + cl;
            float4 xv = *(const float4*)&sX[cur][cl*D_B + tx*4];
            u64 xx[4] = { bcast2(xv.x), bcast2(xv.y), bcast2(xv.z), bcast2(xv.w) };
            F4U q0, q1, kk0, kk1;
            q0.f = *(const float4*)&sWQ[c*C_B + k0];  q1.f = *(const float4*)&sWQ[c*C_B + k0 + 4];
            kk0.f = *(const float4*)&sWK[c*C_B + k0]; kk1.f = *(const float4*)&sWK[c*C_B + k0 + 4];
            u64 bq[4] = { q0.u[0], q0.u[1], q1.u[0], q1.u[1] };
            u64 bk[4] = { kk0.u[0], kk0.u[1], kk1.u[0], kk1.u[1] };
            #pragma unroll
            for (int p = 0; p < 4; p++)
                #pragma unroll
                for (int q = 0; q < 4; q++){
                    aQ[p][q] = ffma2(xx[p], bq[q], aQ[p][q]);
                    aK[p][q] = ffma2(xx[p], bk[q], aK[p][q]);
                }
        }
        __syncthreads();
    }
    #pragma unroll
    for (int q = 0; q < 4; q++)
        #pragma unroll
        for (int h = 0; h < 2; h++){
            int k = k0 + q*2 + h;
            float vq[4], vk[4];
            #pragma unroll
            for (int p = 0; p < 4; p++){
                float lo, hi;
                unpack2(aQ[p][q], lo, hi); vq[p] = h ? hi : lo;
                unpack2(aK[p][q], lo, hi); vk[p] = h ? hi : lo;
            }
            size_t base = ((size_t)(n*C_B + k))*MAT + irow*D_B + tx*4;
            u32 l0, l1;
            u32 h0 = split2(vq[0], vq[1], l0), h1 = split2(vq[2], vq[3], l1);
            *(uint2*)&g_Qh[base] = make_uint2(h0, h1);
            *(uint2*)&g_Ql[base] = make_uint2(l0, l1);
            h0 = split2(vk[0], vk[1], l0); h1 = split2(vk[2], vk[3], l1);
            *(uint2*)&g_Kh[base] = make_uint2(h0, h1);
            *(uint2*)&g_Kl[base] = make_uint2(l0, l1);
        }
}

// ============================================================================
// k_attn: PERSISTENT, 512 threads (16 warps, 4x4 grid, 32x32 warp tiles).
// mm1/mm2 bf16 split-2; mm3/mm4 fp16 single-product. Same math/order as r13.
// ============================================================================
__global__ __launch_bounds__(ATPB, 1) void k_attn(const float* __restrict__ inp,
                                                  const float* __restrict__ lam,
                                                  float* __restrict__ out){
    extern __shared__ char smc[];
    u32 sb = smem_u32(smc);
    u32 B0 = sb, B1 = sb + SBYTES, B2 = sb + 2*SBYTES;
    u32 B2t = B2 + TILEB;                      // St.lo -> X''' -> P
    __shared__ float s_rv[D_B], s_sr[D_B], s_dia[D_B], s_part[D_B][4], s_red[20];
    int tid = threadIdx.x, w = tid >> 5, l = tid & 31;
    int wm = w >> 2, wn = w & 3;
    int r0 = l >> 2, c0 = (l & 3)*2;
    int stride = gridDim.x;

    {
        size_t gb0 = (size_t)blockIdx.x * MAT;
        pf_tile(B0,         g_Qh + gb0, tid);
        pf_tile(B0 + TILEB, g_Ql + gb0, tid);
        pf_tile(B1,         g_Kh + gb0, tid);
        pf_tile(B1 + TILEB, g_Kl + gb0, tid);
        cp_commit();
    }

    for (int nk = blockIdx.x; nk < NK_TOT; nk += stride){
        size_t gb = (size_t)nk * MAT;
        int nk2 = nk + stride;
        if (tid < D_B) s_rv[tid] = g_rv[nk*D_B + tid];
        cp_wait0();
        __syncthreads();

        float acc[2][4][4];
        wmm(B0, B1, 1, 1, wm, wn, l, acc);     // St = Q^T K
        store_acc(smc, B2 - sb, wm, wn, l, acc, 0);
        __syncthreads();

        if (nk2 < NK_TOT){
            size_t gn = (size_t)nk2 * MAT;
            pf_tile(B0,         g_Qh + gn, tid);
            pf_tile(B0 + TILEB, g_Ql + gn, tid);
            cp_commit();
        }

        wmm(B2, B1, 1, 1, wm, wn, l, acc);     // Apre = St^T K
        float mx = -3.4e38f;
        #pragma unroll
        for (int mt = 0; mt < 2; mt++)
            #pragma unroll
            for (int nt = 0; nt < 4; nt++)
                #pragma unroll
                for (int q = 0; q < 4; q++) mx = fmaxf(mx, acc[mt][nt][q]);
        #pragma unroll
        for (int o = 16; o; o >>= 1) mx = fmaxf(mx, __shfl_xor_sync(0xffffffffu, mx, o));
        if (l == 0) s_red[w] = mx;
        __syncthreads();
        if (tid == 0){
            float m2 = s_red[0];
            #pragma unroll
            for (int q = 1; q < 16; q++) m2 = fmaxf(m2, s_red[q]);
            s_red[16] = m2;
        }
        if (nk2 < NK_TOT){
            size_t gn = (size_t)nk2 * MAT;
            pf_tile(B1,         g_Kh + gn, tid);
            pf_tile(B1 + TILEB, g_Kl + gn, tid);
            cp_commit();
        }
        __syncthreads();
        float bmax = s_red[16];
        {   // exp (all-poly, fma pipe) in place + row partial sums
            const u64 kL2E = bcast2(1.4426950408889634f), kMAG = bcast2(12582912.0f),
                      kNMAG = bcast2(-12582912.0f), kN1 = bcast2(-1.0f),
                      kC5 = bcast2(1.3333558146e-3f), kC4 = bcast2(9.6181291076e-3f),
                      kC3 = bcast2(5.5504108664e-2f), kC2 = bcast2(2.4022650695e-1f),
                      kC1 = bcast2(6.9314718055e-1f), kONE = bcast2(1.0f),
                      kNB = bcast2(-bmax);
            float part[2][2] = {};
            #pragma unroll
            for (int mt = 0; mt < 2; mt++)
                #pragma unroll
                for (int nt = 0; nt < 4; nt++){
                    u64 p0 = exp_pair(add2(pack2(acc[mt][nt][0], acc[mt][nt][1]), kNB),
                                      kL2E,kMAG,kNMAG,kN1,kC5,kC4,kC3,kC2,kC1,kONE);
                    u64 p1 = exp_pair(add2(pack2(acc[mt][nt][2], acc[mt][nt][3]), kNB),
                                      kL2E,kMAG,kNMAG,kN1,kC5,kC4,kC3,kC2,kC1,kONE);
                    unpack2(p0, acc[mt][nt][0], acc[mt][nt][1]);
                    unpack2(p1, acc[mt][nt][2], acc[mt][nt][3]);
                    part[mt][0] += acc[mt][nt][0] + acc[mt][nt][1];
                    part[mt][1] += acc[mt][nt][2] + acc[mt][nt][3];
                }
            #pragma unroll
            for (int mt = 0; mt < 2; mt++)
                #pragma unroll
                for (int h = 0; h < 2; h++){
                    float t = part[mt][h];
                    t += __shfl_xor_sync(0xffffffffu, t, 1);
                    t += __shfl_xor_sync(0xffffffffu, t, 2);
                    if ((l & 3) == 0) s_part[wm*32 + mt*16 + h*8 + r0][wn] = t;
                }
        }
        // X''' = clip(inp*rv_i*rv_j) straight from gmem -> B2t (fp16 single)
        for (int e = tid; e < 4096; e += ATPB){
            int i = e >> 5, j = (e & 31)*4;
            float4 v = *(const float4*)&inp[gb + i*128 + j];
            float ri = s_rv[i];
            v.x = clip1(v.x*ri*s_rv[j+0]); v.y = clip1(v.y*ri*s_rv[j+1]);
            v.z = clip1(v.z*ri*s_rv[j+2]); v.w = clip1(v.w*ri*s_rv[j+3]);
            u32 off = (B2t - sb) + (u32)((i*SSTR + j)*2);
            *(u32*)(smc + off)     = cvt2h(v.x, v.y);
            *(u32*)(smc + off + 4) = cvt2h(v.z, v.w);
        }
        __syncthreads();
        if (tid < D_B)
            s_dia[tid] = s_part[tid][0] + s_part[tid][1] + s_part[tid][2] + s_part[tid][3];
        __syncthreads();
        if (tid < 32){
            float t = s_dia[tid] + s_dia[tid+32] + s_dia[tid+64] + s_dia[tid+96];
            #pragma unroll
            for (int o = 16; o; o >>= 1) t += __shfl_xor_sync(0xffffffffu, t, o);
            if (tid == 0) s_red[17] = t;
        }
        __syncthreads();
        if (tid < D_B){
            float d = fmaxf(fmaxf(s_dia[tid], s_red[17]/100000.0f), 1e-5f);
            s_sr[tid] = rsqrtf(d);
        }
        __syncthreads();
        store_acc_h(smc, B2 - sb, wm, wn, l, acc, s_sr, 1.0f);  // e~ (over St.hi)
        __syncthreads();

        wmm_h(B2, B2t, 0, 1, wm, wn, l, acc);            // P = e~ X'''
        __syncthreads();
        store_acc_h(smc, B2t - sb, wm, wn, l, acc, 0, PSCL);  // P/32 (over X''')
        __syncthreads();

        wmm_h(B2t, B2, 0, 0, wm, wn, l, acc);            // O = (P/32) e~^T
        {
            float lamv = lam[nk & (C_B - 1)] * PSCLI;
            #pragma unroll
            for (int mt = 0; mt < 2; mt++)
                #pragma unroll
                for (int nt = 0; nt < 4; nt++){
                    int row = wm*32 + mt*16 + r0, col = wn*32 + nt*8 + c0;
                    float sc0 = s_sr[col], sc1 = s_sr[col+1];
                    #pragma unroll
                    for (int h = 0; h < 2; h++){
                        int rr = row + h*8;
                        float li = lamv * s_sr[rr];
                        float2 iv = *(const float2*)&inp[gb + rr*128 + col];
                        float2 o;
                        o.x = iv.x + li*sc0*acc[mt][nt][h*2+0];
                        o.y = iv.y + li*sc1*acc[mt][nt][h*2+1];
                        *(float2*)&out[gb + rr*128 + col] = o;
                    }
                }
        }
    }
}

// ============================================================================
extern "C" void kernel_launch(void* const* d_in, const int* in_sizes, int n_in,
                              void* d_out, int out_size){
    const float* inp = (const float*)d_in[0];
    const float* wq  = (const float*)d_in[1];
    const float* wk  = (const float*)d_in[2];
    const float* lam = (const float*)d_in[3];
    float* out = (float*)d_out;

    int nsm = 148;
    cudaDeviceGetAttribute(&nsm, cudaDevAttrMultiProcessorCount, 0);
    if (nsm <= 0 || nsm > NK_TOT) nsm = 148;

    cudaFuncSetAttribute(k_attn, cudaFuncAttributeMaxDynamicSharedMemorySize, DSM);

    k_rinv<<<NK_TOT, D_B>>>(inp);
    k_mix<<<dim3(D_B, N_B), 256>>>(inp, wq, wk);
    k_attn<<<nsm, ATPB, DSM>>>(inp, lam, out);
}